// round 1
// baseline (speedup 1.0000x reference)
#include <cuda_runtime.h>
#include <cuda_bf16.h>
#include <math.h>

// ---------------- problem constants ----------------
#define BB 2
#define SS 2048
#define DD 1024
#define HH 16
#define DHH 64
#define MM (BB * SS)        // 4096 tokens
#define LD3 (3 * DD)        // 3072

// ---------------- scratch (device globals, no allocation) ----------------
__device__ float g_ln1 [MM * DD];
__device__ float g_wqkv[DD * LD3];
__device__ float g_qkv [MM * LD3];
__device__ float g_ctx [MM * DD];
__device__ float g_attn[MM * DD];
__device__ float g_ln2 [MM * DD];
__device__ float g_ffn1[MM * DD];
__device__ float g_res2[MM * DD];

// ---------------- layernorm ----------------
__device__ __forceinline__ float block_sum_256(float v, float* red) {
    #pragma unroll
    for (int o = 16; o; o >>= 1) v += __shfl_xor_sync(0xffffffffu, v, o);
    int w = threadIdx.x >> 5;
    if ((threadIdx.x & 31) == 0) red[w] = v;
    __syncthreads();
    if (threadIdx.x < 8) {
        v = red[threadIdx.x];
        #pragma unroll
        for (int o = 4; o; o >>= 1) v += __shfl_xor_sync(0xffu, v, o);
        if (threadIdx.x == 0) red[0] = v;
    }
    __syncthreads();
    float r = red[0];
    __syncthreads();
    return r;
}

__global__ void layernorm_kernel(const float* __restrict__ x,
                                 const float* __restrict__ g,
                                 const float* __restrict__ b,
                                 float* __restrict__ out) {
    __shared__ float red[32];
    int row = blockIdx.x;
    const float* xr = x + (size_t)row * DD;
    float v[4];
    float s = 0.f;
    #pragma unroll
    for (int i = 0; i < 4; i++) {
        v[i] = xr[threadIdx.x + i * 256];
        s += v[i];
    }
    float mean = block_sum_256(s, red) * (1.0f / DD);
    float sq = 0.f;
    #pragma unroll
    for (int i = 0; i < 4; i++) {
        float d = v[i] - mean;
        sq += d * d;
    }
    float var = block_sum_256(sq, red) * (1.0f / DD);
    float inv = rsqrtf(var + 1e-5f);
    float* orow = out + (size_t)row * DD;
    #pragma unroll
    for (int i = 0; i < 4; i++) {
        int c = threadIdx.x + i * 256;
        orow[c] = (v[i] - mean) * inv * g[c] + b[c];
    }
}

// ---------------- repack wq/wk/wv [H,D,DH] -> [D, 3D] row-major ----------------
// out column layout: [q(h0..h15) | k(h0..h15) | v(h0..h15)], each head 64 wide
__global__ void repack_qkv_kernel(const float* __restrict__ wq,
                                  const float* __restrict__ wk,
                                  const float* __restrict__ wv,
                                  float* __restrict__ out) {
    int idx = blockIdx.x * blockDim.x + threadIdx.x;   // over H*D*DH = 1M
    if (idx >= HH * DD * DHH) return;
    int h = idx >> 16;           // / (D*DH) = 65536
    int d = (idx >> 6) & 1023;
    int k = idx & 63;
    int o = d * LD3 + h * DHH + k;
    out[o]            = wq[idx];
    out[o + DD]       = wk[idx];
    out[o + 2 * DD]   = wv[idx];
}

// ---------------- SGEMM: C[M,N] = A[M,K] @ B[K,N]  (+epilogue) ----------------
// EPI: 0 = none, 1 = C += R, 2 = relu
#define GBM 128
#define GBN 128
#define GBK 16
#define GTM 8
#define GTN 8

template <int EPI>
__global__ __launch_bounds__(256, 2)
void sgemm_kernel(const float* __restrict__ A, const float* __restrict__ B,
                  float* __restrict__ C, const float* __restrict__ R,
                  int M, int N, int K) {
    __shared__ float As[GBK][GBM];
    __shared__ float Bs[GBK][GBN];

    int tid = threadIdx.x;
    int brow = blockIdx.y * GBM;
    int bcol = blockIdx.x * GBN;

    int arow = tid >> 2;           // 0..63
    int acol = (tid & 3) * 4;      // 0,4,8,12
    int brw  = tid >> 5;           // 0..7
    int bcl  = (tid & 31) * 4;

    int trow = (tid >> 4) * GTM;   // 0..120
    int tcol = (tid & 15) * GTN;

    float acc[GTM][GTN];
    #pragma unroll
    for (int i = 0; i < GTM; i++)
        #pragma unroll
        for (int j = 0; j < GTN; j++) acc[i][j] = 0.f;

    float ra[GTM], rb[GTN];

    for (int k0 = 0; k0 < K; k0 += GBK) {
        #pragma unroll
        for (int it = 0; it < 2; it++) {
            int r = arow + it * 64;
            float4 v = *(const float4*)&A[(size_t)(brow + r) * K + k0 + acol];
            As[acol + 0][r] = v.x;
            As[acol + 1][r] = v.y;
            As[acol + 2][r] = v.z;
            As[acol + 3][r] = v.w;
        }
        #pragma unroll
        for (int it = 0; it < 2; it++) {
            int r = brw + it * 8;
            *(float4*)&Bs[r][bcl] = *(const float4*)&B[(size_t)(k0 + r) * N + bcol + bcl];
        }
        __syncthreads();
        #pragma unroll
        for (int k = 0; k < GBK; k++) {
            *(float4*)&ra[0] = *(float4*)&As[k][trow];
            *(float4*)&ra[4] = *(float4*)&As[k][trow + 4];
            *(float4*)&rb[0] = *(float4*)&Bs[k][tcol];
            *(float4*)&rb[4] = *(float4*)&Bs[k][tcol + 4];
            #pragma unroll
            for (int i = 0; i < GTM; i++)
                #pragma unroll
                for (int j = 0; j < GTN; j++)
                    acc[i][j] = fmaf(ra[i], rb[j], acc[i][j]);
        }
        __syncthreads();
    }

    #pragma unroll
    for (int i = 0; i < GTM; i++) {
        size_t base = (size_t)(brow + trow + i) * N + bcol + tcol;
        #pragma unroll
        for (int jj = 0; jj < GTN; jj += 4) {
            float4 v = make_float4(acc[i][jj], acc[i][jj + 1], acc[i][jj + 2], acc[i][jj + 3]);
            if (EPI == 1) {
                float4 r = *(const float4*)&R[base + jj];
                v.x += r.x; v.y += r.y; v.z += r.z; v.w += r.w;
            } else if (EPI == 2) {
                v.x = fmaxf(v.x, 0.f); v.y = fmaxf(v.y, 0.f);
                v.z = fmaxf(v.z, 0.f); v.w = fmaxf(v.w, 0.f);
            }
            *(float4*)&C[base + jj] = v;
        }
    }
}

// ---------------- flash attention (fp32, online softmax) ----------------
// grid: (S/64, H, B), block: 128 threads.
// qkv layout: [M, 3072], q at col h*64, k at 1024 + h*64, v at 2048 + h*64.
// ctx out: [M, 1024] with col = h*64 + e   (== head-concat order)
#define FSP 68  // smem row stride (floats): mult of 4 for float4 alignment

__global__ __launch_bounds__(128)
void flash_kernel(const float* __restrict__ qkv, float* __restrict__ ctx) {
    extern __shared__ float sm[];
    float* Qs = sm;                 // [64 d][FSP]  (d-major, transposed)
    float* Ks = Qs + 64 * FSP;      // [64 d][FSP]
    float* Vs = Ks + 64 * FSP;      // [64 t][FSP]  (natural)
    float* Ps = Vs + 64 * FSP;      // [64 t][FSP]  (t-major)

    int tid = threadIdx.x;
    int b = blockIdx.z, h = blockIdx.y;
    int q0g = blockIdx.x * 64;

    const float* qbase = qkv + ((size_t)b * SS + q0g) * LD3 + h * DHH;
    const float* kbase = qkv + ((size_t)b * SS) * LD3 + DD + h * DHH;
    const float* vbase = qkv + ((size_t)b * SS) * LD3 + 2 * DD + h * DHH;

    // load Q tile, transposed + scaled by 1/sqrt(DH) = 0.125
    for (int idx = tid; idx < 64 * 64; idx += 128) {
        int s = idx >> 6, d = idx & 63;
        Qs[d * FSP + s] = qbase[(size_t)s * LD3 + d] * 0.125f;
    }

    int tq = tid >> 3;        // 0..15 -> 4 query rows each
    int tt = tid & 7;         // 0..7  -> 8 key cols / 8 out dims each
    int q0 = tq * 4, t0 = tt * 8, e0 = tt * 8;

    float m[4], l[4], acc_o[4][8];
    #pragma unroll
    for (int i = 0; i < 4; i++) {
        m[i] = -1e30f; l[i] = 0.f;
        #pragma unroll
        for (int j = 0; j < 8; j++) acc_o[i][j] = 0.f;
    }

    for (int kb = 0; kb < SS; kb += 64) {
        __syncthreads();  // prior GEMM2 done reading Ks/Vs/Ps; also fences Q tile on iter 0
        for (int idx = tid; idx < 64 * 64; idx += 128) {
            int s = idx >> 6, d = idx & 63;
            float kv = kbase[(size_t)(kb + s) * LD3 + d];
            float vv = vbase[(size_t)(kb + s) * LD3 + d];
            Ks[d * FSP + s] = kv;     // transposed
            Vs[s * FSP + d] = vv;     // natural
        }
        __syncthreads();

        // GEMM1: S = Q @ K^T  (4x8 per thread)
        float acc_s[4][8];
        #pragma unroll
        for (int i = 0; i < 4; i++)
            #pragma unroll
            for (int j = 0; j < 8; j++) acc_s[i][j] = 0.f;

        #pragma unroll 4
        for (int d = 0; d < 64; d++) {
            float4 a  = *(float4*)&Qs[d * FSP + q0];
            float4 b0 = *(float4*)&Ks[d * FSP + t0];
            float4 b1 = *(float4*)&Ks[d * FSP + t0 + 4];
            float av[4] = {a.x, a.y, a.z, a.w};
            float bv[8] = {b0.x, b0.y, b0.z, b0.w, b1.x, b1.y, b1.z, b1.w};
            #pragma unroll
            for (int i = 0; i < 4; i++)
                #pragma unroll
                for (int j = 0; j < 8; j++)
                    acc_s[i][j] = fmaf(av[i], bv[j], acc_s[i][j]);
        }

        // online softmax update; write P tile (t-major)
        #pragma unroll
        for (int i = 0; i < 4; i++) {
            float rm = acc_s[i][0];
            #pragma unroll
            for (int j = 1; j < 8; j++) rm = fmaxf(rm, acc_s[i][j]);
            #pragma unroll
            for (int o = 1; o < 8; o <<= 1)
                rm = fmaxf(rm, __shfl_xor_sync(0xffffffffu, rm, o, 8));
            float mn = fmaxf(m[i], rm);
            float sc = __expf(m[i] - mn);
            float ls = 0.f;
            #pragma unroll
            for (int j = 0; j < 8; j++) {
                float p = __expf(acc_s[i][j] - mn);
                acc_s[i][j] = p;
                ls += p;
            }
            #pragma unroll
            for (int o = 1; o < 8; o <<= 1)
                ls += __shfl_xor_sync(0xffffffffu, ls, o, 8);
            l[i] = l[i] * sc + ls;
            m[i] = mn;
            #pragma unroll
            for (int j = 0; j < 8; j++) acc_o[i][j] *= sc;
            #pragma unroll
            for (int j = 0; j < 8; j++)
                Ps[(t0 + j) * FSP + q0 + i] = acc_s[i][j];
        }
        __syncthreads();

        // GEMM2: O += P @ V
        #pragma unroll 4
        for (int t = 0; t < 64; t++) {
            float4 a  = *(float4*)&Ps[t * FSP + q0];
            float4 b0 = *(float4*)&Vs[t * FSP + e0];
            float4 b1 = *(float4*)&Vs[t * FSP + e0 + 4];
            float av[4] = {a.x, a.y, a.z, a.w};
            float bv[8] = {b0.x, b0.y, b0.z, b0.w, b1.x, b1.y, b1.z, b1.w};
            #pragma unroll
            for (int i = 0; i < 4; i++)
                #pragma unroll
                for (int j = 0; j < 8; j++)
                    acc_o[i][j] = fmaf(av[i], bv[j], acc_o[i][j]);
        }
    }

    float* obase = ctx + ((size_t)b * SS + q0g) * DD + h * DHH;
    #pragma unroll
    for (int i = 0; i < 4; i++) {
        float inv = 1.0f / l[i];
        float4 v0 = make_float4(acc_o[i][0] * inv, acc_o[i][1] * inv,
                                acc_o[i][2] * inv, acc_o[i][3] * inv);
        float4 v1 = make_float4(acc_o[i][4] * inv, acc_o[i][5] * inv,
                                acc_o[i][6] * inv, acc_o[i][7] * inv);
        *(float4*)&obase[(size_t)(q0 + i) * DD + e0]     = v0;
        *(float4*)&obase[(size_t)(q0 + i) * DD + e0 + 4] = v1;
    }
}

// ---------------- launch ----------------
extern "C" void kernel_launch(void* const* d_in, const int* in_sizes, int n_in,
                              void* d_out, int out_size) {
    const float* x     = (const float*)d_in[0];
    const float* wq    = (const float*)d_in[1];
    const float* wk    = (const float*)d_in[2];
    const float* wv    = (const float*)d_in[3];
    const float* wo    = (const float*)d_in[4];
    const float* w1    = (const float*)d_in[5];
    const float* w2    = (const float*)d_in[6];
    const float* ln1_g = (const float*)d_in[7];
    const float* ln1_b = (const float*)d_in[8];
    const float* ln2_g = (const float*)d_in[9];
    const float* ln2_b = (const float*)d_in[10];
    const float* ln3_g = (const float*)d_in[11];
    const float* ln3_b = (const float*)d_in[12];
    float* out = (float*)d_out;

    float *p_ln1, *p_wqkv, *p_qkv, *p_ctx, *p_attn, *p_ln2, *p_ffn1, *p_res2;
    cudaGetSymbolAddress((void**)&p_ln1,  g_ln1);
    cudaGetSymbolAddress((void**)&p_wqkv, g_wqkv);
    cudaGetSymbolAddress((void**)&p_qkv,  g_qkv);
    cudaGetSymbolAddress((void**)&p_ctx,  g_ctx);
    cudaGetSymbolAddress((void**)&p_attn, g_attn);
    cudaGetSymbolAddress((void**)&p_ln2,  g_ln2);
    cudaGetSymbolAddress((void**)&p_ffn1, g_ffn1);
    cudaGetSymbolAddress((void**)&p_res2, g_res2);

    int flash_smem = 4 * 64 * FSP * (int)sizeof(float);   // 69632 B
    cudaFuncSetAttribute(flash_kernel, cudaFuncAttributeMaxDynamicSharedMemorySize, flash_smem);

    // 1. LN1
    layernorm_kernel<<<MM, 256>>>(x, ln1_g, ln1_b, p_ln1);

    // 2. repack qkv weights -> [1024, 3072]
    repack_qkv_kernel<<<(HH * DD * DHH + 255) / 256, 256>>>(wq, wk, wv, p_wqkv);

    // 3. QKV projection: [4096,1024] @ [1024,3072]
    sgemm_kernel<0><<<dim3(LD3 / GBN, MM / GBM), 256>>>(p_ln1, p_wqkv, p_qkv, nullptr, MM, LD3, DD);

    // 4. flash attention
    flash_kernel<<<dim3(SS / 64, HH, BB), 128, flash_smem>>>(p_qkv, p_ctx);

    // 5. output projection + residual: attn = ctx @ wo + x
    sgemm_kernel<1><<<dim3(DD / GBN, MM / GBM), 256>>>(p_ctx, wo, p_attn, x, MM, DD, DD);

    // 6. LN2
    layernorm_kernel<<<MM, 256>>>(p_attn, ln2_g, ln2_b, p_ln2);

    // 7. FFN1 + relu
    sgemm_kernel<2><<<dim3(DD / GBN, MM / GBM), 256>>>(p_ln2, w1, p_ffn1, nullptr, MM, DD, DD);

    // 8. FFN2 + residual (residual = ln2 output)
    sgemm_kernel<1><<<dim3(DD / GBN, MM / GBM), 256>>>(p_ffn1, w2, p_res2, p_ln2, MM, DD, DD);

    // 9. LN3 -> output
    layernorm_kernel<<<MM, 256>>>(p_res2, ln3_g, ln3_b, out);
}

// round 2
// speedup vs baseline: 1.0002x; 1.0002x over previous
#include <cuda_runtime.h>
#include <cuda_bf16.h>
#include <math.h>

// ---------------- problem constants ----------------
#define BB 2
#define SS 2048
#define DD 1024
#define HH 16
#define DHH 64
#define MM (BB * SS)        // 4096 tokens
#define LD3 (3 * DD)        // 3072

// ---------------- scratch (device globals, no allocation) ----------------
__device__ float g_ln1 [MM * DD];
__device__ float g_wqkv[DD * LD3];
__device__ float g_qkv [MM * LD3];
__device__ float g_ctx [MM * DD];
__device__ float g_attn[MM * DD];
__device__ float g_ln2 [MM * DD];
__device__ float g_ffn1[MM * DD];
__device__ float g_res2[MM * DD];

// ---------------- layernorm ----------------
__device__ __forceinline__ float block_sum_256(float v, float* red) {
    #pragma unroll
    for (int o = 16; o; o >>= 1) v += __shfl_xor_sync(0xffffffffu, v, o);
    int w = threadIdx.x >> 5;
    if ((threadIdx.x & 31) == 0) red[w] = v;
    __syncthreads();
    if (threadIdx.x < 8) {
        v = red[threadIdx.x];
        #pragma unroll
        for (int o = 4; o; o >>= 1) v += __shfl_xor_sync(0xffu, v, o);
        if (threadIdx.x == 0) red[0] = v;
    }
    __syncthreads();
    float r = red[0];
    __syncthreads();
    return r;
}

__global__ void layernorm_kernel(const float* __restrict__ x,
                                 const float* __restrict__ g,
                                 const float* __restrict__ b,
                                 float* __restrict__ out) {
    __shared__ float red[32];
    int row = blockIdx.x;
    const float* xr = x + (size_t)row * DD;
    float v[4];
    float s = 0.f;
    #pragma unroll
    for (int i = 0; i < 4; i++) {
        v[i] = xr[threadIdx.x + i * 256];
        s += v[i];
    }
    float mean = block_sum_256(s, red) * (1.0f / DD);
    float sq = 0.f;
    #pragma unroll
    for (int i = 0; i < 4; i++) {
        float d = v[i] - mean;
        sq += d * d;
    }
    float var = block_sum_256(sq, red) * (1.0f / DD);
    float inv = rsqrtf(var + 1e-5f);
    float* orow = out + (size_t)row * DD;
    #pragma unroll
    for (int i = 0; i < 4; i++) {
        int c = threadIdx.x + i * 256;
        orow[c] = (v[i] - mean) * inv * g[c] + b[c];
    }
}

// ---------------- repack wq/wk/wv [H,D,DH] -> [D, 3D] row-major ----------------
// out column layout: [q(h0..h15) | k(h0..h15) | v(h0..h15)], each head 64 wide
__global__ void repack_qkv_kernel(const float* __restrict__ wq,
                                  const float* __restrict__ wk,
                                  const float* __restrict__ wv,
                                  float* __restrict__ out) {
    int idx = blockIdx.x * blockDim.x + threadIdx.x;   // over H*D*DH = 1M
    if (idx >= HH * DD * DHH) return;
    int h = idx >> 16;           // / (D*DH) = 65536
    int d = (idx >> 6) & 1023;
    int k = idx & 63;
    int o = d * LD3 + h * DHH + k;
    out[o]            = wq[idx];
    out[o + DD]       = wk[idx];
    out[o + 2 * DD]   = wv[idx];
}

// ---------------- SGEMM: C[M,N] = A[M,K] @ B[K,N]  (+epilogue) ----------------
// EPI: 0 = none, 1 = C += R, 2 = relu
#define GBM 128
#define GBN 128
#define GBK 16
#define GTM 8
#define GTN 8

template <int EPI>
__global__ __launch_bounds__(256, 2)
void sgemm_kernel(const float* __restrict__ A, const float* __restrict__ B,
                  float* __restrict__ C, const float* __restrict__ R,
                  int M, int N, int K) {
    __shared__ float As[GBK][GBM];
    __shared__ float Bs[GBK][GBN];

    int tid = threadIdx.x;
    int brow = blockIdx.y * GBM;
    int bcol = blockIdx.x * GBN;

    int arow = tid >> 2;           // 0..63
    int acol = (tid & 3) * 4;      // 0,4,8,12
    int brw  = tid >> 5;           // 0..7
    int bcl  = (tid & 31) * 4;

    int trow = (tid >> 4) * GTM;   // 0..120
    int tcol = (tid & 15) * GTN;

    float acc[GTM][GTN];
    #pragma unroll
    for (int i = 0; i < GTM; i++)
        #pragma unroll
        for (int j = 0; j < GTN; j++) acc[i][j] = 0.f;

    float ra[GTM], rb[GTN];

    for (int k0 = 0; k0 < K; k0 += GBK) {
        #pragma unroll
        for (int it = 0; it < 2; it++) {
            int r = arow + it * 64;
            float4 v = *(const float4*)&A[(size_t)(brow + r) * K + k0 + acol];
            As[acol + 0][r] = v.x;
            As[acol + 1][r] = v.y;
            As[acol + 2][r] = v.z;
            As[acol + 3][r] = v.w;
        }
        #pragma unroll
        for (int it = 0; it < 2; it++) {
            int r = brw + it * 8;
            *(float4*)&Bs[r][bcl] = *(const float4*)&B[(size_t)(k0 + r) * N + bcol + bcl];
        }
        __syncthreads();
        #pragma unroll
        for (int k = 0; k < GBK; k++) {
            *(float4*)&ra[0] = *(float4*)&As[k][trow];
            *(float4*)&ra[4] = *(float4*)&As[k][trow + 4];
            *(float4*)&rb[0] = *(float4*)&Bs[k][tcol];
            *(float4*)&rb[4] = *(float4*)&Bs[k][tcol + 4];
            #pragma unroll
            for (int i = 0; i < GTM; i++)
                #pragma unroll
                for (int j = 0; j < GTN; j++)
                    acc[i][j] = fmaf(ra[i], rb[j], acc[i][j]);
        }
        __syncthreads();
    }

    #pragma unroll
    for (int i = 0; i < GTM; i++) {
        size_t base = (size_t)(brow + trow + i) * N + bcol + tcol;
        #pragma unroll
        for (int jj = 0; jj < GTN; jj += 4) {
            float4 v = make_float4(acc[i][jj], acc[i][jj + 1], acc[i][jj + 2], acc[i][jj + 3]);
            if (EPI == 1) {
                float4 r = *(const float4*)&R[base + jj];
                v.x += r.x; v.y += r.y; v.z += r.z; v.w += r.w;
            } else if (EPI == 2) {
                v.x = fmaxf(v.x, 0.f); v.y = fmaxf(v.y, 0.f);
                v.z = fmaxf(v.z, 0.f); v.w = fmaxf(v.w, 0.f);
            }
            *(float4*)&C[base + jj] = v;
        }
    }
}

// ---------------- flash attention (fp32, online softmax) ----------------
// grid: (S/64, H, B), block: 128 threads.
// qkv layout: [M, 3072], q at col h*64, k at 1024 + h*64, v at 2048 + h*64.
// ctx out: [M, 1024] with col = h*64 + e   (== head-concat order)
#define FSP 68  // smem row stride (floats): mult of 4 for float4 alignment

__global__ __launch_bounds__(128)
void flash_kernel(const float* __restrict__ qkv, float* __restrict__ ctx) {
    extern __shared__ float sm[];
    float* Qs = sm;                 // [64 d][FSP]  (d-major, transposed)
    float* Ks = Qs + 64 * FSP;      // [64 d][FSP]
    float* Vs = Ks + 64 * FSP;      // [64 t][FSP]  (natural)
    float* Ps = Vs + 64 * FSP;      // [64 t][FSP]  (t-major)

    int tid = threadIdx.x;
    int b = blockIdx.z, h = blockIdx.y;
    int q0g = blockIdx.x * 64;

    const float* qbase = qkv + ((size_t)b * SS + q0g) * LD3 + h * DHH;
    const float* kbase = qkv + ((size_t)b * SS) * LD3 + DD + h * DHH;
    const float* vbase = qkv + ((size_t)b * SS) * LD3 + 2 * DD + h * DHH;

    // load Q tile, transposed + scaled by 1/sqrt(DH) = 0.125
    for (int idx = tid; idx < 64 * 64; idx += 128) {
        int s = idx >> 6, d = idx & 63;
        Qs[d * FSP + s] = qbase[(size_t)s * LD3 + d] * 0.125f;
    }

    int tq = tid >> 3;        // 0..15 -> 4 query rows each
    int tt = tid & 7;         // 0..7  -> 8 key cols / 8 out dims each
    int q0 = tq * 4, t0 = tt * 8, e0 = tt * 8;

    float m[4], l[4], acc_o[4][8];
    #pragma unroll
    for (int i = 0; i < 4; i++) {
        m[i] = -1e30f; l[i] = 0.f;
        #pragma unroll
        for (int j = 0; j < 8; j++) acc_o[i][j] = 0.f;
    }

    for (int kb = 0; kb < SS; kb += 64) {
        __syncthreads();  // prior GEMM2 done reading Ks/Vs/Ps; also fences Q tile on iter 0
        for (int idx = tid; idx < 64 * 64; idx += 128) {
            int s = idx >> 6, d = idx & 63;
            float kv = kbase[(size_t)(kb + s) * LD3 + d];
            float vv = vbase[(size_t)(kb + s) * LD3 + d];
            Ks[d * FSP + s] = kv;     // transposed
            Vs[s * FSP + d] = vv;     // natural
        }
        __syncthreads();

        // GEMM1: S = Q @ K^T  (4x8 per thread)
        float acc_s[4][8];
        #pragma unroll
        for (int i = 0; i < 4; i++)
            #pragma unroll
            for (int j = 0; j < 8; j++) acc_s[i][j] = 0.f;

        #pragma unroll 4
        for (int d = 0; d < 64; d++) {
            float4 a  = *(float4*)&Qs[d * FSP + q0];
            float4 b0 = *(float4*)&Ks[d * FSP + t0];
            float4 b1 = *(float4*)&Ks[d * FSP + t0 + 4];
            float av[4] = {a.x, a.y, a.z, a.w};
            float bv[8] = {b0.x, b0.y, b0.z, b0.w, b1.x, b1.y, b1.z, b1.w};
            #pragma unroll
            for (int i = 0; i < 4; i++)
                #pragma unroll
                for (int j = 0; j < 8; j++)
                    acc_s[i][j] = fmaf(av[i], bv[j], acc_s[i][j]);
        }

        // online softmax update; write P tile (t-major)
        #pragma unroll
        for (int i = 0; i < 4; i++) {
            float rm = acc_s[i][0];
            #pragma unroll
            for (int j = 1; j < 8; j++) rm = fmaxf(rm, acc_s[i][j]);
            #pragma unroll
            for (int o = 1; o < 8; o <<= 1)
                rm = fmaxf(rm, __shfl_xor_sync(0xffffffffu, rm, o, 8));
            float mn = fmaxf(m[i], rm);
            float sc = __expf(m[i] - mn);
            float ls = 0.f;
            #pragma unroll
            for (int j = 0; j < 8; j++) {
                float p = __expf(acc_s[i][j] - mn);
                acc_s[i][j] = p;
                ls += p;
            }
            #pragma unroll
            for (int o = 1; o < 8; o <<= 1)
                ls += __shfl_xor_sync(0xffffffffu, ls, o, 8);
            l[i] = l[i] * sc + ls;
            m[i] = mn;
            #pragma unroll
            for (int j = 0; j < 8; j++) acc_o[i][j] *= sc;
            #pragma unroll
            for (int j = 0; j < 8; j++)
                Ps[(t0 + j) * FSP + q0 + i] = acc_s[i][j];
        }
        __syncthreads();

        // GEMM2: O += P @ V
        #pragma unroll 4
        for (int t = 0; t < 64; t++) {
            float4 a  = *(float4*)&Ps[t * FSP + q0];
            float4 b0 = *(float4*)&Vs[t * FSP + e0];
            float4 b1 = *(float4*)&Vs[t * FSP + e0 + 4];
            float av[4] = {a.x, a.y, a.z, a.w};
            float bv[8] = {b0.x, b0.y, b0.z, b0.w, b1.x, b1.y, b1.z, b1.w};
            #pragma unroll
            for (int i = 0; i < 4; i++)
                #pragma unroll
                for (int j = 0; j < 8; j++)
                    acc_o[i][j] = fmaf(av[i], bv[j], acc_o[i][j]);
        }
    }

    float* obase = ctx + ((size_t)b * SS + q0g) * DD + h * DHH;
    #pragma unroll
    for (int i = 0; i < 4; i++) {
        float inv = 1.0f / l[i];
        float4 v0 = make_float4(acc_o[i][0] * inv, acc_o[i][1] * inv,
                                acc_o[i][2] * inv, acc_o[i][3] * inv);
        float4 v1 = make_float4(acc_o[i][4] * inv, acc_o[i][5] * inv,
                                acc_o[i][6] * inv, acc_o[i][7] * inv);
        *(float4*)&obase[(size_t)(q0 + i) * DD + e0]     = v0;
        *(float4*)&obase[(size_t)(q0 + i) * DD + e0 + 4] = v1;
    }
}

// ---------------- launch ----------------
extern "C" void kernel_launch(void* const* d_in, const int* in_sizes, int n_in,
                              void* d_out, int out_size) {
    const float* x     = (const float*)d_in[0];
    const float* wq    = (const float*)d_in[1];
    const float* wk    = (const float*)d_in[2];
    const float* wv    = (const float*)d_in[3];
    const float* wo    = (const float*)d_in[4];
    const float* w1    = (const float*)d_in[5];
    const float* w2    = (const float*)d_in[6];
    const float* ln1_g = (const float*)d_in[7];
    const float* ln1_b = (const float*)d_in[8];
    const float* ln2_g = (const float*)d_in[9];
    const float* ln2_b = (const float*)d_in[10];
    const float* ln3_g = (const float*)d_in[11];
    const float* ln3_b = (const float*)d_in[12];
    float* out = (float*)d_out;

    float *p_ln1, *p_wqkv, *p_qkv, *p_ctx, *p_attn, *p_ln2, *p_ffn1, *p_res2;
    cudaGetSymbolAddress((void**)&p_ln1,  g_ln1);
    cudaGetSymbolAddress((void**)&p_wqkv, g_wqkv);
    cudaGetSymbolAddress((void**)&p_qkv,  g_qkv);
    cudaGetSymbolAddress((void**)&p_ctx,  g_ctx);
    cudaGetSymbolAddress((void**)&p_attn, g_attn);
    cudaGetSymbolAddress((void**)&p_ln2,  g_ln2);
    cudaGetSymbolAddress((void**)&p_ffn1, g_ffn1);
    cudaGetSymbolAddress((void**)&p_res2, g_res2);

    int flash_smem = 4 * 64 * FSP * (int)sizeof(float);   // 69632 B
    cudaFuncSetAttribute(flash_kernel, cudaFuncAttributeMaxDynamicSharedMemorySize, flash_smem);

    // 1. LN1
    layernorm_kernel<<<MM, 256>>>(x, ln1_g, ln1_b, p_ln1);

    // 2. repack qkv weights -> [1024, 3072]
    repack_qkv_kernel<<<(HH * DD * DHH + 255) / 256, 256>>>(wq, wk, wv, p_wqkv);

    // 3. QKV projection: [4096,1024] @ [1024,3072]
    sgemm_kernel<0><<<dim3(LD3 / GBN, MM / GBM), 256>>>(p_ln1, p_wqkv, p_qkv, nullptr, MM, LD3, DD);

    // 4. flash attention
    flash_kernel<<<dim3(SS / 64, HH, BB), 128, flash_smem>>>(p_qkv, p_ctx);

    // 5. output projection + residual: attn = ctx @ wo + x
    sgemm_kernel<1><<<dim3(DD / GBN, MM / GBM), 256>>>(p_ctx, wo, p_attn, x, MM, DD, DD);

    // 6. LN2
    layernorm_kernel<<<MM, 256>>>(p_attn, ln2_g, ln2_b, p_ln2);

    // 7. FFN1 + relu
    sgemm_kernel<2><<<dim3(DD / GBN, MM / GBM), 256>>>(p_ln2, w1, p_ffn1, nullptr, MM, DD, DD);

    // 8. FFN2 + residual (residual = ln2 output)
    sgemm_kernel<1><<<dim3(DD / GBN, MM / GBM), 256>>>(p_ffn1, w2, p_res2, p_ln2, MM, DD, DD);

    // 9. LN3 -> output
    layernorm_kernel<<<MM, 256>>>(p_res2, ln3_g, ln3_b, out);
}

// round 4
// speedup vs baseline: 1.1245x; 1.1243x over previous
#include <cuda_runtime.h>
#include <cuda_bf16.h>
#include <math.h>
#include <stdint.h>

#define BB 2
#define SS 2048
#define DD 1024
#define HH 16
#define DHH 64
#define MM (BB * SS)
#define LD3 (3 * DD)

// ---------------- scratch ----------------
__device__ float g_qkv [MM * LD3];
__device__ float g_ctx [MM * DD];
__device__ float g_attn[MM * DD];
__device__ float g_ln2f[MM * DD];
__device__ float g_ffn1[MM * DD];
__device__ float g_res2[MM * DD];

__device__ __nv_bfloat16 g_ln1h[MM * DD], g_ln1l[MM * DD];
__device__ __nv_bfloat16 g_ln2h[MM * DD], g_ln2l[MM * DD];
__device__ __nv_bfloat16 g_ctxh[MM * DD], g_ctxl[MM * DD];
__device__ __nv_bfloat16 g_f1h [MM * DD], g_f1l [MM * DD];
__device__ __nv_bfloat16 g_wqh[LD3 * DD], g_wql[LD3 * DD];
__device__ __nv_bfloat16 g_woh[DD * DD],  g_wol[DD * DD];
__device__ __nv_bfloat16 g_w1h[DD * DD],  g_w1l[DD * DD];
__device__ __nv_bfloat16 g_w2h[DD * DD],  g_w2l[DD * DD];

// ---------------- helpers ----------------
__device__ __forceinline__ uint32_t smem_u32(const void* p) {
    uint32_t a;
    asm("{ .reg .u64 t; cvta.to.shared.u64 t, %1; cvt.u32.u64 %0, t; }" : "=r"(a) : "l"(p));
    return a;
}
__device__ __forceinline__ void cpa16(uint32_t dst, const void* src) {
    asm volatile("cp.async.cg.shared.global [%0], [%1], 16;" :: "r"(dst), "l"(src) : "memory");
}
__device__ __forceinline__ void cpcommit() { asm volatile("cp.async.commit_group;" ::: "memory"); }
template <int N> __device__ __forceinline__ void cpwait() {
    asm volatile("cp.async.wait_group %0;" :: "n"(N) : "memory");
}
__device__ __forceinline__ void ldsm_x4(uint32_t& r0, uint32_t& r1, uint32_t& r2, uint32_t& r3, uint32_t a) {
    asm volatile("ldmatrix.sync.aligned.m8n8.x4.shared.b16 {%0,%1,%2,%3}, [%4];"
        : "=r"(r0), "=r"(r1), "=r"(r2), "=r"(r3) : "r"(a));
}
__device__ __forceinline__ void ldsm_x2(uint32_t& r0, uint32_t& r1, uint32_t a) {
    asm volatile("ldmatrix.sync.aligned.m8n8.x2.shared.b16 {%0,%1}, [%2];"
        : "=r"(r0), "=r"(r1) : "r"(a));
}
__device__ __forceinline__ void mma16816(float* d, const uint32_t* a, const uint32_t* b) {
    asm volatile("mma.sync.aligned.m16n8k16.row.col.f32.bf16.bf16.f32 "
        "{%0,%1,%2,%3},{%4,%5,%6,%7},{%8,%9},{%0,%1,%2,%3};"
        : "+f"(d[0]), "+f"(d[1]), "+f"(d[2]), "+f"(d[3])
        : "r"(a[0]), "r"(a[1]), "r"(a[2]), "r"(a[3]), "r"(b[0]), "r"(b[1]));
}
__device__ __forceinline__ void bf16split(float v, __nv_bfloat16& h, __nv_bfloat16& l) {
    h = __float2bfloat16_rn(v);
    l = __float2bfloat16_rn(v - __bfloat162float(h));
}

// ---------------- layernorm ----------------
__device__ __forceinline__ float block_sum_256(float v, float* red) {
    #pragma unroll
    for (int o = 16; o; o >>= 1) v += __shfl_xor_sync(0xffffffffu, v, o);
    int w = threadIdx.x >> 5;
    if ((threadIdx.x & 31) == 0) red[w] = v;
    __syncthreads();
    if (threadIdx.x < 8) {
        v = red[threadIdx.x];
        #pragma unroll
        for (int o = 4; o; o >>= 1) v += __shfl_xor_sync(0xffu, v, o);
        if (threadIdx.x == 0) red[0] = v;
    }
    __syncthreads();
    float r = red[0];
    __syncthreads();
    return r;
}

__global__ void layernorm_kernel(const float* __restrict__ x,
                                 const float* __restrict__ g,
                                 const float* __restrict__ b,
                                 float* __restrict__ outf,
                                 __nv_bfloat16* __restrict__ outh,
                                 __nv_bfloat16* __restrict__ outl) {
    __shared__ float red[32];
    int row = blockIdx.x;
    const float* xr = x + (size_t)row * DD;
    float v[4], s = 0.f;
    #pragma unroll
    for (int i = 0; i < 4; i++) { v[i] = xr[threadIdx.x + i * 256]; s += v[i]; }
    float mean = block_sum_256(s, red) * (1.0f / DD);
    float sq = 0.f;
    #pragma unroll
    for (int i = 0; i < 4; i++) { float d = v[i] - mean; sq += d * d; }
    float inv = rsqrtf(block_sum_256(sq, red) * (1.0f / DD) + 1e-5f);
    #pragma unroll
    for (int i = 0; i < 4; i++) {
        int c = threadIdx.x + i * 256;
        float y = (v[i] - mean) * inv * g[c] + b[c];
        size_t o = (size_t)row * DD + c;
        if (outf) outf[o] = y;
        if (outh) { __nv_bfloat16 h, l; bf16split(y, h, l); outh[o] = h; outl[o] = l; }
    }
}

// ---------------- fp32 -> bf16 hi/lo ----------------
__global__ void split_kernel(const float* __restrict__ in,
                             __nv_bfloat16* __restrict__ oh,
                             __nv_bfloat16* __restrict__ ol, int n4) {
    int i = blockIdx.x * 256 + threadIdx.x;
    if (i >= n4) return;
    float4 v = ((const float4*)in)[i];
    __nv_bfloat16 h[4], l[4];
    bf16split(v.x, h[0], l[0]); bf16split(v.y, h[1], l[1]);
    bf16split(v.z, h[2], l[2]); bf16split(v.w, h[3], l[3]);
    ((uint2*)oh)[i] = *(uint2*)h;
    ((uint2*)ol)[i] = *(uint2*)l;
}

// ---------------- weight transposes -> [N,K] bf16 hi/lo ----------------
__global__ void transpose_qkv_kernel(const float* __restrict__ wq, const float* __restrict__ wk,
                                     const float* __restrict__ wv,
                                     __nv_bfloat16* __restrict__ th, __nv_bfloat16* __restrict__ tl) {
    __shared__ float t[32][33];
    int sel = blockIdx.z >> 4, h = blockIdx.z & 15;
    const float* src = (sel == 0 ? wq : (sel == 1 ? wk : wv)) + (size_t)h * DD * DHH;
    int d0 = blockIdx.x * 32, dh0 = blockIdx.y * 32;
    int tx = threadIdx.x, ty = threadIdx.y;
    #pragma unroll
    for (int j = 0; j < 4; j++)
        t[ty + j * 8][tx] = src[(size_t)(d0 + ty + j * 8) * DHH + dh0 + tx];
    __syncthreads();
    int nb = sel * DD + h * DHH + dh0;
    #pragma unroll
    for (int j = 0; j < 4; j++) {
        size_t o = (size_t)(nb + ty + j * 8) * DD + d0 + tx;
        __nv_bfloat16 hh, ll; bf16split(t[tx][ty + j * 8], hh, ll);
        th[o] = hh; tl[o] = ll;
    }
}

__global__ void transpose_sq_kernel(const float* __restrict__ w0, const float* __restrict__ w1,
                                    const float* __restrict__ w2,
                                    __nv_bfloat16* __restrict__ t0h, __nv_bfloat16* __restrict__ t0l,
                                    __nv_bfloat16* __restrict__ t1h, __nv_bfloat16* __restrict__ t1l,
                                    __nv_bfloat16* __restrict__ t2h, __nv_bfloat16* __restrict__ t2l) {
    __shared__ float t[32][33];
    int z = blockIdx.z;
    const float* src = z == 0 ? w0 : (z == 1 ? w1 : w2);
    __nv_bfloat16* dh = z == 0 ? t0h : (z == 1 ? t1h : t2h);
    __nv_bfloat16* dl = z == 0 ? t0l : (z == 1 ? t1l : t2l);
    int r0 = blockIdx.x * 32, c0 = blockIdx.y * 32;
    int tx = threadIdx.x, ty = threadIdx.y;
    #pragma unroll
    for (int j = 0; j < 4; j++)
        t[ty + j * 8][tx] = src[(size_t)(r0 + ty + j * 8) * DD + c0 + tx];
    __syncthreads();
    #pragma unroll
    for (int j = 0; j < 4; j++) {
        size_t o = (size_t)(c0 + ty + j * 8) * DD + r0 + tx;
        __nv_bfloat16 hh, ll; bf16split(t[tx][ty + j * 8], hh, ll);
        dh[o] = hh; dl[o] = ll;
    }
}

// ---------------- mma.sync bf16x2 GEMM ----------------
// C[M,N] = (Ah+Al)[M,K] @ (Bh+Bl)[N,K]^T, fp32 out.
// CTA 128x128, BK=32, 8 warps (warp tile 64x32), 3-stage cp.async pipeline.
// 3 passes over K: (Ah,Bh), (Ah,Bl), (Al,Bh). EPI: 0 plain, 1 +R, 2 relu.
#define GLDA 40                        // smem stride in bf16 elems (80B rows)
#define G_ABYTES (128 * GLDA * 2)      // 10240
#define G_STAGE  (2 * G_ABYTES)        // 20480
#define G_SMEM   (3 * G_STAGE)         // 61440

__device__ __forceinline__ void g_load_chunk(uint32_t sA,
    const __nv_bfloat16* __restrict__ Asrc, const __nv_bfloat16* __restrict__ Bsrc,
    int brow, int bcol, int k0, int K, int tid)
{
    uint32_t sB = sA + G_ABYTES;
    #pragma unroll
    for (int it = 0; it < 2; it++) {
        int g = tid + it * 256;        // 0..511
        int r = g >> 2, gi = g & 3;
        uint32_t so = (uint32_t)(r * GLDA + gi * 8) * 2;
        cpa16(sA + so, Asrc + (size_t)(brow + r) * K + k0 + gi * 8);
        cpa16(sB + so, Bsrc + (size_t)(bcol + r) * K + k0 + gi * 8);
    }
}

template <int EPI>
__global__ void __launch_bounds__(256, 1)
gemm_mma_kernel(const __nv_bfloat16* __restrict__ Ah, const __nv_bfloat16* __restrict__ Al,
                const __nv_bfloat16* __restrict__ Bh, const __nv_bfloat16* __restrict__ Bl,
                float* __restrict__ C, const float* __restrict__ R, int N, int K) {
    extern __shared__ char smg[];
    uint32_t sbase = smem_u32(smg);
    int tid = threadIdx.x, lane = tid & 31, wid = tid >> 5;
    int wm = (wid >> 2) * 64;          // warp m offset (0 or 64)
    int wn = (wid & 3) * 32;           // warp n offset
    int brow = blockIdx.y * 128, bcol = blockIdx.x * 128;

    int kcPer = K >> 5;                // chunks per pass
    int NC = 3 * kcPer;

    const __nv_bfloat16* APass[3] = {Ah, Ah, Al};
    const __nv_bfloat16* BPass[3] = {Bh, Bl, Bh};

    float acc[4][4][4];
    #pragma unroll
    for (int i = 0; i < 4; i++)
        #pragma unroll
        for (int j = 0; j < 4; j++)
            #pragma unroll
            for (int e = 0; e < 4; e++) acc[i][j][e] = 0.f;

    // prologue: chunks 0,1
    #pragma unroll
    for (int i = 0; i < 2; i++) {
        g_load_chunk(sbase + i * G_STAGE, APass[0], BPass[0], brow, bcol, i * 32, K, tid);
        cpcommit();
    }

    // precomputed ldmatrix lane offsets (element units within tile row layout)
    int aRow = lane & 15, aCol8 = (lane >> 4) * 8;
    int bRow = lane & 7,  bCol8 = ((lane >> 3) & 1) * 8;

    for (int c = 0; c < NC; c++) {
        if (c == NC - 1) cpwait<0>(); else cpwait<1>();
        __syncthreads();
        if (c + 2 < NC) {
            int cc = c + 2;
            int pass = cc / kcPer, kc = cc % kcPer;
            g_load_chunk(sbase + (cc % 3) * G_STAGE, APass[pass], BPass[pass],
                         brow, bcol, kc * 32, K, tid);
            cpcommit();
        }
        uint32_t sA = sbase + (c % 3) * G_STAGE;
        uint32_t sB = sA + G_ABYTES;

        #pragma unroll
        for (int ks = 0; ks < 2; ks++) {
            uint32_t afrag[4][4], bfrag[4][2];
            #pragma unroll
            for (int mt = 0; mt < 4; mt++) {
                uint32_t a = sA + (uint32_t)((wm + mt * 16 + aRow) * GLDA + ks * 16 + aCol8) * 2;
                ldsm_x4(afrag[mt][0], afrag[mt][1], afrag[mt][2], afrag[mt][3], a);
            }
            #pragma unroll
            for (int nt = 0; nt < 4; nt++) {
                uint32_t a = sB + (uint32_t)((wn + nt * 8 + bRow) * GLDA + ks * 16 + bCol8) * 2;
                ldsm_x2(bfrag[nt][0], bfrag[nt][1], a);
            }
            #pragma unroll
            for (int mt = 0; mt < 4; mt++)
                #pragma unroll
                for (int nt = 0; nt < 4; nt++)
                    mma16816(acc[mt][nt], afrag[mt], bfrag[nt]);
        }
    }

    // epilogue
    int r0 = brow + wm + (lane >> 2);
    int c0 = bcol + wn + (lane & 3) * 2;
    #pragma unroll
    for (int mt = 0; mt < 4; mt++) {
        #pragma unroll
        for (int half = 0; half < 2; half++) {
            int row = r0 + mt * 16 + half * 8;
            #pragma unroll
            for (int nt = 0; nt < 4; nt++) {
                float2 v = half ? make_float2(acc[mt][nt][2], acc[mt][nt][3])
                                : make_float2(acc[mt][nt][0], acc[mt][nt][1]);
                size_t o = (size_t)row * N + c0 + nt * 8;
                if (EPI == 1) {
                    float2 rr = *(const float2*)&R[o];
                    v.x += rr.x; v.y += rr.y;
                } else if (EPI == 2) {
                    v.x = fmaxf(v.x, 0.f); v.y = fmaxf(v.y, 0.f);
                }
                *(float2*)&C[o] = v;
            }
        }
    }
}

// ---------------- flash attention (fp32, unchanged) ----------------
#define FSP 68

__global__ __launch_bounds__(128)
void flash_kernel(const float* __restrict__ qkv, float* __restrict__ ctx) {
    extern __shared__ float smf[];
    float* Qs = smf;
    float* Ks = Qs + 64 * FSP;
    float* Vs = Ks + 64 * FSP;
    float* Ps = Vs + 64 * FSP;

    int tid = threadIdx.x;
    int b = blockIdx.z, h = blockIdx.y;
    int q0g = blockIdx.x * 64;

    const float* qbase = qkv + ((size_t)b * SS + q0g) * LD3 + h * DHH;
    const float* kbase = qkv + ((size_t)b * SS) * LD3 + DD + h * DHH;
    const float* vbase = qkv + ((size_t)b * SS) * LD3 + 2 * DD + h * DHH;

    for (int idx = tid; idx < 64 * 64; idx += 128) {
        int s = idx >> 6, d = idx & 63;
        Qs[d * FSP + s] = qbase[(size_t)s * LD3 + d] * 0.125f;
    }

    int tq = tid >> 3, tt = tid & 7;
    int q0 = tq * 4, t0 = tt * 8, e0 = tt * 8;

    float m[4], l[4], acc_o[4][8];
    #pragma unroll
    for (int i = 0; i < 4; i++) {
        m[i] = -1e30f; l[i] = 0.f;
        #pragma unroll
        for (int j = 0; j < 8; j++) acc_o[i][j] = 0.f;
    }

    for (int kb = 0; kb < SS; kb += 64) {
        __syncthreads();
        for (int idx = tid; idx < 64 * 64; idx += 128) {
            int s = idx >> 6, d = idx & 63;
            Ks[d * FSP + s] = kbase[(size_t)(kb + s) * LD3 + d];
            Vs[s * FSP + d] = vbase[(size_t)(kb + s) * LD3 + d];
        }
        __syncthreads();

        float acc_s[4][8];
        #pragma unroll
        for (int i = 0; i < 4; i++)
            #pragma unroll
            for (int j = 0; j < 8; j++) acc_s[i][j] = 0.f;

        #pragma unroll 4
        for (int d = 0; d < 64; d++) {
            float4 a  = *(float4*)&Qs[d * FSP + q0];
            float4 b0 = *(float4*)&Ks[d * FSP + t0];
            float4 b1 = *(float4*)&Ks[d * FSP + t0 + 4];
            float av[4] = {a.x, a.y, a.z, a.w};
            float bv[8] = {b0.x, b0.y, b0.z, b0.w, b1.x, b1.y, b1.z, b1.w};
            #pragma unroll
            for (int i = 0; i < 4; i++)
                #pragma unroll
                for (int j = 0; j < 8; j++)
                    acc_s[i][j] = fmaf(av[i], bv[j], acc_s[i][j]);
        }

        #pragma unroll
        for (int i = 0; i < 4; i++) {
            float rm = acc_s[i][0];
            #pragma unroll
            for (int j = 1; j < 8; j++) rm = fmaxf(rm, acc_s[i][j]);
            #pragma unroll
            for (int o = 1; o < 8; o <<= 1)
                rm = fmaxf(rm, __shfl_xor_sync(0xffffffffu, rm, o, 8));
            float mn = fmaxf(m[i], rm);
            float sc = __expf(m[i] - mn);
            float ls = 0.f;
            #pragma unroll
            for (int j = 0; j < 8; j++) {
                float p = __expf(acc_s[i][j] - mn);
                acc_s[i][j] = p;
                ls += p;
            }
            #pragma unroll
            for (int o = 1; o < 8; o <<= 1)
                ls += __shfl_xor_sync(0xffffffffu, ls, o, 8);
            l[i] = l[i] * sc + ls;
            m[i] = mn;
            #pragma unroll
            for (int j = 0; j < 8; j++) acc_o[i][j] *= sc;
            #pragma unroll
            for (int j = 0; j < 8; j++)
                Ps[(t0 + j) * FSP + q0 + i] = acc_s[i][j];
        }
        __syncthreads();

        #pragma unroll 4
        for (int t = 0; t < 64; t++) {
            float4 a  = *(float4*)&Ps[t * FSP + q0];
            float4 b0 = *(float4*)&Vs[t * FSP + e0];
            float4 b1 = *(float4*)&Vs[t * FSP + e0 + 4];
            float av[4] = {a.x, a.y, a.z, a.w};
            float bv[8] = {b0.x, b0.y, b0.z, b0.w, b1.x, b1.y, b1.z, b1.w};
            #pragma unroll
            for (int i = 0; i < 4; i++)
                #pragma unroll
                for (int j = 0; j < 8; j++)
                    acc_o[i][j] = fmaf(av[i], bv[j], acc_o[i][j]);
        }
    }

    float* obase = ctx + ((size_t)b * SS + q0g) * DD + h * DHH;
    #pragma unroll
    for (int i = 0; i < 4; i++) {
        float inv = 1.0f / l[i];
        float4 v0 = make_float4(acc_o[i][0] * inv, acc_o[i][1] * inv,
                                acc_o[i][2] * inv, acc_o[i][3] * inv);
        float4 v1 = make_float4(acc_o[i][4] * inv, acc_o[i][5] * inv,
                                acc_o[i][6] * inv, acc_o[i][7] * inv);
        *(float4*)&obase[(size_t)(q0 + i) * DD + e0]     = v0;
        *(float4*)&obase[(size_t)(q0 + i) * DD + e0 + 4] = v1;
    }
}

// ---------------- launch ----------------
#define SYM(p, s) cudaGetSymbolAddress((void**)&p, s)

extern "C" void kernel_launch(void* const* d_in, const int* in_sizes, int n_in,
                              void* d_out, int out_size) {
    const float* x     = (const float*)d_in[0];
    const float* wq    = (const float*)d_in[1];
    const float* wk    = (const float*)d_in[2];
    const float* wv    = (const float*)d_in[3];
    const float* wo    = (const float*)d_in[4];
    const float* w1    = (const float*)d_in[5];
    const float* w2    = (const float*)d_in[6];
    const float* ln1_g = (const float*)d_in[7];
    const float* ln1_b = (const float*)d_in[8];
    const float* ln2_g = (const float*)d_in[9];
    const float* ln2_b = (const float*)d_in[10];
    const float* ln3_g = (const float*)d_in[11];
    const float* ln3_b = (const float*)d_in[12];
    float* out = (float*)d_out;

    float *p_qkv, *p_ctx, *p_attn, *p_ln2f, *p_ffn1, *p_res2;
    __nv_bfloat16 *p_ln1h, *p_ln1l, *p_ln2h, *p_ln2l, *p_ctxh, *p_ctxl, *p_f1h, *p_f1l;
    __nv_bfloat16 *p_wqh, *p_wql, *p_woh, *p_wol, *p_w1h, *p_w1l, *p_w2h, *p_w2l;
    SYM(p_qkv, g_qkv); SYM(p_ctx, g_ctx); SYM(p_attn, g_attn);
    SYM(p_ln2f, g_ln2f); SYM(p_ffn1, g_ffn1); SYM(p_res2, g_res2);
    SYM(p_ln1h, g_ln1h); SYM(p_ln1l, g_ln1l); SYM(p_ln2h, g_ln2h); SYM(p_ln2l, g_ln2l);
    SYM(p_ctxh, g_ctxh); SYM(p_ctxl, g_ctxl); SYM(p_f1h, g_f1h); SYM(p_f1l, g_f1l);
    SYM(p_wqh, g_wqh); SYM(p_wql, g_wql); SYM(p_woh, g_woh); SYM(p_wol, g_wol);
    SYM(p_w1h, g_w1h); SYM(p_w1l, g_w1l); SYM(p_w2h, g_w2h); SYM(p_w2l, g_w2l);

    cudaFuncSetAttribute(gemm_mma_kernel<0>, cudaFuncAttributeMaxDynamicSharedMemorySize, G_SMEM);
    cudaFuncSetAttribute(gemm_mma_kernel<1>, cudaFuncAttributeMaxDynamicSharedMemorySize, G_SMEM);
    cudaFuncSetAttribute(gemm_mma_kernel<2>, cudaFuncAttributeMaxDynamicSharedMemorySize, G_SMEM);
    int fsmem = 4 * 64 * FSP * (int)sizeof(float);
    cudaFuncSetAttribute(flash_kernel, cudaFuncAttributeMaxDynamicSharedMemorySize, fsmem);

    // weight prep
    transpose_qkv_kernel<<<dim3(DD / 32, DHH / 32, 48), dim3(32, 8)>>>(wq, wk, wv, p_wqh, p_wql);
    transpose_sq_kernel<<<dim3(32, 32, 3), dim3(32, 8)>>>(wo, w1, w2,
        p_woh, p_wol, p_w1h, p_w1l, p_w2h, p_w2l);

    // 1. LN1 -> bf16 hi/lo
    layernorm_kernel<<<MM, 256>>>(x, ln1_g, ln1_b, nullptr, p_ln1h, p_ln1l);
    // 2. QKV = ln1 @ wqkv   [4096,3072]
    gemm_mma_kernel<0><<<dim3(LD3 / 128, MM / 128), 256, G_SMEM>>>(
        p_ln1h, p_ln1l, p_wqh, p_wql, p_qkv, nullptr, LD3, DD);
    // 3. flash attention -> ctx fp32
    flash_kernel<<<dim3(SS / 64, HH, BB), 128, fsmem>>>(p_qkv, p_ctx);
    // 4. ctx -> bf16 hi/lo
    split_kernel<<<(MM * DD / 4 + 255) / 256, 256>>>(p_ctx, p_ctxh, p_ctxl, MM * DD / 4);
    // 5. attn = ctx @ wo + x
    gemm_mma_kernel<1><<<dim3(DD / 128, MM / 128), 256, G_SMEM>>>(
        p_ctxh, p_ctxl, p_woh, p_wol, p_attn, x, DD, DD);
    // 6. LN2 -> fp32 + hi/lo
    layernorm_kernel<<<MM, 256>>>(p_attn, ln2_g, ln2_b, p_ln2f, p_ln2h, p_ln2l);
    // 7. ffn1 = relu(ln2 @ w1)
    gemm_mma_kernel<2><<<dim3(DD / 128, MM / 128), 256, G_SMEM>>>(
        p_ln2h, p_ln2l, p_w1h, p_w1l, p_ffn1, nullptr, DD, DD);
    // 8. ffn1 -> bf16 hi/lo
    split_kernel<<<(MM * DD / 4 + 255) / 256, 256>>>(p_ffn1, p_f1h, p_f1l, MM * DD / 4);
    // 9. res2 = ffn1 @ w2 + ln2
    gemm_mma_kernel<1><<<dim3(DD / 128, MM / 128), 256, G_SMEM>>>(
        p_f1h, p_f1l, p_w2h, p_w2l, p_res2, p_ln2f, DD, DD);
    // 10. LN3 -> out
    layernorm_kernel<<<MM, 256>>>(p_res2, ln3_g, ln3_b, out, nullptr, nullptr);
}

// round 5
// speedup vs baseline: 3.3300x; 2.9613x over previous
#include <cuda_runtime.h>
#include <cuda_bf16.h>
#include <math.h>
#include <stdint.h>

#define BB 2
#define SS 2048
#define DD 1024
#define HH 16
#define DHH 64
#define MM (BB * SS)
#define LD3 (3 * DD)

// ---------------- scratch ----------------
__device__ float g_attn[MM * DD];
__device__ float g_ln2f[MM * DD];
__device__ float g_res2[MM * DD];

__device__ __nv_bfloat16 g_ln1h[MM * DD], g_ln1l[MM * DD];
__device__ __nv_bfloat16 g_ln2h[MM * DD], g_ln2l[MM * DD];
__device__ __nv_bfloat16 g_ctxh[MM * DD], g_ctxl[MM * DD];
__device__ __nv_bfloat16 g_f1h [MM * DD], g_f1l [MM * DD];
__device__ __nv_bfloat16 g_qkvh[MM * LD3], g_qkvl[MM * LD3];
__device__ __nv_bfloat16 g_wqh[LD3 * DD], g_wql[LD3 * DD];
__device__ __nv_bfloat16 g_woh[DD * DD],  g_wol[DD * DD];
__device__ __nv_bfloat16 g_w1h[DD * DD],  g_w1l[DD * DD];
__device__ __nv_bfloat16 g_w2h[DD * DD],  g_w2l[DD * DD];

// ---------------- helpers ----------------
__device__ __forceinline__ uint32_t smem_u32(const void* p) {
    uint32_t a;
    asm("{ .reg .u64 t; cvta.to.shared.u64 t, %1; cvt.u32.u64 %0, t; }" : "=r"(a) : "l"(p));
    return a;
}
__device__ __forceinline__ void cpa16(uint32_t dst, const void* src) {
    asm volatile("cp.async.cg.shared.global [%0], [%1], 16;" :: "r"(dst), "l"(src) : "memory");
}
__device__ __forceinline__ void cpcommit() { asm volatile("cp.async.commit_group;" ::: "memory"); }
template <int N> __device__ __forceinline__ void cpwait() {
    asm volatile("cp.async.wait_group %0;" :: "n"(N) : "memory");
}
__device__ __forceinline__ void ldsm_x4(uint32_t* r, uint32_t a) {
    asm volatile("ldmatrix.sync.aligned.m8n8.x4.shared.b16 {%0,%1,%2,%3}, [%4];"
        : "=r"(r[0]), "=r"(r[1]), "=r"(r[2]), "=r"(r[3]) : "r"(a));
}
__device__ __forceinline__ void ldsm_x2(uint32_t* r, uint32_t a) {
    asm volatile("ldmatrix.sync.aligned.m8n8.x2.shared.b16 {%0,%1}, [%2];"
        : "=r"(r[0]), "=r"(r[1]) : "r"(a));
}
__device__ __forceinline__ void ldsm_x2t(uint32_t* r, uint32_t a) {
    asm volatile("ldmatrix.sync.aligned.m8n8.x2.trans.shared.b16 {%0,%1}, [%2];"
        : "=r"(r[0]), "=r"(r[1]) : "r"(a));
}
__device__ __forceinline__ void mma16816(float* d, const uint32_t* a, const uint32_t* b) {
    asm volatile("mma.sync.aligned.m16n8k16.row.col.f32.bf16.bf16.f32 "
        "{%0,%1,%2,%3},{%4,%5,%6,%7},{%8,%9},{%0,%1,%2,%3};"
        : "+f"(d[0]), "+f"(d[1]), "+f"(d[2]), "+f"(d[3])
        : "r"(a[0]), "r"(a[1]), "r"(a[2]), "r"(a[3]), "r"(b[0]), "r"(b[1]));
}
__device__ __forceinline__ void bf16split(float v, __nv_bfloat16& h, __nv_bfloat16& l) {
    h = __float2bfloat16_rn(v);
    l = __float2bfloat16_rn(v - __bfloat162float(h));
}
__device__ __forceinline__ uint32_t packbf(float a, float b) {
    __nv_bfloat162 t = __float22bfloat162_rn(make_float2(a, b));
    return *(uint32_t*)&t;
}
__device__ __forceinline__ uint32_t packsplit(float a, float b, int lo) {
    __nv_bfloat16 ha, la, hb, lb;
    bf16split(a, ha, la); bf16split(b, hb, lb);
    __nv_bfloat162 t;
    if (lo) { t.x = la; t.y = lb; } else { t.x = ha; t.y = hb; }
    return *(uint32_t*)&t;
}

// ---------------- layernorm ----------------
__device__ __forceinline__ float block_sum_256(float v, float* red) {
    #pragma unroll
    for (int o = 16; o; o >>= 1) v += __shfl_xor_sync(0xffffffffu, v, o);
    int w = threadIdx.x >> 5;
    if ((threadIdx.x & 31) == 0) red[w] = v;
    __syncthreads();
    if (threadIdx.x < 8) {
        v = red[threadIdx.x];
        #pragma unroll
        for (int o = 4; o; o >>= 1) v += __shfl_xor_sync(0xffu, v, o);
        if (threadIdx.x == 0) red[0] = v;
    }
    __syncthreads();
    float r = red[0];
    __syncthreads();
    return r;
}

__global__ void layernorm_kernel(const float* __restrict__ x,
                                 const float* __restrict__ g,
                                 const float* __restrict__ b,
                                 float* __restrict__ outf,
                                 __nv_bfloat16* __restrict__ outh,
                                 __nv_bfloat16* __restrict__ outl) {
    __shared__ float red[32];
    int row = blockIdx.x;
    const float* xr = x + (size_t)row * DD;
    float v[4], s = 0.f;
    #pragma unroll
    for (int i = 0; i < 4; i++) { v[i] = xr[threadIdx.x + i * 256]; s += v[i]; }
    float mean = block_sum_256(s, red) * (1.0f / DD);
    float sq = 0.f;
    #pragma unroll
    for (int i = 0; i < 4; i++) { float d = v[i] - mean; sq += d * d; }
    float inv = rsqrtf(block_sum_256(sq, red) * (1.0f / DD) + 1e-5f);
    #pragma unroll
    for (int i = 0; i < 4; i++) {
        int c = threadIdx.x + i * 256;
        float y = (v[i] - mean) * inv * g[c] + b[c];
        size_t o = (size_t)row * DD + c;
        if (outf) outf[o] = y;
        if (outh) { __nv_bfloat16 h, l; bf16split(y, h, l); outh[o] = h; outl[o] = l; }
    }
}

// ---------------- weight transposes -> [N,K] bf16 hi/lo ----------------
__global__ void transpose_qkv_kernel(const float* __restrict__ wq, const float* __restrict__ wk,
                                     const float* __restrict__ wv,
                                     __nv_bfloat16* __restrict__ th, __nv_bfloat16* __restrict__ tl) {
    __shared__ float t[32][33];
    int sel = blockIdx.z >> 4, h = blockIdx.z & 15;
    const float* src = (sel == 0 ? wq : (sel == 1 ? wk : wv)) + (size_t)h * DD * DHH;
    int d0 = blockIdx.x * 32, dh0 = blockIdx.y * 32;
    int tx = threadIdx.x, ty = threadIdx.y;
    #pragma unroll
    for (int j = 0; j < 4; j++)
        t[ty + j * 8][tx] = src[(size_t)(d0 + ty + j * 8) * DHH + dh0 + tx];
    __syncthreads();
    int nb = sel * DD + h * DHH + dh0;
    #pragma unroll
    for (int j = 0; j < 4; j++) {
        size_t o = (size_t)(nb + ty + j * 8) * DD + d0 + tx;
        __nv_bfloat16 hh, ll; bf16split(t[tx][ty + j * 8], hh, ll);
        th[o] = hh; tl[o] = ll;
    }
}

__global__ void transpose_sq_kernel(const float* __restrict__ w0, const float* __restrict__ w1,
                                    const float* __restrict__ w2,
                                    __nv_bfloat16* __restrict__ t0h, __nv_bfloat16* __restrict__ t0l,
                                    __nv_bfloat16* __restrict__ t1h, __nv_bfloat16* __restrict__ t1l,
                                    __nv_bfloat16* __restrict__ t2h, __nv_bfloat16* __restrict__ t2l) {
    __shared__ float t[32][33];
    int z = blockIdx.z;
    const float* src = z == 0 ? w0 : (z == 1 ? w1 : w2);
    __nv_bfloat16* dh = z == 0 ? t0h : (z == 1 ? t1h : t2h);
    __nv_bfloat16* dl = z == 0 ? t0l : (z == 1 ? t1l : t2l);
    int r0 = blockIdx.x * 32, c0 = blockIdx.y * 32;
    int tx = threadIdx.x, ty = threadIdx.y;
    #pragma unroll
    for (int j = 0; j < 4; j++)
        t[ty + j * 8][tx] = src[(size_t)(r0 + ty + j * 8) * DD + c0 + tx];
    __syncthreads();
    #pragma unroll
    for (int j = 0; j < 4; j++) {
        size_t o = (size_t)(c0 + ty + j * 8) * DD + r0 + tx;
        __nv_bfloat16 hh, ll; bf16split(t[tx][ty + j * 8], hh, ll);
        dh[o] = hh; dl[o] = ll;
    }
}

// ---------------- fused mma.sync bf16x2 GEMM ----------------
// C = (Ah+Al)(Bh+Bl)^T via hi*hi + hi*lo + lo*hi in ONE K pass.
// CTA 128x128, BK=32, 8 warps, 3-stage cp.async pipeline.
#define GLDA 40
#define GTILE (128 * GLDA * 2)   // 10240 B per tile
#define GSTG  (4 * GTILE)        // 40960 B per stage (Ah,Al,Bh,Bl)
#define GSM   (3 * GSTG)         // 122880

__device__ __forceinline__ void g_load4(uint32_t st,
    const __nv_bfloat16* __restrict__ Ah, const __nv_bfloat16* __restrict__ Al,
    const __nv_bfloat16* __restrict__ Bh, const __nv_bfloat16* __restrict__ Bl,
    int brow, int bcol, int k0, int K, int tid)
{
    #pragma unroll
    for (int it = 0; it < 2; it++) {
        int g = tid + it * 256;
        int r = g >> 2, gi = g & 3;
        uint32_t so = (uint32_t)(r * GLDA + gi * 8) * 2;
        size_t ao = (size_t)(brow + r) * K + k0 + gi * 8;
        size_t bo = (size_t)(bcol + r) * K + k0 + gi * 8;
        cpa16(st + so,             Ah + ao);
        cpa16(st + GTILE + so,     Al + ao);
        cpa16(st + 2 * GTILE + so, Bh + bo);
        cpa16(st + 3 * GTILE + so, Bl + bo);
    }
}

template <int ADD, int RELU, int SPLIT>
__global__ void __launch_bounds__(256, 1)
gemm_mma_kernel(const __nv_bfloat16* __restrict__ Ah, const __nv_bfloat16* __restrict__ Al,
                const __nv_bfloat16* __restrict__ Bh, const __nv_bfloat16* __restrict__ Bl,
                float* __restrict__ Cf, __nv_bfloat16* __restrict__ Ch,
                __nv_bfloat16* __restrict__ Cl, const float* __restrict__ R, int N, int K) {
    extern __shared__ char smg[];
    uint32_t sbase = smem_u32(smg);
    int tid = threadIdx.x, lane = tid & 31, wid = tid >> 5;
    int wm = (wid >> 2) * 64, wn = (wid & 3) * 32;
    int brow = blockIdx.y * 128, bcol = blockIdx.x * 128;
    int NC = K >> 5;

    float acc[4][4][4];
    #pragma unroll
    for (int i = 0; i < 4; i++)
        #pragma unroll
        for (int j = 0; j < 4; j++)
            #pragma unroll
            for (int e = 0; e < 4; e++) acc[i][j][e] = 0.f;

    g_load4(sbase, Ah, Al, Bh, Bl, brow, bcol, 0, K, tid); cpcommit();
    g_load4(sbase + GSTG, Ah, Al, Bh, Bl, brow, bcol, 32, K, tid); cpcommit();

    int aRow = lane & 15, aCol8 = (lane >> 4) * 8;
    int bRow = lane & 7,  bCol8 = ((lane >> 3) & 1) * 8;

    for (int c = 0; c < NC; c++) {
        if (c >= NC - 2) cpwait<0>(); else cpwait<1>();
        __syncthreads();
        if (c + 2 < NC) {
            g_load4(sbase + ((c + 2) % 3) * GSTG, Ah, Al, Bh, Bl,
                    brow, bcol, (c + 2) * 32, K, tid);
            cpcommit();
        }
        uint32_t sA = sbase + (c % 3) * GSTG;

        #pragma unroll
        for (int ks = 0; ks < 2; ks++) {
            uint32_t ah[4][4], al[4][4], bh[4][2], bl[4][2];
            #pragma unroll
            for (int mt = 0; mt < 4; mt++) {
                uint32_t off = (uint32_t)((wm + mt * 16 + aRow) * GLDA + ks * 16 + aCol8) * 2;
                ldsm_x4(ah[mt], sA + off);
                ldsm_x4(al[mt], sA + GTILE + off);
            }
            #pragma unroll
            for (int nt = 0; nt < 4; nt++) {
                uint32_t off = (uint32_t)((wn + nt * 8 + bRow) * GLDA + ks * 16 + bCol8) * 2;
                ldsm_x2(bh[nt], sA + 2 * GTILE + off);
                ldsm_x2(bl[nt], sA + 3 * GTILE + off);
            }
            #pragma unroll
            for (int mt = 0; mt < 4; mt++)
                #pragma unroll
                for (int nt = 0; nt < 4; nt++) {
                    mma16816(acc[mt][nt], ah[mt], bh[nt]);
                    mma16816(acc[mt][nt], ah[mt], bl[nt]);
                    mma16816(acc[mt][nt], al[mt], bh[nt]);
                }
        }
        __syncthreads();
    }

    int r0 = brow + wm + (lane >> 2);
    int c0 = bcol + wn + (lane & 3) * 2;
    #pragma unroll
    for (int mt = 0; mt < 4; mt++)
        #pragma unroll
        for (int half = 0; half < 2; half++) {
            int row = r0 + mt * 16 + half * 8;
            #pragma unroll
            for (int nt = 0; nt < 4; nt++) {
                float vx = acc[mt][nt][half * 2], vy = acc[mt][nt][half * 2 + 1];
                size_t o = (size_t)row * N + c0 + nt * 8;
                if (ADD) { vx += R[o]; vy += R[o + 1]; }
                if (RELU) { vx = fmaxf(vx, 0.f); vy = fmaxf(vy, 0.f); }
                if (SPLIT) {
                    *(uint32_t*)&Ch[o] = packsplit(vx, vy, 0);
                    *(uint32_t*)&Cl[o] = packsplit(vx, vy, 1);
                } else {
                    *(float2*)&Cf[o] = make_float2(vx, vy);
                }
            }
        }
}

// ---------------- flash attention on tensor cores ----------------
// 64 queries/CTA, 4 warps (16 q-rows each). K-tiles of 64 keys.
// S = QhKh + QlKh + QhKl (fp32 acc); softmax fp32; O += P(bf16) * V(bf16).
#define FST 72
#define F_QH 0
#define F_QL 9216
#define F_ST0 18432
#define F_STG 27648            // per stage: KH, KL(+9216), V(+18432)
#define F_SM (F_ST0 + 2 * F_STG)   // 73728

__global__ void __launch_bounds__(128, 3)
flash_mma_kernel(const __nv_bfloat16* __restrict__ qh, const __nv_bfloat16* __restrict__ ql,
                 __nv_bfloat16* __restrict__ ch, __nv_bfloat16* __restrict__ cl) {
    extern __shared__ char smf[];
    uint32_t sb = smem_u32(smf);
    int tid = threadIdx.x, lane = tid & 31, w = tid >> 5;
    int b = blockIdx.z, h = blockIdx.y, q0 = blockIdx.x * 64;

    // load Q hi/lo tile [64 x 64]
    #pragma unroll
    for (int i = 0; i < 4; i++) {
        int g = tid + i * 128, r = g >> 3, gr = g & 7;
        size_t src = (size_t)(b * SS + q0 + r) * LD3 + h * DHH + gr * 8;
        uint32_t dst = (uint32_t)(r * FST + gr * 8) * 2;
        cpa16(sb + F_QH + dst, qh + src);
        cpa16(sb + F_QL + dst, ql + src);
    }
    cpcommit();
    cpwait<0>();
    __syncthreads();

    int lr = lane & 15, hc = (lane >> 4) * 8;
    uint32_t Qh[4][4], Ql[4][4];
    #pragma unroll
    for (int kk = 0; kk < 4; kk++) {
        uint32_t off = (uint32_t)((16 * w + lr) * FST + kk * 16 + hc) * 2;
        ldsm_x4(Qh[kk], sb + F_QH + off);
        ldsm_x4(Ql[kk], sb + F_QL + off);
    }

    // prologue K/V loads
    #pragma unroll
    for (int s = 0; s < 2; s++) {
        uint32_t st = sb + F_ST0 + s * F_STG;
        #pragma unroll
        for (int i = 0; i < 4; i++) {
            int g = tid + i * 128, r = g >> 3, gr = g & 7;
            size_t kro = (size_t)(b * SS + s * 64 + r) * LD3 + DD + h * DHH + gr * 8;
            uint32_t dst = (uint32_t)(r * FST + gr * 8) * 2;
            cpa16(st + dst,         qh + kro);
            cpa16(st + 9216 + dst,  ql + kro);
            cpa16(st + 18432 + dst, qh + kro + DD);   // V (col 2048)
        }
        cpcommit();
    }

    float m0 = -1e30f, m1 = -1e30f, l0 = 0.f, l1 = 0.f;
    float ao[8][4];
    #pragma unroll
    for (int n = 0; n < 8; n++)
        #pragma unroll
        for (int e = 0; e < 4; e++) ao[n][e] = 0.f;

    for (int kb = 0; kb < SS; kb += 64) {
        if (kb + 128 >= SS) cpwait<0>(); else cpwait<1>();
        __syncthreads();
        uint32_t st = sb + F_ST0 + ((kb >> 6) & 1) * F_STG;

        // S = Q K^T (3-term hi/lo)
        float s_[8][4];
        #pragma unroll
        for (int n = 0; n < 8; n++)
            #pragma unroll
            for (int e = 0; e < 4; e++) s_[n][e] = 0.f;
        #pragma unroll
        for (int kk = 0; kk < 4; kk++) {
            #pragma unroll
            for (int nt = 0; nt < 8; nt++) {
                uint32_t off = (uint32_t)((nt * 8 + (lane & 7)) * FST + kk * 16
                                          + ((lane >> 3) & 1) * 8) * 2;
                uint32_t bh[2], bl[2];
                ldsm_x2(bh, st + off);
                ldsm_x2(bl, st + 9216 + off);
                mma16816(s_[nt], Qh[kk], bh);
                mma16816(s_[nt], Ql[kk], bh);
                mma16816(s_[nt], Qh[kk], bl);
            }
        }

        // online softmax (rows r and r+8, scale 0.125)
        float tm0 = -1e30f, tm1 = -1e30f;
        #pragma unroll
        for (int n = 0; n < 8; n++) {
            #pragma unroll
            for (int e = 0; e < 4; e++) s_[n][e] *= 0.125f;
            tm0 = fmaxf(tm0, fmaxf(s_[n][0], s_[n][1]));
            tm1 = fmaxf(tm1, fmaxf(s_[n][2], s_[n][3]));
        }
        tm0 = fmaxf(tm0, __shfl_xor_sync(0xffffffffu, tm0, 1));
        tm0 = fmaxf(tm0, __shfl_xor_sync(0xffffffffu, tm0, 2));
        tm1 = fmaxf(tm1, __shfl_xor_sync(0xffffffffu, tm1, 1));
        tm1 = fmaxf(tm1, __shfl_xor_sync(0xffffffffu, tm1, 2));
        float mn0 = fmaxf(m0, tm0), mn1 = fmaxf(m1, tm1);
        float sc0 = __expf(m0 - mn0), sc1 = __expf(m1 - mn1);
        m0 = mn0; m1 = mn1;
        float ls0 = 0.f, ls1 = 0.f;
        #pragma unroll
        for (int n = 0; n < 8; n++) {
            s_[n][0] = __expf(s_[n][0] - mn0);
            s_[n][1] = __expf(s_[n][1] - mn0);
            s_[n][2] = __expf(s_[n][2] - mn1);
            s_[n][3] = __expf(s_[n][3] - mn1);
            ls0 += s_[n][0] + s_[n][1];
            ls1 += s_[n][2] + s_[n][3];
        }
        ls0 += __shfl_xor_sync(0xffffffffu, ls0, 1);
        ls0 += __shfl_xor_sync(0xffffffffu, ls0, 2);
        ls1 += __shfl_xor_sync(0xffffffffu, ls1, 1);
        ls1 += __shfl_xor_sync(0xffffffffu, ls1, 2);
        l0 = l0 * sc0 + ls0;
        l1 = l1 * sc1 + ls1;
        #pragma unroll
        for (int n = 0; n < 8; n++) {
            ao[n][0] *= sc0; ao[n][1] *= sc0;
            ao[n][2] *= sc1; ao[n][3] *= sc1;
        }

        // P frags (register-resident) and O += P V
        #pragma unroll
        for (int k2 = 0; k2 < 4; k2++) {
            uint32_t pa[4];
            pa[0] = packbf(s_[2 * k2][0],     s_[2 * k2][1]);
            pa[1] = packbf(s_[2 * k2][2],     s_[2 * k2][3]);
            pa[2] = packbf(s_[2 * k2 + 1][0], s_[2 * k2 + 1][1]);
            pa[3] = packbf(s_[2 * k2 + 1][2], s_[2 * k2 + 1][3]);
            #pragma unroll
            for (int nt = 0; nt < 8; nt++) {
                uint32_t bv[2];
                ldsm_x2t(bv, st + 18432
                         + (uint32_t)((k2 * 16 + (lane & 15)) * FST + nt * 8) * 2);
                mma16816(ao[nt], pa, bv);
            }
        }
        __syncthreads();

        // prefetch kb+128 into this stage
        if (kb + 128 < SS) {
            #pragma unroll
            for (int i = 0; i < 4; i++) {
                int g = tid + i * 128, r = g >> 3, gr = g & 7;
                size_t kro = (size_t)(b * SS + kb + 128 + r) * LD3 + DD + h * DHH + gr * 8;
                uint32_t dst = (uint32_t)(r * FST + gr * 8) * 2;
                cpa16(st + dst,         qh + kro);
                cpa16(st + 9216 + dst,  ql + kro);
                cpa16(st + 18432 + dst, qh + kro + DD);
            }
            cpcommit();
        }
    }

    // epilogue: ctx hi/lo
    float i0 = 1.0f / l0, i1 = 1.0f / l1;
    int row0 = b * SS + q0 + 16 * w + (lane >> 2);
    int cb = h * DHH + (lane & 3) * 2;
    #pragma unroll
    for (int nt = 0; nt < 8; nt++) {
        size_t o0 = (size_t)row0 * DD + cb + nt * 8;
        size_t o1 = (size_t)(row0 + 8) * DD + cb + nt * 8;
        float v0 = ao[nt][0] * i0, v1 = ao[nt][1] * i0;
        float v2 = ao[nt][2] * i1, v3 = ao[nt][3] * i1;
        *(uint32_t*)&ch[o0] = packsplit(v0, v1, 0);
        *(uint32_t*)&cl[o0] = packsplit(v0, v1, 1);
        *(uint32_t*)&ch[o1] = packsplit(v2, v3, 0);
        *(uint32_t*)&cl[o1] = packsplit(v2, v3, 1);
    }
}

// ---------------- launch ----------------
#define SYM(p, s) cudaGetSymbolAddress((void**)&p, s)

extern "C" void kernel_launch(void* const* d_in, const int* in_sizes, int n_in,
                              void* d_out, int out_size) {
    const float* x     = (const float*)d_in[0];
    const float* wq    = (const float*)d_in[1];
    const float* wk    = (const float*)d_in[2];
    const float* wv    = (const float*)d_in[3];
    const float* wo    = (const float*)d_in[4];
    const float* w1    = (const float*)d_in[5];
    const float* w2    = (const float*)d_in[6];
    const float* ln1_g = (const float*)d_in[7];
    const float* ln1_b = (const float*)d_in[8];
    const float* ln2_g = (const float*)d_in[9];
    const float* ln2_b = (const float*)d_in[10];
    const float* ln3_g = (const float*)d_in[11];
    const float* ln3_b = (const float*)d_in[12];
    float* out = (float*)d_out;

    float *p_attn, *p_ln2f, *p_res2;
    __nv_bfloat16 *p_ln1h, *p_ln1l, *p_ln2h, *p_ln2l, *p_ctxh, *p_ctxl, *p_f1h, *p_f1l;
    __nv_bfloat16 *p_qkvh, *p_qkvl;
    __nv_bfloat16 *p_wqh, *p_wql, *p_woh, *p_wol, *p_w1h, *p_w1l, *p_w2h, *p_w2l;
    SYM(p_attn, g_attn); SYM(p_ln2f, g_ln2f); SYM(p_res2, g_res2);
    SYM(p_ln1h, g_ln1h); SYM(p_ln1l, g_ln1l); SYM(p_ln2h, g_ln2h); SYM(p_ln2l, g_ln2l);
    SYM(p_ctxh, g_ctxh); SYM(p_ctxl, g_ctxl); SYM(p_f1h, g_f1h); SYM(p_f1l, g_f1l);
    SYM(p_qkvh, g_qkvh); SYM(p_qkvl, g_qkvl);
    SYM(p_wqh, g_wqh); SYM(p_wql, g_wql); SYM(p_woh, g_woh); SYM(p_wol, g_wol);
    SYM(p_w1h, g_w1h); SYM(p_w1l, g_w1l); SYM(p_w2h, g_w2h); SYM(p_w2l, g_w2l);

    cudaFuncSetAttribute(gemm_mma_kernel<0,0,1>, cudaFuncAttributeMaxDynamicSharedMemorySize, GSM);
    cudaFuncSetAttribute(gemm_mma_kernel<1,0,0>, cudaFuncAttributeMaxDynamicSharedMemorySize, GSM);
    cudaFuncSetAttribute(gemm_mma_kernel<0,1,1>, cudaFuncAttributeMaxDynamicSharedMemorySize, GSM);
    cudaFuncSetAttribute(flash_mma_kernel, cudaFuncAttributeMaxDynamicSharedMemorySize, F_SM);

    transpose_qkv_kernel<<<dim3(DD / 32, DHH / 32, 48), dim3(32, 8)>>>(wq, wk, wv, p_wqh, p_wql);
    transpose_sq_kernel<<<dim3(32, 32, 3), dim3(32, 8)>>>(wo, w1, w2,
        p_woh, p_wol, p_w1h, p_w1l, p_w2h, p_w2l);

    // 1. LN1 -> bf16 hi/lo
    layernorm_kernel<<<MM, 256>>>(x, ln1_g, ln1_b, nullptr, p_ln1h, p_ln1l);
    // 2. QKV (split bf16 out)
    gemm_mma_kernel<0,0,1><<<dim3(LD3 / 128, MM / 128), 256, GSM>>>(
        p_ln1h, p_ln1l, p_wqh, p_wql, nullptr, p_qkvh, p_qkvl, nullptr, LD3, DD);
    // 3. flash attention (tensor cores) -> ctx hi/lo
    flash_mma_kernel<<<dim3(SS / 64, HH, BB), 128, F_SM>>>(p_qkvh, p_qkvl, p_ctxh, p_ctxl);
    // 4. attn = ctx @ wo + x (fp32)
    gemm_mma_kernel<1,0,0><<<dim3(DD / 128, MM / 128), 256, GSM>>>(
        p_ctxh, p_ctxl, p_woh, p_wol, p_attn, nullptr, nullptr, x, DD, DD);
    // 5. LN2 -> fp32 + hi/lo
    layernorm_kernel<<<MM, 256>>>(p_attn, ln2_g, ln2_b, p_ln2f, p_ln2h, p_ln2l);
    // 6. ffn1 = relu(ln2 @ w1) (split bf16)
    gemm_mma_kernel<0,1,1><<<dim3(DD / 128, MM / 128), 256, GSM>>>(
        p_ln2h, p_ln2l, p_w1h, p_w1l, nullptr, p_f1h, p_f1l, nullptr, DD, DD);
    // 7. res2 = ffn1 @ w2 + ln2 (fp32)
    gemm_mma_kernel<1,0,0><<<dim3(DD / 128, MM / 128), 256, GSM>>>(
        p_f1h, p_f1l, p_w2h, p_w2l, p_res2, nullptr, nullptr, p_ln2f, DD, DD);
    // 8. LN3 -> out
    layernorm_kernel<<<MM, 256>>>(p_res2, ln3_g, ln3_b, out, nullptr, nullptr);
}

// round 6
// speedup vs baseline: 3.6256x; 1.0888x over previous
#include <cuda_runtime.h>
#include <cuda_bf16.h>
#include <math.h>
#include <stdint.h>

#define BB 2
#define SS 2048
#define DD 1024
#define HH 16
#define DHH 64
#define MM (BB * SS)
#define LD3 (3 * DD)

// ---------------- scratch ----------------
__device__ float g_attn[MM * DD];
__device__ float g_ln2f[MM * DD];
__device__ float g_res2[MM * DD];

__device__ __nv_bfloat16 g_ln1h[MM * DD], g_ln1l[MM * DD];
__device__ __nv_bfloat16 g_ln2h[MM * DD], g_ln2l[MM * DD];
__device__ __nv_bfloat16 g_ctxh[MM * DD], g_ctxl[MM * DD];
__device__ __nv_bfloat16 g_f1h [MM * DD], g_f1l [MM * DD];
__device__ __nv_bfloat16 g_qkvh[MM * LD3], g_qkvl[MM * LD3];
__device__ __nv_bfloat16 g_wqh[LD3 * DD], g_wql[LD3 * DD];
__device__ __nv_bfloat16 g_woh[DD * DD],  g_wol[DD * DD];
__device__ __nv_bfloat16 g_w1h[DD * DD],  g_w1l[DD * DD];
__device__ __nv_bfloat16 g_w2h[DD * DD],  g_w2l[DD * DD];

// ---------------- helpers ----------------
__device__ __forceinline__ uint32_t smem_u32(const void* p) {
    uint32_t a;
    asm("{ .reg .u64 t; cvta.to.shared.u64 t, %1; cvt.u32.u64 %0, t; }" : "=r"(a) : "l"(p));
    return a;
}
__device__ __forceinline__ void cpa16(uint32_t dst, const void* src) {
    asm volatile("cp.async.cg.shared.global [%0], [%1], 16;" :: "r"(dst), "l"(src) : "memory");
}
__device__ __forceinline__ void cpcommit() { asm volatile("cp.async.commit_group;" ::: "memory"); }
template <int N> __device__ __forceinline__ void cpwait() {
    asm volatile("cp.async.wait_group %0;" :: "n"(N) : "memory");
}
__device__ __forceinline__ void ldsm_x4(uint32_t* r, uint32_t a) {
    asm volatile("ldmatrix.sync.aligned.m8n8.x4.shared.b16 {%0,%1,%2,%3}, [%4];"
        : "=r"(r[0]), "=r"(r[1]), "=r"(r[2]), "=r"(r[3]) : "r"(a));
}
__device__ __forceinline__ void ldsm_x2(uint32_t* r, uint32_t a) {
    asm volatile("ldmatrix.sync.aligned.m8n8.x2.shared.b16 {%0,%1}, [%2];"
        : "=r"(r[0]), "=r"(r[1]) : "r"(a));
}
__device__ __forceinline__ void ldsm_x2t(uint32_t* r, uint32_t a) {
    asm volatile("ldmatrix.sync.aligned.m8n8.x2.trans.shared.b16 {%0,%1}, [%2];"
        : "=r"(r[0]), "=r"(r[1]) : "r"(a));
}
__device__ __forceinline__ void mma16816(float* d, const uint32_t* a, const uint32_t* b) {
    asm volatile("mma.sync.aligned.m16n8k16.row.col.f32.bf16.bf16.f32 "
        "{%0,%1,%2,%3},{%4,%5,%6,%7},{%8,%9},{%0,%1,%2,%3};"
        : "+f"(d[0]), "+f"(d[1]), "+f"(d[2]), "+f"(d[3])
        : "r"(a[0]), "r"(a[1]), "r"(a[2]), "r"(a[3]), "r"(b[0]), "r"(b[1]));
}
__device__ __forceinline__ void bf16split(float v, __nv_bfloat16& h, __nv_bfloat16& l) {
    h = __float2bfloat16_rn(v);
    l = __float2bfloat16_rn(v - __bfloat162float(h));
}
__device__ __forceinline__ uint32_t packbf(float a, float b) {
    __nv_bfloat162 t = __float22bfloat162_rn(make_float2(a, b));
    return *(uint32_t*)&t;
}
__device__ __forceinline__ uint32_t packsplit(float a, float b, int lo) {
    __nv_bfloat16 ha, la, hb, lb;
    bf16split(a, ha, la); bf16split(b, hb, lb);
    __nv_bfloat162 t;
    if (lo) { t.x = la; t.y = lb; } else { t.x = ha; t.y = hb; }
    return *(uint32_t*)&t;
}

// ---------------- layernorm ----------------
__device__ __forceinline__ float block_sum_256(float v, float* red) {
    #pragma unroll
    for (int o = 16; o; o >>= 1) v += __shfl_xor_sync(0xffffffffu, v, o);
    int w = threadIdx.x >> 5;
    if ((threadIdx.x & 31) == 0) red[w] = v;
    __syncthreads();
    if (threadIdx.x < 8) {
        v = red[threadIdx.x];
        #pragma unroll
        for (int o = 4; o; o >>= 1) v += __shfl_xor_sync(0xffu, v, o);
        if (threadIdx.x == 0) red[0] = v;
    }
    __syncthreads();
    float r = red[0];
    __syncthreads();
    return r;
}

__global__ void layernorm_kernel(const float* __restrict__ x,
                                 const float* __restrict__ g,
                                 const float* __restrict__ b,
                                 float* __restrict__ outf,
                                 __nv_bfloat16* __restrict__ outh,
                                 __nv_bfloat16* __restrict__ outl) {
    __shared__ float red[32];
    int row = blockIdx.x;
    const float* xr = x + (size_t)row * DD;
    float v[4], s = 0.f;
    #pragma unroll
    for (int i = 0; i < 4; i++) { v[i] = xr[threadIdx.x + i * 256]; s += v[i]; }
    float mean = block_sum_256(s, red) * (1.0f / DD);
    float sq = 0.f;
    #pragma unroll
    for (int i = 0; i < 4; i++) { float d = v[i] - mean; sq += d * d; }
    float inv = rsqrtf(block_sum_256(sq, red) * (1.0f / DD) + 1e-5f);
    #pragma unroll
    for (int i = 0; i < 4; i++) {
        int c = threadIdx.x + i * 256;
        float y = (v[i] - mean) * inv * g[c] + b[c];
        size_t o = (size_t)row * DD + c;
        if (outf) outf[o] = y;
        if (outh) { __nv_bfloat16 h, l; bf16split(y, h, l); outh[o] = h; outl[o] = l; }
    }
}

// ---------------- weight transposes -> [N,K] bf16 hi/lo ----------------
__global__ void transpose_qkv_kernel(const float* __restrict__ wq, const float* __restrict__ wk,
                                     const float* __restrict__ wv,
                                     __nv_bfloat16* __restrict__ th, __nv_bfloat16* __restrict__ tl) {
    __shared__ float t[32][33];
    int sel = blockIdx.z >> 4, h = blockIdx.z & 15;
    const float* src = (sel == 0 ? wq : (sel == 1 ? wk : wv)) + (size_t)h * DD * DHH;
    int d0 = blockIdx.x * 32, dh0 = blockIdx.y * 32;
    int tx = threadIdx.x, ty = threadIdx.y;
    #pragma unroll
    for (int j = 0; j < 4; j++)
        t[ty + j * 8][tx] = src[(size_t)(d0 + ty + j * 8) * DHH + dh0 + tx];
    __syncthreads();
    int nb = sel * DD + h * DHH + dh0;
    #pragma unroll
    for (int j = 0; j < 4; j++) {
        size_t o = (size_t)(nb + ty + j * 8) * DD + d0 + tx;
        __nv_bfloat16 hh, ll; bf16split(t[tx][ty + j * 8], hh, ll);
        th[o] = hh; tl[o] = ll;
    }
}

__global__ void transpose_sq_kernel(const float* __restrict__ w0, const float* __restrict__ w1,
                                    const float* __restrict__ w2,
                                    __nv_bfloat16* __restrict__ t0h, __nv_bfloat16* __restrict__ t0l,
                                    __nv_bfloat16* __restrict__ t1h, __nv_bfloat16* __restrict__ t1l,
                                    __nv_bfloat16* __restrict__ t2h, __nv_bfloat16* __restrict__ t2l) {
    __shared__ float t[32][33];
    int z = blockIdx.z;
    const float* src = z == 0 ? w0 : (z == 1 ? w1 : w2);
    __nv_bfloat16* dh = z == 0 ? t0h : (z == 1 ? t1h : t2h);
    __nv_bfloat16* dl = z == 0 ? t0l : (z == 1 ? t1l : t2l);
    int r0 = blockIdx.x * 32, c0 = blockIdx.y * 32;
    int tx = threadIdx.x, ty = threadIdx.y;
    #pragma unroll
    for (int j = 0; j < 4; j++)
        t[ty + j * 8][tx] = src[(size_t)(r0 + ty + j * 8) * DD + c0 + tx];
    __syncthreads();
    #pragma unroll
    for (int j = 0; j < 4; j++) {
        size_t o = (size_t)(c0 + ty + j * 8) * DD + r0 + tx;
        __nv_bfloat16 hh, ll; bf16split(t[tx][ty + j * 8], hh, ll);
        dh[o] = hh; dl[o] = ll;
    }
}

// ---------------- fused mma.sync bf16x2 GEMM (2-stage, occ 2) ----------------
#define GLDA 40
#define GTILE (128 * GLDA * 2)   // 10240 B per tile
#define GSTG  (4 * GTILE)        // 40960 B per stage (Ah,Al,Bh,Bl)
#define GSM   (2 * GSTG)         // 81920

__device__ __forceinline__ void g_load4(uint32_t st,
    const __nv_bfloat16* __restrict__ Ah, const __nv_bfloat16* __restrict__ Al,
    const __nv_bfloat16* __restrict__ Bh, const __nv_bfloat16* __restrict__ Bl,
    int brow, int bcol, int k0, int K, int tid)
{
    #pragma unroll
    for (int it = 0; it < 2; it++) {
        int g = tid + it * 256;
        int r = g >> 2, gi = g & 3;
        uint32_t so = (uint32_t)(r * GLDA + gi * 8) * 2;
        size_t ao = (size_t)(brow + r) * K + k0 + gi * 8;
        size_t bo = (size_t)(bcol + r) * K + k0 + gi * 8;
        cpa16(st + so,             Ah + ao);
        cpa16(st + GTILE + so,     Al + ao);
        cpa16(st + 2 * GTILE + so, Bh + bo);
        cpa16(st + 3 * GTILE + so, Bl + bo);
    }
}

template <int ADD, int RELU, int SPLIT>
__global__ void __launch_bounds__(256, 2)
gemm_mma_kernel(const __nv_bfloat16* __restrict__ Ah, const __nv_bfloat16* __restrict__ Al,
                const __nv_bfloat16* __restrict__ Bh, const __nv_bfloat16* __restrict__ Bl,
                float* __restrict__ Cf, __nv_bfloat16* __restrict__ Ch,
                __nv_bfloat16* __restrict__ Cl, const float* __restrict__ R, int N, int K) {
    extern __shared__ char smg[];
    uint32_t sbase = smem_u32(smg);
    int tid = threadIdx.x, lane = tid & 31, wid = tid >> 5;
    int wm = (wid >> 2) * 64, wn = (wid & 3) * 32;
    int brow = blockIdx.y * 128, bcol = blockIdx.x * 128;
    int NC = K >> 5;

    float acc[4][4][4];
    #pragma unroll
    for (int i = 0; i < 4; i++)
        #pragma unroll
        for (int j = 0; j < 4; j++)
            #pragma unroll
            for (int e = 0; e < 4; e++) acc[i][j][e] = 0.f;

    g_load4(sbase, Ah, Al, Bh, Bl, brow, bcol, 0, K, tid); cpcommit();
    g_load4(sbase + GSTG, Ah, Al, Bh, Bl, brow, bcol, 32, K, tid); cpcommit();

    int aRow = lane & 15, aCol8 = (lane >> 4) * 8;
    int bRow = lane & 7,  bCol8 = ((lane >> 3) & 1) * 8;

    for (int c = 0; c < NC; c++) {
        if (c == NC - 1) cpwait<0>(); else cpwait<1>();
        __syncthreads();
        uint32_t sA = sbase + (c & 1) * GSTG;

        #pragma unroll
        for (int ks = 0; ks < 2; ks++) {
            uint32_t ah[4][4], al[4][4];
            #pragma unroll
            for (int mt = 0; mt < 4; mt++) {
                uint32_t off = (uint32_t)((wm + mt * 16 + aRow) * GLDA + ks * 16 + aCol8) * 2;
                ldsm_x4(ah[mt], sA + off);
                ldsm_x4(al[mt], sA + GTILE + off);
            }
            #pragma unroll
            for (int nt = 0; nt < 4; nt++) {
                uint32_t bh[2], bl[2];
                uint32_t off = (uint32_t)((wn + nt * 8 + bRow) * GLDA + ks * 16 + bCol8) * 2;
                ldsm_x2(bh, sA + 2 * GTILE + off);
                ldsm_x2(bl, sA + 3 * GTILE + off);
                #pragma unroll
                for (int mt = 0; mt < 4; mt++) {
                    mma16816(acc[mt][nt], ah[mt], bh);
                    mma16816(acc[mt][nt], ah[mt], bl);
                    mma16816(acc[mt][nt], al[mt], bh);
                }
            }
        }
        __syncthreads();
        if (c + 2 < NC) {
            g_load4(sA, Ah, Al, Bh, Bl, brow, bcol, (c + 2) * 32, K, tid);
            cpcommit();
        }
    }

    int r0 = brow + wm + (lane >> 2);
    int c0 = bcol + wn + (lane & 3) * 2;
    #pragma unroll
    for (int mt = 0; mt < 4; mt++)
        #pragma unroll
        for (int half = 0; half < 2; half++) {
            int row = r0 + mt * 16 + half * 8;
            #pragma unroll
            for (int nt = 0; nt < 4; nt++) {
                float vx = acc[mt][nt][half * 2], vy = acc[mt][nt][half * 2 + 1];
                size_t o = (size_t)row * N + c0 + nt * 8;
                if (ADD) { vx += R[o]; vy += R[o + 1]; }
                if (RELU) { vx = fmaxf(vx, 0.f); vy = fmaxf(vy, 0.f); }
                if (SPLIT) {
                    *(uint32_t*)&Ch[o] = packsplit(vx, vy, 0);
                    *(uint32_t*)&Cl[o] = packsplit(vx, vy, 1);
                } else {
                    *(float2*)&Cf[o] = make_float2(vx, vy);
                }
            }
        }
}

// ---------------- flash attention on tensor cores ----------------
#define FST 72
#define F_QH 0
#define F_QL 9216
#define F_ST0 18432
#define F_STG 27648
#define F_SM (F_ST0 + 2 * F_STG)   // 73728

__global__ void __launch_bounds__(128, 3)
flash_mma_kernel(const __nv_bfloat16* __restrict__ qh, const __nv_bfloat16* __restrict__ ql,
                 __nv_bfloat16* __restrict__ ch, __nv_bfloat16* __restrict__ cl) {
    extern __shared__ char smf[];
    uint32_t sb = smem_u32(smf);
    int tid = threadIdx.x, lane = tid & 31, w = tid >> 5;
    int b = blockIdx.z, h = blockIdx.y, q0 = blockIdx.x * 64;

    #pragma unroll
    for (int i = 0; i < 4; i++) {
        int g = tid + i * 128, r = g >> 3, gr = g & 7;
        size_t src = (size_t)(b * SS + q0 + r) * LD3 + h * DHH + gr * 8;
        uint32_t dst = (uint32_t)(r * FST + gr * 8) * 2;
        cpa16(sb + F_QH + dst, qh + src);
        cpa16(sb + F_QL + dst, ql + src);
    }
    cpcommit();
    cpwait<0>();
    __syncthreads();

    int lr = lane & 15, hc = (lane >> 4) * 8;
    uint32_t Qh[4][4], Ql[4][4];
    #pragma unroll
    for (int kk = 0; kk < 4; kk++) {
        uint32_t off = (uint32_t)((16 * w + lr) * FST + kk * 16 + hc) * 2;
        ldsm_x4(Qh[kk], sb + F_QH + off);
        ldsm_x4(Ql[kk], sb + F_QL + off);
    }

    #pragma unroll
    for (int s = 0; s < 2; s++) {
        uint32_t st = sb + F_ST0 + s * F_STG;
        #pragma unroll
        for (int i = 0; i < 4; i++) {
            int g = tid + i * 128, r = g >> 3, gr = g & 7;
            size_t kro = (size_t)(b * SS + s * 64 + r) * LD3 + DD + h * DHH + gr * 8;
            uint32_t dst = (uint32_t)(r * FST + gr * 8) * 2;
            cpa16(st + dst,         qh + kro);
            cpa16(st + 9216 + dst,  ql + kro);
            cpa16(st + 18432 + dst, qh + kro + DD);
        }
        cpcommit();
    }

    float m0 = -1e30f, m1 = -1e30f, l0 = 0.f, l1 = 0.f;
    float ao[8][4];
    #pragma unroll
    for (int n = 0; n < 8; n++)
        #pragma unroll
        for (int e = 0; e < 4; e++) ao[n][e] = 0.f;

    for (int kb = 0; kb < SS; kb += 64) {
        if (kb + 128 >= SS) cpwait<0>(); else cpwait<1>();
        __syncthreads();
        uint32_t st = sb + F_ST0 + ((kb >> 6) & 1) * F_STG;

        float s_[8][4];
        #pragma unroll
        for (int n = 0; n < 8; n++)
            #pragma unroll
            for (int e = 0; e < 4; e++) s_[n][e] = 0.f;
        #pragma unroll
        for (int kk = 0; kk < 4; kk++) {
            #pragma unroll
            for (int nt = 0; nt < 8; nt++) {
                uint32_t off = (uint32_t)((nt * 8 + (lane & 7)) * FST + kk * 16
                                          + ((lane >> 3) & 1) * 8) * 2;
                uint32_t bh[2], bl[2];
                ldsm_x2(bh, st + off);
                ldsm_x2(bl, st + 9216 + off);
                mma16816(s_[nt], Qh[kk], bh);
                mma16816(s_[nt], Ql[kk], bh);
                mma16816(s_[nt], Qh[kk], bl);
            }
        }

        float tm0 = -1e30f, tm1 = -1e30f;
        #pragma unroll
        for (int n = 0; n < 8; n++) {
            #pragma unroll
            for (int e = 0; e < 4; e++) s_[n][e] *= 0.125f;
            tm0 = fmaxf(tm0, fmaxf(s_[n][0], s_[n][1]));
            tm1 = fmaxf(tm1, fmaxf(s_[n][2], s_[n][3]));
        }
        tm0 = fmaxf(tm0, __shfl_xor_sync(0xffffffffu, tm0, 1));
        tm0 = fmaxf(tm0, __shfl_xor_sync(0xffffffffu, tm0, 2));
        tm1 = fmaxf(tm1, __shfl_xor_sync(0xffffffffu, tm1, 1));
        tm1 = fmaxf(tm1, __shfl_xor_sync(0xffffffffu, tm1, 2));
        float mn0 = fmaxf(m0, tm0), mn1 = fmaxf(m1, tm1);
        float sc0 = __expf(m0 - mn0), sc1 = __expf(m1 - mn1);
        m0 = mn0; m1 = mn1;
        float ls0 = 0.f, ls1 = 0.f;
        #pragma unroll
        for (int n = 0; n < 8; n++) {
            s_[n][0] = __expf(s_[n][0] - mn0);
            s_[n][1] = __expf(s_[n][1] - mn0);
            s_[n][2] = __expf(s_[n][2] - mn1);
            s_[n][3] = __expf(s_[n][3] - mn1);
            ls0 += s_[n][0] + s_[n][1];
            ls1 += s_[n][2] + s_[n][3];
        }
        ls0 += __shfl_xor_sync(0xffffffffu, ls0, 1);
        ls0 += __shfl_xor_sync(0xffffffffu, ls0, 2);
        ls1 += __shfl_xor_sync(0xffffffffu, ls1, 1);
        ls1 += __shfl_xor_sync(0xffffffffu, ls1, 2);
        l0 = l0 * sc0 + ls0;
        l1 = l1 * sc1 + ls1;
        #pragma unroll
        for (int n = 0; n < 8; n++) {
            ao[n][0] *= sc0; ao[n][1] *= sc0;
            ao[n][2] *= sc1; ao[n][3] *= sc1;
        }

        #pragma unroll
        for (int k2 = 0; k2 < 4; k2++) {
            uint32_t pa[4];
            pa[0] = packbf(s_[2 * k2][0],     s_[2 * k2][1]);
            pa[1] = packbf(s_[2 * k2][2],     s_[2 * k2][3]);
            pa[2] = packbf(s_[2 * k2 + 1][0], s_[2 * k2 + 1][1]);
            pa[3] = packbf(s_[2 * k2 + 1][2], s_[2 * k2 + 1][3]);
            #pragma unroll
            for (int nt = 0; nt < 8; nt++) {
                uint32_t bv[2];
                ldsm_x2t(bv, st + 18432
                         + (uint32_t)((k2 * 16 + (lane & 15)) * FST + nt * 8) * 2);
                mma16816(ao[nt], pa, bv);
            }
        }
        __syncthreads();

        if (kb + 128 < SS) {
            #pragma unroll
            for (int i = 0; i < 4; i++) {
                int g = tid + i * 128, r = g >> 3, gr = g & 7;
                size_t kro = (size_t)(b * SS + kb + 128 + r) * LD3 + DD + h * DHH + gr * 8;
                uint32_t dst = (uint32_t)(r * FST + gr * 8) * 2;
                cpa16(st + dst,         qh + kro);
                cpa16(st + 9216 + dst,  ql + kro);
                cpa16(st + 18432 + dst, qh + kro + DD);
            }
            cpcommit();
        }
    }

    float i0 = 1.0f / l0, i1 = 1.0f / l1;
    int row0 = b * SS + q0 + 16 * w + (lane >> 2);
    int cb = h * DHH + (lane & 3) * 2;
    #pragma unroll
    for (int nt = 0; nt < 8; nt++) {
        size_t o0 = (size_t)row0 * DD + cb + nt * 8;
        size_t o1 = (size_t)(row0 + 8) * DD + cb + nt * 8;
        float v0 = ao[nt][0] * i0, v1 = ao[nt][1] * i0;
        float v2 = ao[nt][2] * i1, v3 = ao[nt][3] * i1;
        *(uint32_t*)&ch[o0] = packsplit(v0, v1, 0);
        *(uint32_t*)&cl[o0] = packsplit(v0, v1, 1);
        *(uint32_t*)&ch[o1] = packsplit(v2, v3, 0);
        *(uint32_t*)&cl[o1] = packsplit(v2, v3, 1);
    }
}

// ---------------- launch ----------------
#define SYM(p, s) cudaGetSymbolAddress((void**)&p, s)

extern "C" void kernel_launch(void* const* d_in, const int* in_sizes, int n_in,
                              void* d_out, int out_size) {
    const float* x     = (const float*)d_in[0];
    const float* wq    = (const float*)d_in[1];
    const float* wk    = (const float*)d_in[2];
    const float* wv    = (const float*)d_in[3];
    const float* wo    = (const float*)d_in[4];
    const float* w1    = (const float*)d_in[5];
    const float* w2    = (const float*)d_in[6];
    const float* ln1_g = (const float*)d_in[7];
    const float* ln1_b = (const float*)d_in[8];
    const float* ln2_g = (const float*)d_in[9];
    const float* ln2_b = (const float*)d_in[10];
    const float* ln3_g = (const float*)d_in[11];
    const float* ln3_b = (const float*)d_in[12];
    float* out = (float*)d_out;

    float *p_attn, *p_ln2f, *p_res2;
    __nv_bfloat16 *p_ln1h, *p_ln1l, *p_ln2h, *p_ln2l, *p_ctxh, *p_ctxl, *p_f1h, *p_f1l;
    __nv_bfloat16 *p_qkvh, *p_qkvl;
    __nv_bfloat16 *p_wqh, *p_wql, *p_woh, *p_wol, *p_w1h, *p_w1l, *p_w2h, *p_w2l;
    SYM(p_attn, g_attn); SYM(p_ln2f, g_ln2f); SYM(p_res2, g_res2);
    SYM(p_ln1h, g_ln1h); SYM(p_ln1l, g_ln1l); SYM(p_ln2h, g_ln2h); SYM(p_ln2l, g_ln2l);
    SYM(p_ctxh, g_ctxh); SYM(p_ctxl, g_ctxl); SYM(p_f1h, g_f1h); SYM(p_f1l, g_f1l);
    SYM(p_qkvh, g_qkvh); SYM(p_qkvl, g_qkvl);
    SYM(p_wqh, g_wqh); SYM(p_wql, g_wql); SYM(p_woh, g_woh); SYM(p_wol, g_wol);
    SYM(p_w1h, g_w1h); SYM(p_w1l, g_w1l); SYM(p_w2h, g_w2h); SYM(p_w2l, g_w2l);

    cudaFuncSetAttribute(gemm_mma_kernel<0,0,1>, cudaFuncAttributeMaxDynamicSharedMemorySize, GSM);
    cudaFuncSetAttribute(gemm_mma_kernel<1,0,0>, cudaFuncAttributeMaxDynamicSharedMemorySize, GSM);
    cudaFuncSetAttribute(gemm_mma_kernel<0,1,1>, cudaFuncAttributeMaxDynamicSharedMemorySize, GSM);
    cudaFuncSetAttribute(flash_mma_kernel, cudaFuncAttributeMaxDynamicSharedMemorySize, F_SM);

    transpose_qkv_kernel<<<dim3(DD / 32, DHH / 32, 48), dim3(32, 8)>>>(wq, wk, wv, p_wqh, p_wql);
    transpose_sq_kernel<<<dim3(32, 32, 3), dim3(32, 8)>>>(wo, w1, w2,
        p_woh, p_wol, p_w1h, p_w1l, p_w2h, p_w2l);

    layernorm_kernel<<<MM, 256>>>(x, ln1_g, ln1_b, nullptr, p_ln1h, p_ln1l);
    gemm_mma_kernel<0,0,1><<<dim3(LD3 / 128, MM / 128), 256, GSM>>>(
        p_ln1h, p_ln1l, p_wqh, p_wql, nullptr, p_qkvh, p_qkvl, nullptr, LD3, DD);
    flash_mma_kernel<<<dim3(SS / 64, HH, BB), 128, F_SM>>>(p_qkvh, p_qkvl, p_ctxh, p_ctxl);
    gemm_mma_kernel<1,0,0><<<dim3(DD / 128, MM / 128), 256, GSM>>>(
        p_ctxh, p_ctxl, p_woh, p_wol, p_attn, nullptr, nullptr, x, DD, DD);
    layernorm_kernel<<<MM, 256>>>(p_attn, ln2_g, ln2_b, p_ln2f, p_ln2h, p_ln2l);
    gemm_mma_kernel<0,1,1><<<dim3(DD / 128, MM / 128), 256, GSM>>>(
        p_ln2h, p_ln2l, p_w1h, p_w1l, nullptr, p_f1h, p_f1l, nullptr, DD, DD);
    gemm_mma_kernel<1,0,0><<<dim3(DD / 128, MM / 128), 256, GSM>>>(
        p_f1h, p_f1l, p_w2h, p_w2l, p_res2, nullptr, nullptr, p_ln2f, DD, DD);
    layernorm_kernel<<<MM, 256>>>(p_res2, ln3_g, ln3_b, out, nullptr, nullptr);
}

// round 7
// speedup vs baseline: 3.7219x; 1.0266x over previous
#include <cuda_runtime.h>
#include <cuda_bf16.h>
#include <math.h>
#include <stdint.h>

#define BB 2
#define SS 2048
#define DD 1024
#define HH 16
#define DHH 64
#define MM (BB * SS)
#define LD3 (3 * DD)

// ---------------- scratch ----------------
__device__ float g_attn[MM * DD];
__device__ float g_ln2f[MM * DD];
__device__ float g_res2[MM * DD];

__device__ __nv_bfloat16 g_ln1h[MM * DD], g_ln1l[MM * DD];
__device__ __nv_bfloat16 g_ln2h[MM * DD], g_ln2l[MM * DD];
__device__ __nv_bfloat16 g_ctxh[MM * DD], g_ctxl[MM * DD];
__device__ __nv_bfloat16 g_f1h [MM * DD], g_f1l [MM * DD];
__device__ __nv_bfloat16 g_qkvh[MM * LD3], g_qkvl[MM * LD3];
__device__ __nv_bfloat16 g_wqh[LD3 * DD], g_wql[LD3 * DD];
__device__ __nv_bfloat16 g_woh[DD * DD],  g_wol[DD * DD];
__device__ __nv_bfloat16 g_w1h[DD * DD],  g_w1l[DD * DD];
__device__ __nv_bfloat16 g_w2h[DD * DD],  g_w2l[DD * DD];

// ---------------- helpers ----------------
__device__ __forceinline__ uint32_t smem_u32(const void* p) {
    uint32_t a;
    asm("{ .reg .u64 t; cvta.to.shared.u64 t, %1; cvt.u32.u64 %0, t; }" : "=r"(a) : "l"(p));
    return a;
}
__device__ __forceinline__ void cpa16(uint32_t dst, const void* src) {
    asm volatile("cp.async.cg.shared.global [%0], [%1], 16;" :: "r"(dst), "l"(src) : "memory");
}
__device__ __forceinline__ void cpcommit() { asm volatile("cp.async.commit_group;" ::: "memory"); }
template <int N> __device__ __forceinline__ void cpwait() {
    asm volatile("cp.async.wait_group %0;" :: "n"(N) : "memory");
}
__device__ __forceinline__ void ldsm_x4(uint32_t* r, uint32_t a) {
    asm volatile("ldmatrix.sync.aligned.m8n8.x4.shared.b16 {%0,%1,%2,%3}, [%4];"
        : "=r"(r[0]), "=r"(r[1]), "=r"(r[2]), "=r"(r[3]) : "r"(a));
}
__device__ __forceinline__ void ldsm_x2(uint32_t* r, uint32_t a) {
    asm volatile("ldmatrix.sync.aligned.m8n8.x2.shared.b16 {%0,%1}, [%2];"
        : "=r"(r[0]), "=r"(r[1]) : "r"(a));
}
__device__ __forceinline__ void ldsm_x2t(uint32_t* r, uint32_t a) {
    asm volatile("ldmatrix.sync.aligned.m8n8.x2.trans.shared.b16 {%0,%1}, [%2];"
        : "=r"(r[0]), "=r"(r[1]) : "r"(a));
}
__device__ __forceinline__ void mma16816(float* d, const uint32_t* a, const uint32_t* b) {
    asm volatile("mma.sync.aligned.m16n8k16.row.col.f32.bf16.bf16.f32 "
        "{%0,%1,%2,%3},{%4,%5,%6,%7},{%8,%9},{%0,%1,%2,%3};"
        : "+f"(d[0]), "+f"(d[1]), "+f"(d[2]), "+f"(d[3])
        : "r"(a[0]), "r"(a[1]), "r"(a[2]), "r"(a[3]), "r"(b[0]), "r"(b[1]));
}
__device__ __forceinline__ void bf16split(float v, __nv_bfloat16& h, __nv_bfloat16& l) {
    h = __float2bfloat16_rn(v);
    l = __float2bfloat16_rn(v - __bfloat162float(h));
}
__device__ __forceinline__ uint32_t packbf(float a, float b) {
    __nv_bfloat162 t = __float22bfloat162_rn(make_float2(a, b));
    return *(uint32_t*)&t;
}
__device__ __forceinline__ uint32_t packsplit(float a, float b, int lo) {
    __nv_bfloat16 ha, la, hb, lb;
    bf16split(a, ha, la); bf16split(b, hb, lb);
    __nv_bfloat162 t;
    if (lo) { t.x = la; t.y = lb; } else { t.x = ha; t.y = hb; }
    return *(uint32_t*)&t;
}

// ---------------- layernorm ----------------
__device__ __forceinline__ float block_sum_256(float v, float* red) {
    #pragma unroll
    for (int o = 16; o; o >>= 1) v += __shfl_xor_sync(0xffffffffu, v, o);
    int w = threadIdx.x >> 5;
    if ((threadIdx.x & 31) == 0) red[w] = v;
    __syncthreads();
    if (threadIdx.x < 8) {
        v = red[threadIdx.x];
        #pragma unroll
        for (int o = 4; o; o >>= 1) v += __shfl_xor_sync(0xffu, v, o);
        if (threadIdx.x == 0) red[0] = v;
    }
    __syncthreads();
    float r = red[0];
    __syncthreads();
    return r;
}

__global__ void layernorm_kernel(const float* __restrict__ x,
                                 const float* __restrict__ g,
                                 const float* __restrict__ b,
                                 float* __restrict__ outf,
                                 __nv_bfloat16* __restrict__ outh,
                                 __nv_bfloat16* __restrict__ outl) {
    __shared__ float red[32];
    int row = blockIdx.x;
    const float* xr = x + (size_t)row * DD;
    float v[4], s = 0.f;
    #pragma unroll
    for (int i = 0; i < 4; i++) { v[i] = xr[threadIdx.x + i * 256]; s += v[i]; }
    float mean = block_sum_256(s, red) * (1.0f / DD);
    float sq = 0.f;
    #pragma unroll
    for (int i = 0; i < 4; i++) { float d = v[i] - mean; sq += d * d; }
    float inv = rsqrtf(block_sum_256(sq, red) * (1.0f / DD) + 1e-5f);
    #pragma unroll
    for (int i = 0; i < 4; i++) {
        int c = threadIdx.x + i * 256;
        float y = (v[i] - mean) * inv * g[c] + b[c];
        size_t o = (size_t)row * DD + c;
        if (outf) outf[o] = y;
        if (outh) { __nv_bfloat16 h, l; bf16split(y, h, l); outh[o] = h; outl[o] = l; }
    }
}

// ---------------- weight transposes -> [N,K] bf16 hi/lo ----------------
__global__ void transpose_qkv_kernel(const float* __restrict__ wq, const float* __restrict__ wk,
                                     const float* __restrict__ wv,
                                     __nv_bfloat16* __restrict__ th, __nv_bfloat16* __restrict__ tl) {
    __shared__ float t[32][33];
    int sel = blockIdx.z >> 4, h = blockIdx.z & 15;
    const float* src = (sel == 0 ? wq : (sel == 1 ? wk : wv)) + (size_t)h * DD * DHH;
    int d0 = blockIdx.x * 32, dh0 = blockIdx.y * 32;
    int tx = threadIdx.x, ty = threadIdx.y;
    #pragma unroll
    for (int j = 0; j < 4; j++)
        t[ty + j * 8][tx] = src[(size_t)(d0 + ty + j * 8) * DHH + dh0 + tx];
    __syncthreads();
    int nb = sel * DD + h * DHH + dh0;
    #pragma unroll
    for (int j = 0; j < 4; j++) {
        size_t o = (size_t)(nb + ty + j * 8) * DD + d0 + tx;
        __nv_bfloat16 hh, ll; bf16split(t[tx][ty + j * 8], hh, ll);
        th[o] = hh; tl[o] = ll;
    }
}

__global__ void transpose_sq_kernel(const float* __restrict__ w0, const float* __restrict__ w1,
                                    const float* __restrict__ w2,
                                    __nv_bfloat16* __restrict__ t0h, __nv_bfloat16* __restrict__ t0l,
                                    __nv_bfloat16* __restrict__ t1h, __nv_bfloat16* __restrict__ t1l,
                                    __nv_bfloat16* __restrict__ t2h, __nv_bfloat16* __restrict__ t2l) {
    __shared__ float t[32][33];
    int z = blockIdx.z;
    const float* src = z == 0 ? w0 : (z == 1 ? w1 : w2);
    __nv_bfloat16* dh = z == 0 ? t0h : (z == 1 ? t1h : t2h);
    __nv_bfloat16* dl = z == 0 ? t0l : (z == 1 ? t1l : t2l);
    int r0 = blockIdx.x * 32, c0 = blockIdx.y * 32;
    int tx = threadIdx.x, ty = threadIdx.y;
    #pragma unroll
    for (int j = 0; j < 4; j++)
        t[ty + j * 8][tx] = src[(size_t)(r0 + ty + j * 8) * DD + c0 + tx];
    __syncthreads();
    #pragma unroll
    for (int j = 0; j < 4; j++) {
        size_t o = (size_t)(c0 + ty + j * 8) * DD + r0 + tx;
        __nv_bfloat16 hh, ll; bf16split(t[tx][ty + j * 8], hh, ll);
        dh[o] = hh; dl[o] = ll;
    }
}

// ---------------- fused mma.sync bf16x2 GEMM (2-stage, 1 barrier/chunk) ----------------
#define GLDA 40
#define GTILE (128 * GLDA * 2)   // 10240 B per tile
#define GSTG  (4 * GTILE)        // 40960 B per stage (Ah,Al,Bh,Bl)
#define GSM   (2 * GSTG)         // 81920

__device__ __forceinline__ void g_load4(uint32_t st,
    const __nv_bfloat16* __restrict__ Ah, const __nv_bfloat16* __restrict__ Al,
    const __nv_bfloat16* __restrict__ Bh, const __nv_bfloat16* __restrict__ Bl,
    int brow, int bcol, int k0, int K, int tid)
{
    #pragma unroll
    for (int it = 0; it < 2; it++) {
        int g = tid + it * 256;
        int r = g >> 2, gi = g & 3;
        uint32_t so = (uint32_t)(r * GLDA + gi * 8) * 2;
        size_t ao = (size_t)(brow + r) * K + k0 + gi * 8;
        size_t bo = (size_t)(bcol + r) * K + k0 + gi * 8;
        cpa16(st + so,             Ah + ao);
        cpa16(st + GTILE + so,     Al + ao);
        cpa16(st + 2 * GTILE + so, Bh + bo);
        cpa16(st + 3 * GTILE + so, Bl + bo);
    }
}

template <int ADD, int RELU, int SPLIT>
__global__ void __launch_bounds__(256, 2)
gemm_mma_kernel(const __nv_bfloat16* __restrict__ Ah, const __nv_bfloat16* __restrict__ Al,
                const __nv_bfloat16* __restrict__ Bh, const __nv_bfloat16* __restrict__ Bl,
                float* __restrict__ Cf, __nv_bfloat16* __restrict__ Ch,
                __nv_bfloat16* __restrict__ Cl, const float* __restrict__ R, int N, int K) {
    extern __shared__ char smg[];
    uint32_t sbase = smem_u32(smg);
    int tid = threadIdx.x, lane = tid & 31, wid = tid >> 5;
    int wm = (wid >> 2) * 64, wn = (wid & 3) * 32;
    int brow = blockIdx.y * 128, bcol = blockIdx.x * 128;
    int NC = K >> 5;

    float acc[4][4][4];
    #pragma unroll
    for (int i = 0; i < 4; i++)
        #pragma unroll
        for (int j = 0; j < 4; j++)
            #pragma unroll
            for (int e = 0; e < 4; e++) acc[i][j][e] = 0.f;

    g_load4(sbase, Ah, Al, Bh, Bl, brow, bcol, 0, K, tid); cpcommit();

    int aRow = lane & 15, aCol8 = (lane >> 4) * 8;
    // B x4 ldsm lane mapping: 16 n-rows x 16 k-cols -> two nt fragments
    int bnRow = (lane & 7) + ((lane >> 4) & 1) * 8;
    int bkCol = ((lane >> 3) & 1) * 8;

    for (int c = 0; c < NC; c++) {
        cpwait<0>();
        __syncthreads();
        if (c + 1 < NC) {
            g_load4(sbase + ((c + 1) & 1) * GSTG, Ah, Al, Bh, Bl,
                    brow, bcol, (c + 1) * 32, K, tid);
            cpcommit();
        }
        uint32_t sA = sbase + (c & 1) * GSTG;

        #pragma unroll
        for (int ks = 0; ks < 2; ks++) {
            uint32_t bh[4][2], bl[4][2];
            #pragma unroll
            for (int ntp = 0; ntp < 2; ntp++) {
                uint32_t off = (uint32_t)((wn + ntp * 16 + bnRow) * GLDA + ks * 16 + bkCol) * 2;
                ldsm_x4(&bh[ntp * 2][0], sA + 2 * GTILE + off);
                ldsm_x4(&bl[ntp * 2][0], sA + 3 * GTILE + off);
            }
            #pragma unroll
            for (int mt = 0; mt < 4; mt++) {
                uint32_t ah[4], al[4];
                uint32_t off = (uint32_t)((wm + mt * 16 + aRow) * GLDA + ks * 16 + aCol8) * 2;
                ldsm_x4(ah, sA + off);
                ldsm_x4(al, sA + GTILE + off);
                #pragma unroll
                for (int nt = 0; nt < 4; nt++) {
                    mma16816(acc[mt][nt], ah, bh[nt]);
                    mma16816(acc[mt][nt], ah, bl[nt]);
                    mma16816(acc[mt][nt], al, bh[nt]);
                }
            }
        }
    }

    int r0 = brow + wm + (lane >> 2);
    int c0 = bcol + wn + (lane & 3) * 2;
    #pragma unroll
    for (int mt = 0; mt < 4; mt++)
        #pragma unroll
        for (int half = 0; half < 2; half++) {
            int row = r0 + mt * 16 + half * 8;
            #pragma unroll
            for (int nt = 0; nt < 4; nt++) {
                float vx = acc[mt][nt][half * 2], vy = acc[mt][nt][half * 2 + 1];
                size_t o = (size_t)row * N + c0 + nt * 8;
                if (ADD) { vx += R[o]; vy += R[o + 1]; }
                if (RELU) { vx = fmaxf(vx, 0.f); vy = fmaxf(vy, 0.f); }
                if (SPLIT) {
                    *(uint32_t*)&Ch[o] = packsplit(vx, vy, 0);
                    *(uint32_t*)&Cl[o] = packsplit(vx, vy, 1);
                } else {
                    *(float2*)&Cf[o] = make_float2(vx, vy);
                }
            }
        }
}

// ---------------- flash attention on tensor cores (1 barrier/tile) ----------------
#define FST 72
#define F_QH 0
#define F_QL 9216
#define F_ST0 18432
#define F_STG 27648
#define F_SM (F_ST0 + 2 * F_STG)   // 73728

__device__ __forceinline__ void f_load_tile(uint32_t st,
    const __nv_bfloat16* __restrict__ qh, const __nv_bfloat16* __restrict__ ql,
    int b, int h, int krow, int tid)
{
    #pragma unroll
    for (int i = 0; i < 4; i++) {
        int g = tid + i * 128, r = g >> 3, gr = g & 7;
        size_t kro = (size_t)(b * SS + krow + r) * LD3 + DD + h * DHH + gr * 8;
        uint32_t dst = (uint32_t)(r * FST + gr * 8) * 2;
        cpa16(st + dst,         qh + kro);
        cpa16(st + 9216 + dst,  ql + kro);
        cpa16(st + 18432 + dst, qh + kro + DD);
    }
}

__global__ void __launch_bounds__(128, 3)
flash_mma_kernel(const __nv_bfloat16* __restrict__ qh, const __nv_bfloat16* __restrict__ ql,
                 __nv_bfloat16* __restrict__ ch, __nv_bfloat16* __restrict__ cl) {
    extern __shared__ char smf[];
    uint32_t sb = smem_u32(smf);
    int tid = threadIdx.x, lane = tid & 31, w = tid >> 5;
    int b = blockIdx.z, h = blockIdx.y, q0 = blockIdx.x * 64;

    #pragma unroll
    for (int i = 0; i < 4; i++) {
        int g = tid + i * 128, r = g >> 3, gr = g & 7;
        size_t src = (size_t)(b * SS + q0 + r) * LD3 + h * DHH + gr * 8;
        uint32_t dst = (uint32_t)(r * FST + gr * 8) * 2;
        cpa16(sb + F_QH + dst, qh + src);
        cpa16(sb + F_QL + dst, ql + src);
    }
    cpcommit();
    // first K/V tile
    f_load_tile(sb + F_ST0, qh, ql, b, h, 0, tid);
    cpcommit();

    cpwait<1>();   // Q done
    __syncthreads();
    int lr = lane & 15, hc = (lane >> 4) * 8;
    uint32_t Qh[4][4], Ql[4][4];
    #pragma unroll
    for (int kk = 0; kk < 4; kk++) {
        uint32_t off = (uint32_t)((16 * w + lr) * FST + kk * 16 + hc) * 2;
        ldsm_x4(Qh[kk], sb + F_QH + off);
        ldsm_x4(Ql[kk], sb + F_QL + off);
    }

    float m0 = -1e30f, m1 = -1e30f, l0 = 0.f, l1 = 0.f;
    float ao[8][4];
    #pragma unroll
    for (int n = 0; n < 8; n++)
        #pragma unroll
        for (int e = 0; e < 4; e++) ao[n][e] = 0.f;

    for (int kb = 0; kb < SS; kb += 64) {
        int t = kb >> 6;
        cpwait<0>();
        __syncthreads();
        if (kb + 64 < SS) {
            f_load_tile(sb + F_ST0 + ((t + 1) & 1) * F_STG, qh, ql, b, h, kb + 64, tid);
            cpcommit();
        }
        uint32_t st = sb + F_ST0 + (t & 1) * F_STG;

        float s_[8][4];
        #pragma unroll
        for (int n = 0; n < 8; n++)
            #pragma unroll
            for (int e = 0; e < 4; e++) s_[n][e] = 0.f;
        #pragma unroll
        for (int kk = 0; kk < 4; kk++) {
            #pragma unroll
            for (int nt = 0; nt < 8; nt++) {
                uint32_t off = (uint32_t)((nt * 8 + (lane & 7)) * FST + kk * 16
                                          + ((lane >> 3) & 1) * 8) * 2;
                uint32_t bh[2], bl[2];
                ldsm_x2(bh, st + off);
                ldsm_x2(bl, st + 9216 + off);
                mma16816(s_[nt], Qh[kk], bh);
                mma16816(s_[nt], Ql[kk], bh);
                mma16816(s_[nt], Qh[kk], bl);
            }
        }

        float tm0 = -1e30f, tm1 = -1e30f;
        #pragma unroll
        for (int n = 0; n < 8; n++) {
            #pragma unroll
            for (int e = 0; e < 4; e++) s_[n][e] *= 0.125f;
            tm0 = fmaxf(tm0, fmaxf(s_[n][0], s_[n][1]));
            tm1 = fmaxf(tm1, fmaxf(s_[n][2], s_[n][3]));
        }
        tm0 = fmaxf(tm0, __shfl_xor_sync(0xffffffffu, tm0, 1));
        tm0 = fmaxf(tm0, __shfl_xor_sync(0xffffffffu, tm0, 2));
        tm1 = fmaxf(tm1, __shfl_xor_sync(0xffffffffu, tm1, 1));
        tm1 = fmaxf(tm1, __shfl_xor_sync(0xffffffffu, tm1, 2));
        float mn0 = fmaxf(m0, tm0), mn1 = fmaxf(m1, tm1);
        float sc0 = __expf(m0 - mn0), sc1 = __expf(m1 - mn1);
        m0 = mn0; m1 = mn1;
        float ls0 = 0.f, ls1 = 0.f;
        #pragma unroll
        for (int n = 0; n < 8; n++) {
            s_[n][0] = __expf(s_[n][0] - mn0);
            s_[n][1] = __expf(s_[n][1] - mn0);
            s_[n][2] = __expf(s_[n][2] - mn1);
            s_[n][3] = __expf(s_[n][3] - mn1);
            ls0 += s_[n][0] + s_[n][1];
            ls1 += s_[n][2] + s_[n][3];
        }
        ls0 += __shfl_xor_sync(0xffffffffu, ls0, 1);
        ls0 += __shfl_xor_sync(0xffffffffu, ls0, 2);
        ls1 += __shfl_xor_sync(0xffffffffu, ls1, 1);
        ls1 += __shfl_xor_sync(0xffffffffu, ls1, 2);
        l0 = l0 * sc0 + ls0;
        l1 = l1 * sc1 + ls1;
        #pragma unroll
        for (int n = 0; n < 8; n++) {
            ao[n][0] *= sc0; ao[n][1] *= sc0;
            ao[n][2] *= sc1; ao[n][3] *= sc1;
        }

        #pragma unroll
        for (int k2 = 0; k2 < 4; k2++) {
            uint32_t pa[4];
            pa[0] = packbf(s_[2 * k2][0],     s_[2 * k2][1]);
            pa[1] = packbf(s_[2 * k2][2],     s_[2 * k2][3]);
            pa[2] = packbf(s_[2 * k2 + 1][0], s_[2 * k2 + 1][1]);
            pa[3] = packbf(s_[2 * k2 + 1][2], s_[2 * k2 + 1][3]);
            #pragma unroll
            for (int nt = 0; nt < 8; nt++) {
                uint32_t bv[2];
                ldsm_x2t(bv, st + 18432
                         + (uint32_t)((k2 * 16 + (lane & 15)) * FST + nt * 8) * 2);
                mma16816(ao[nt], pa, bv);
            }
        }
    }

    float i0 = 1.0f / l0, i1 = 1.0f / l1;
    int row0 = b * SS + q0 + 16 * w + (lane >> 2);
    int cb = h * DHH + (lane & 3) * 2;
    #pragma unroll
    for (int nt = 0; nt < 8; nt++) {
        size_t o0 = (size_t)row0 * DD + cb + nt * 8;
        size_t o1 = (size_t)(row0 + 8) * DD + cb + nt * 8;
        float v0 = ao[nt][0] * i0, v1 = ao[nt][1] * i0;
        float v2 = ao[nt][2] * i1, v3 = ao[nt][3] * i1;
        *(uint32_t*)&ch[o0] = packsplit(v0, v1, 0);
        *(uint32_t*)&cl[o0] = packsplit(v0, v1, 1);
        *(uint32_t*)&ch[o1] = packsplit(v2, v3, 0);
        *(uint32_t*)&cl[o1] = packsplit(v2, v3, 1);
    }
}

// ---------------- launch ----------------
#define SYM(p, s) cudaGetSymbolAddress((void**)&p, s)

extern "C" void kernel_launch(void* const* d_in, const int* in_sizes, int n_in,
                              void* d_out, int out_size) {
    const float* x     = (const float*)d_in[0];
    const float* wq    = (const float*)d_in[1];
    const float* wk    = (const float*)d_in[2];
    const float* wv    = (const float*)d_in[3];
    const float* wo    = (const float*)d_in[4];
    const float* w1    = (const float*)d_in[5];
    const float* w2    = (const float*)d_in[6];
    const float* ln1_g = (const float*)d_in[7];
    const float* ln1_b = (const float*)d_in[8];
    const float* ln2_g = (const float*)d_in[9];
    const float* ln2_b = (const float*)d_in[10];
    const float* ln3_g = (const float*)d_in[11];
    const float* ln3_b = (const float*)d_in[12];
    float* out = (float*)d_out;

    float *p_attn, *p_ln2f, *p_res2;
    __nv_bfloat16 *p_ln1h, *p_ln1l, *p_ln2h, *p_ln2l, *p_ctxh, *p_ctxl, *p_f1h, *p_f1l;
    __nv_bfloat16 *p_qkvh, *p_qkvl;
    __nv_bfloat16 *p_wqh, *p_wql, *p_woh, *p_wol, *p_w1h, *p_w1l, *p_w2h, *p_w2l;
    SYM(p_attn, g_attn); SYM(p_ln2f, g_ln2f); SYM(p_res2, g_res2);
    SYM(p_ln1h, g_ln1h); SYM(p_ln1l, g_ln1l); SYM(p_ln2h, g_ln2h); SYM(p_ln2l, g_ln2l);
    SYM(p_ctxh, g_ctxh); SYM(p_ctxl, g_ctxl); SYM(p_f1h, g_f1h); SYM(p_f1l, g_f1l);
    SYM(p_qkvh, g_qkvh); SYM(p_qkvl, g_qkvl);
    SYM(p_wqh, g_wqh); SYM(p_wql, g_wql); SYM(p_woh, g_woh); SYM(p_wol, g_wol);
    SYM(p_w1h, g_w1h); SYM(p_w1l, g_w1l); SYM(p_w2h, g_w2h); SYM(p_w2l, g_w2l);

    cudaFuncSetAttribute(gemm_mma_kernel<0,0,1>, cudaFuncAttributeMaxDynamicSharedMemorySize, GSM);
    cudaFuncSetAttribute(gemm_mma_kernel<1,0,0>, cudaFuncAttributeMaxDynamicSharedMemorySize, GSM);
    cudaFuncSetAttribute(gemm_mma_kernel<0,1,1>, cudaFuncAttributeMaxDynamicSharedMemorySize, GSM);
    cudaFuncSetAttribute(flash_mma_kernel, cudaFuncAttributeMaxDynamicSharedMemorySize, F_SM);

    transpose_qkv_kernel<<<dim3(DD / 32, DHH / 32, 48), dim3(32, 8)>>>(wq, wk, wv, p_wqh, p_wql);
    transpose_sq_kernel<<<dim3(32, 32, 3), dim3(32, 8)>>>(wo, w1, w2,
        p_woh, p_wol, p_w1h, p_w1l, p_w2h, p_w2l);

    layernorm_kernel<<<MM, 256>>>(x, ln1_g, ln1_b, nullptr, p_ln1h, p_ln1l);
    gemm_mma_kernel<0,0,1><<<dim3(LD3 / 128, MM / 128), 256, GSM>>>(
        p_ln1h, p_ln1l, p_wqh, p_wql, nullptr, p_qkvh, p_qkvl, nullptr, LD3, DD);
    flash_mma_kernel<<<dim3(SS / 64, HH, BB), 128, F_SM>>>(p_qkvh, p_qkvl, p_ctxh, p_ctxl);
    gemm_mma_kernel<1,0,0><<<dim3(DD / 128, MM / 128), 256, GSM>>>(
        p_ctxh, p_ctxl, p_woh, p_wol, p_attn, nullptr, nullptr, x, DD, DD);
    layernorm_kernel<<<MM, 256>>>(p_attn, ln2_g, ln2_b, p_ln2f, p_ln2h, p_ln2l);
    gemm_mma_kernel<0,1,1><<<dim3(DD / 128, MM / 128), 256, GSM>>>(
        p_ln2h, p_ln2l, p_w1h, p_w1l, nullptr, p_f1h, p_f1l, nullptr, DD, DD);
    gemm_mma_kernel<1,0,0><<<dim3(DD / 128, MM / 128), 256, GSM>>>(
        p_f1h, p_f1l, p_w2h, p_w2l, p_res2, nullptr, nullptr, p_ln2f, DD, DD);
    layernorm_kernel<<<MM, 256>>>(p_res2, ln3_g, ln3_b, out, nullptr, nullptr);
}

// round 8
// speedup vs baseline: 3.7515x; 1.0079x over previous
#include <cuda_runtime.h>
#include <cuda_bf16.h>
#include <math.h>
#include <stdint.h>

#define BB 2
#define SS 2048
#define DD 1024
#define HH 16
#define DHH 64
#define MM (BB * SS)
#define LD3 (3 * DD)

// ---------------- scratch ----------------
__device__ float g_attn[MM * DD];
__device__ float g_ln2f[MM * DD];
__device__ float g_res2[MM * DD];

__device__ __nv_bfloat16 g_ln1h[MM * DD], g_ln1l[MM * DD];
__device__ __nv_bfloat16 g_ln2h[MM * DD], g_ln2l[MM * DD];
__device__ __nv_bfloat16 g_ctxh[MM * DD], g_ctxl[MM * DD];
__device__ __nv_bfloat16 g_f1h [MM * DD], g_f1l [MM * DD];
__device__ __nv_bfloat16 g_qkvh[MM * LD3], g_qkvl[MM * LD3];
__device__ __nv_bfloat16 g_wqh[LD3 * DD], g_wql[LD3 * DD];
__device__ __nv_bfloat16 g_woh[DD * DD],  g_wol[DD * DD];
__device__ __nv_bfloat16 g_w1h[DD * DD],  g_w1l[DD * DD];
__device__ __nv_bfloat16 g_w2h[DD * DD],  g_w2l[DD * DD];

// ---------------- helpers ----------------
__device__ __forceinline__ uint32_t smem_u32(const void* p) {
    uint32_t a;
    asm("{ .reg .u64 t; cvta.to.shared.u64 t, %1; cvt.u32.u64 %0, t; }" : "=r"(a) : "l"(p));
    return a;
}
__device__ __forceinline__ void cpa16(uint32_t dst, const void* src) {
    asm volatile("cp.async.cg.shared.global [%0], [%1], 16;" :: "r"(dst), "l"(src) : "memory");
}
__device__ __forceinline__ void cpcommit() { asm volatile("cp.async.commit_group;" ::: "memory"); }
template <int N> __device__ __forceinline__ void cpwait() {
    asm volatile("cp.async.wait_group %0;" :: "n"(N) : "memory");
}
__device__ __forceinline__ void ldsm_x4(uint32_t* r, uint32_t a) {
    asm volatile("ldmatrix.sync.aligned.m8n8.x4.shared.b16 {%0,%1,%2,%3}, [%4];"
        : "=r"(r[0]), "=r"(r[1]), "=r"(r[2]), "=r"(r[3]) : "r"(a));
}
__device__ __forceinline__ void ldsm_x4t(uint32_t* r, uint32_t a) {
    asm volatile("ldmatrix.sync.aligned.m8n8.x4.trans.shared.b16 {%0,%1,%2,%3}, [%4];"
        : "=r"(r[0]), "=r"(r[1]), "=r"(r[2]), "=r"(r[3]) : "r"(a));
}
__device__ __forceinline__ void mma16816(float* d, const uint32_t* a, const uint32_t* b) {
    asm volatile("mma.sync.aligned.m16n8k16.row.col.f32.bf16.bf16.f32 "
        "{%0,%1,%2,%3},{%4,%5,%6,%7},{%8,%9},{%0,%1,%2,%3};"
        : "+f"(d[0]), "+f"(d[1]), "+f"(d[2]), "+f"(d[3])
        : "r"(a[0]), "r"(a[1]), "r"(a[2]), "r"(a[3]), "r"(b[0]), "r"(b[1]));
}
__device__ __forceinline__ void bf16split(float v, __nv_bfloat16& h, __nv_bfloat16& l) {
    h = __float2bfloat16_rn(v);
    l = __float2bfloat16_rn(v - __bfloat162float(h));
}
__device__ __forceinline__ uint32_t packbf(float a, float b) {
    __nv_bfloat162 t = __float22bfloat162_rn(make_float2(a, b));
    return *(uint32_t*)&t;
}
__device__ __forceinline__ uint32_t packsplit(float a, float b, int lo) {
    __nv_bfloat16 ha, la, hb, lb;
    bf16split(a, ha, la); bf16split(b, hb, lb);
    __nv_bfloat162 t;
    if (lo) { t.x = la; t.y = lb; } else { t.x = ha; t.y = hb; }
    return *(uint32_t*)&t;
}

// ---------------- layernorm ----------------
__device__ __forceinline__ float block_sum_256(float v, float* red) {
    #pragma unroll
    for (int o = 16; o; o >>= 1) v += __shfl_xor_sync(0xffffffffu, v, o);
    int w = threadIdx.x >> 5;
    if ((threadIdx.x & 31) == 0) red[w] = v;
    __syncthreads();
    if (threadIdx.x < 8) {
        v = red[threadIdx.x];
        #pragma unroll
        for (int o = 4; o; o >>= 1) v += __shfl_xor_sync(0xffu, v, o);
        if (threadIdx.x == 0) red[0] = v;
    }
    __syncthreads();
    float r = red[0];
    __syncthreads();
    return r;
}

__global__ void layernorm_kernel(const float* __restrict__ x,
                                 const float* __restrict__ g,
                                 const float* __restrict__ b,
                                 float* __restrict__ outf,
                                 __nv_bfloat16* __restrict__ outh,
                                 __nv_bfloat16* __restrict__ outl) {
    __shared__ float red[32];
    int row = blockIdx.x;
    const float* xr = x + (size_t)row * DD;
    float v[4], s = 0.f;
    #pragma unroll
    for (int i = 0; i < 4; i++) { v[i] = xr[threadIdx.x + i * 256]; s += v[i]; }
    float mean = block_sum_256(s, red) * (1.0f / DD);
    float sq = 0.f;
    #pragma unroll
    for (int i = 0; i < 4; i++) { float d = v[i] - mean; sq += d * d; }
    float inv = rsqrtf(block_sum_256(sq, red) * (1.0f / DD) + 1e-5f);
    #pragma unroll
    for (int i = 0; i < 4; i++) {
        int c = threadIdx.x + i * 256;
        float y = (v[i] - mean) * inv * g[c] + b[c];
        size_t o = (size_t)row * DD + c;
        if (outf) outf[o] = y;
        if (outh) { __nv_bfloat16 h, l; bf16split(y, h, l); outh[o] = h; outl[o] = l; }
    }
}

// ---------------- weight transposes -> [N,K] bf16 hi/lo ----------------
__global__ void transpose_qkv_kernel(const float* __restrict__ wq, const float* __restrict__ wk,
                                     const float* __restrict__ wv,
                                     __nv_bfloat16* __restrict__ th, __nv_bfloat16* __restrict__ tl) {
    __shared__ float t[32][33];
    int sel = blockIdx.z >> 4, h = blockIdx.z & 15;
    const float* src = (sel == 0 ? wq : (sel == 1 ? wk : wv)) + (size_t)h * DD * DHH;
    int d0 = blockIdx.x * 32, dh0 = blockIdx.y * 32;
    int tx = threadIdx.x, ty = threadIdx.y;
    #pragma unroll
    for (int j = 0; j < 4; j++)
        t[ty + j * 8][tx] = src[(size_t)(d0 + ty + j * 8) * DHH + dh0 + tx];
    __syncthreads();
    int nb = sel * DD + h * DHH + dh0;
    #pragma unroll
    for (int j = 0; j < 4; j++) {
        size_t o = (size_t)(nb + ty + j * 8) * DD + d0 + tx;
        __nv_bfloat16 hh, ll; bf16split(t[tx][ty + j * 8], hh, ll);
        th[o] = hh; tl[o] = ll;
    }
}

__global__ void transpose_sq_kernel(const float* __restrict__ w0, const float* __restrict__ w1,
                                    const float* __restrict__ w2,
                                    __nv_bfloat16* __restrict__ t0h, __nv_bfloat16* __restrict__ t0l,
                                    __nv_bfloat16* __restrict__ t1h, __nv_bfloat16* __restrict__ t1l,
                                    __nv_bfloat16* __restrict__ t2h, __nv_bfloat16* __restrict__ t2l) {
    __shared__ float t[32][33];
    int z = blockIdx.z;
    const float* src = z == 0 ? w0 : (z == 1 ? w1 : w2);
    __nv_bfloat16* dh = z == 0 ? t0h : (z == 1 ? t1h : t2h);
    __nv_bfloat16* dl = z == 0 ? t0l : (z == 1 ? t1l : t2l);
    int r0 = blockIdx.x * 32, c0 = blockIdx.y * 32;
    int tx = threadIdx.x, ty = threadIdx.y;
    #pragma unroll
    for (int j = 0; j < 4; j++)
        t[ty + j * 8][tx] = src[(size_t)(r0 + ty + j * 8) * DD + c0 + tx];
    __syncthreads();
    #pragma unroll
    for (int j = 0; j < 4; j++) {
        size_t o = (size_t)(c0 + ty + j * 8) * DD + r0 + tx;
        __nv_bfloat16 hh, ll; bf16split(t[tx][ty + j * 8], hh, ll);
        dh[o] = hh; dl[o] = ll;
    }
}

// ---------------- fused mma.sync bf16x2 GEMM ----------------
// 128 threads, tile 64(M)x128(N), BK=32, warp tile 64x32, occ 3, term-major MMA.
#define GLDA 40
#define ATILE (64 * GLDA * 2)    // 5120
#define BTILE (128 * GLDA * 2)   // 10240
#define GSTG  (2 * ATILE + 2 * BTILE)  // 30720
#define GSM   (2 * GSTG)               // 61440

__device__ __forceinline__ void g_load(uint32_t st,
    const __nv_bfloat16* __restrict__ Ah, const __nv_bfloat16* __restrict__ Al,
    const __nv_bfloat16* __restrict__ Bh, const __nv_bfloat16* __restrict__ Bl,
    int brow, int bcol, int k0, int K, int tid)
{
    #pragma unroll
    for (int it = 0; it < 2; it++) {
        int g = tid + it * 128;
        int r = g >> 2, gi = g & 3;
        uint32_t so = (uint32_t)(r * GLDA + gi * 8) * 2;
        size_t ao = (size_t)(brow + r) * K + k0 + gi * 8;
        cpa16(st + so,         Ah + ao);
        cpa16(st + ATILE + so, Al + ao);
    }
    #pragma unroll
    for (int it = 0; it < 4; it++) {
        int g = tid + it * 128;
        int r = g >> 2, gi = g & 3;
        uint32_t so = (uint32_t)(r * GLDA + gi * 8) * 2;
        size_t bo = (size_t)(bcol + r) * K + k0 + gi * 8;
        cpa16(st + 2 * ATILE + so,         Bh + bo);
        cpa16(st + 2 * ATILE + BTILE + so, Bl + bo);
    }
}

template <int ADD, int RELU, int SPLIT>
__global__ void __launch_bounds__(128, 3)
gemm_mma_kernel(const __nv_bfloat16* __restrict__ Ah, const __nv_bfloat16* __restrict__ Al,
                const __nv_bfloat16* __restrict__ Bh, const __nv_bfloat16* __restrict__ Bl,
                float* __restrict__ Cf, __nv_bfloat16* __restrict__ Ch,
                __nv_bfloat16* __restrict__ Cl, const float* __restrict__ R, int N, int K) {
    extern __shared__ char smg[];
    uint32_t sbase = smem_u32(smg);
    int tid = threadIdx.x, lane = tid & 31, wid = tid >> 5;
    int wn = wid * 32;
    int brow = blockIdx.y * 64, bcol = blockIdx.x * 128;
    int NC = K >> 5;

    float acc[4][4][4];
    #pragma unroll
    for (int i = 0; i < 4; i++)
        #pragma unroll
        for (int j = 0; j < 4; j++)
            #pragma unroll
            for (int e = 0; e < 4; e++) acc[i][j][e] = 0.f;

    g_load(sbase, Ah, Al, Bh, Bl, brow, bcol, 0, K, tid); cpcommit();

    int aRow = lane & 15, aCol8 = (lane >> 4) * 8;
    int bnRow = (lane & 7) + ((lane >> 4) & 1) * 8;
    int bkCol = ((lane >> 3) & 1) * 8;

    for (int c = 0; c < NC; c++) {
        cpwait<0>();
        __syncthreads();
        if (c + 1 < NC) {
            g_load(sbase + ((c + 1) & 1) * GSTG, Ah, Al, Bh, Bl,
                   brow, bcol, (c + 1) * 32, K, tid);
            cpcommit();
        }
        uint32_t sA = sbase + (c & 1) * GSTG;

        #pragma unroll
        for (int ks = 0; ks < 2; ks++) {
            uint32_t ah[4][4], al[4][4], bh[4][2], bl[4][2];
            #pragma unroll
            for (int mt = 0; mt < 4; mt++) {
                uint32_t off = (uint32_t)((mt * 16 + aRow) * GLDA + ks * 16 + aCol8) * 2;
                ldsm_x4(ah[mt], sA + off);
                ldsm_x4(al[mt], sA + ATILE + off);
            }
            #pragma unroll
            for (int ntp = 0; ntp < 2; ntp++) {
                uint32_t off = (uint32_t)((wn + ntp * 16 + bnRow) * GLDA + ks * 16 + bkCol) * 2;
                ldsm_x4(&bh[ntp * 2][0], sA + 2 * ATILE + off);
                ldsm_x4(&bl[ntp * 2][0], sA + 2 * ATILE + BTILE + off);
            }
            // term-major: RAW chain distance 16
            #pragma unroll
            for (int mt = 0; mt < 4; mt++)
                #pragma unroll
                for (int nt = 0; nt < 4; nt++)
                    mma16816(acc[mt][nt], ah[mt], bh[nt]);
            #pragma unroll
            for (int mt = 0; mt < 4; mt++)
                #pragma unroll
                for (int nt = 0; nt < 4; nt++)
                    mma16816(acc[mt][nt], ah[mt], bl[nt]);
            #pragma unroll
            for (int mt = 0; mt < 4; mt++)
                #pragma unroll
                for (int nt = 0; nt < 4; nt++)
                    mma16816(acc[mt][nt], al[mt], bh[nt]);
        }
    }

    int r0 = brow + (lane >> 2);
    int c0 = bcol + wn + (lane & 3) * 2;
    #pragma unroll
    for (int mt = 0; mt < 4; mt++)
        #pragma unroll
        for (int half = 0; half < 2; half++) {
            int row = r0 + mt * 16 + half * 8;
            #pragma unroll
            for (int nt = 0; nt < 4; nt++) {
                float vx = acc[mt][nt][half * 2], vy = acc[mt][nt][half * 2 + 1];
                size_t o = (size_t)row * N + c0 + nt * 8;
                if (ADD) { vx += R[o]; vy += R[o + 1]; }
                if (RELU) { vx = fmaxf(vx, 0.f); vy = fmaxf(vy, 0.f); }
                if (SPLIT) {
                    *(uint32_t*)&Ch[o] = packsplit(vx, vy, 0);
                    *(uint32_t*)&Cl[o] = packsplit(vx, vy, 1);
                } else {
                    *(float2*)&Cf[o] = make_float2(vx, vy);
                }
            }
        }
}

// ---------------- flash attention on tensor cores ----------------
#define FST 72
#define F_QH 0
#define F_QL 9216
#define F_ST0 18432
#define F_STG 27648
#define F_SM (F_ST0 + 2 * F_STG)   // 73728

__device__ __forceinline__ void f_load_tile(uint32_t st,
    const __nv_bfloat16* __restrict__ qh, const __nv_bfloat16* __restrict__ ql,
    int b, int h, int krow, int tid)
{
    #pragma unroll
    for (int i = 0; i < 4; i++) {
        int g = tid + i * 128, r = g >> 3, gr = g & 7;
        size_t kro = (size_t)(b * SS + krow + r) * LD3 + DD + h * DHH + gr * 8;
        uint32_t dst = (uint32_t)(r * FST + gr * 8) * 2;
        cpa16(st + dst,         qh + kro);
        cpa16(st + 9216 + dst,  ql + kro);
        cpa16(st + 18432 + dst, qh + kro + DD);
    }
}

__global__ void __launch_bounds__(128, 3)
flash_mma_kernel(const __nv_bfloat16* __restrict__ qh, const __nv_bfloat16* __restrict__ ql,
                 __nv_bfloat16* __restrict__ ch, __nv_bfloat16* __restrict__ cl) {
    extern __shared__ char smf[];
    uint32_t sb = smem_u32(smf);
    int tid = threadIdx.x, lane = tid & 31, w = tid >> 5;
    int b = blockIdx.z, h = blockIdx.y, q0 = blockIdx.x * 64;

    #pragma unroll
    for (int i = 0; i < 4; i++) {
        int g = tid + i * 128, r = g >> 3, gr = g & 7;
        size_t src = (size_t)(b * SS + q0 + r) * LD3 + h * DHH + gr * 8;
        uint32_t dst = (uint32_t)(r * FST + gr * 8) * 2;
        cpa16(sb + F_QH + dst, qh + src);
        cpa16(sb + F_QL + dst, ql + src);
    }
    cpcommit();
    f_load_tile(sb + F_ST0, qh, ql, b, h, 0, tid);
    cpcommit();

    cpwait<1>();
    __syncthreads();
    int lr = lane & 15, hc = (lane >> 4) * 8;
    uint32_t Qh[4][4], Ql[4][4];
    #pragma unroll
    for (int kk = 0; kk < 4; kk++) {
        uint32_t off = (uint32_t)((16 * w + lr) * FST + kk * 16 + hc) * 2;
        ldsm_x4(Qh[kk], sb + F_QH + off);
        ldsm_x4(Ql[kk], sb + F_QL + off);
    }

    int bnRow = (lane & 7) + ((lane >> 4) & 1) * 8;
    int bkCol = ((lane >> 3) & 1) * 8;
    int vRow = (lane & 7) + ((lane >> 3) & 1) * 8;
    int vCol = (lane >> 4) * 8;

    float m0 = -1e30f, m1 = -1e30f, l0 = 0.f, l1 = 0.f;
    float ao[8][4];
    #pragma unroll
    for (int n = 0; n < 8; n++)
        #pragma unroll
        for (int e = 0; e < 4; e++) ao[n][e] = 0.f;

    for (int kb = 0; kb < SS; kb += 64) {
        int t = kb >> 6;
        cpwait<0>();
        __syncthreads();
        if (kb + 64 < SS) {
            f_load_tile(sb + F_ST0 + ((t + 1) & 1) * F_STG, qh, ql, b, h, kb + 64, tid);
            cpcommit();
        }
        uint32_t st = sb + F_ST0 + (t & 1) * F_STG;

        float s_[8][4];
        #pragma unroll
        for (int n = 0; n < 8; n++)
            #pragma unroll
            for (int e = 0; e < 4; e++) s_[n][e] = 0.f;
        #pragma unroll
        for (int kk = 0; kk < 4; kk++) {
            uint32_t bh[8][2], bl[8][2];
            #pragma unroll
            for (int ntp = 0; ntp < 4; ntp++) {
                uint32_t off = (uint32_t)((ntp * 16 + bnRow) * FST + kk * 16 + bkCol) * 2;
                ldsm_x4(&bh[ntp * 2][0], st + off);
                ldsm_x4(&bl[ntp * 2][0], st + 9216 + off);
            }
            #pragma unroll
            for (int nt = 0; nt < 8; nt++) mma16816(s_[nt], Qh[kk], bh[nt]);
            #pragma unroll
            for (int nt = 0; nt < 8; nt++) mma16816(s_[nt], Ql[kk], bh[nt]);
            #pragma unroll
            for (int nt = 0; nt < 8; nt++) mma16816(s_[nt], Qh[kk], bl[nt]);
        }

        float tm0 = -1e30f, tm1 = -1e30f;
        #pragma unroll
        for (int n = 0; n < 8; n++) {
            #pragma unroll
            for (int e = 0; e < 4; e++) s_[n][e] *= 0.125f;
            tm0 = fmaxf(tm0, fmaxf(s_[n][0], s_[n][1]));
            tm1 = fmaxf(tm1, fmaxf(s_[n][2], s_[n][3]));
        }
        tm0 = fmaxf(tm0, __shfl_xor_sync(0xffffffffu, tm0, 1));
        tm0 = fmaxf(tm0, __shfl_xor_sync(0xffffffffu, tm0, 2));
        tm1 = fmaxf(tm1, __shfl_xor_sync(0xffffffffu, tm1, 1));
        tm1 = fmaxf(tm1, __shfl_xor_sync(0xffffffffu, tm1, 2));
        float mn0 = fmaxf(m0, tm0), mn1 = fmaxf(m1, tm1);
        float sc0 = __expf(m0 - mn0), sc1 = __expf(m1 - mn1);
        m0 = mn0; m1 = mn1;
        float ls0 = 0.f, ls1 = 0.f;
        #pragma unroll
        for (int n = 0; n < 8; n++) {
            s_[n][0] = __expf(s_[n][0] - mn0);
            s_[n][1] = __expf(s_[n][1] - mn0);
            s_[n][2] = __expf(s_[n][2] - mn1);
            s_[n][3] = __expf(s_[n][3] - mn1);
            ls0 += s_[n][0] + s_[n][1];
            ls1 += s_[n][2] + s_[n][3];
        }
        ls0 += __shfl_xor_sync(0xffffffffu, ls0, 1);
        ls0 += __shfl_xor_sync(0xffffffffu, ls0, 2);
        ls1 += __shfl_xor_sync(0xffffffffu, ls1, 1);
        ls1 += __shfl_xor_sync(0xffffffffu, ls1, 2);
        l0 = l0 * sc0 + ls0;
        l1 = l1 * sc1 + ls1;
        #pragma unroll
        for (int n = 0; n < 8; n++) {
            ao[n][0] *= sc0; ao[n][1] *= sc0;
            ao[n][2] *= sc1; ao[n][3] *= sc1;
        }

        #pragma unroll
        for (int k2 = 0; k2 < 4; k2++) {
            uint32_t pa[4];
            pa[0] = packbf(s_[2 * k2][0],     s_[2 * k2][1]);
            pa[1] = packbf(s_[2 * k2][2],     s_[2 * k2][3]);
            pa[2] = packbf(s_[2 * k2 + 1][0], s_[2 * k2 + 1][1]);
            pa[3] = packbf(s_[2 * k2 + 1][2], s_[2 * k2 + 1][3]);
            #pragma unroll
            for (int ntp = 0; ntp < 4; ntp++) {
                uint32_t bv[4];
                ldsm_x4t(bv, st + 18432
                         + (uint32_t)((k2 * 16 + vRow) * FST + ntp * 16 + vCol) * 2);
                mma16816(ao[ntp * 2],     pa, &bv[0]);
                mma16816(ao[ntp * 2 + 1], pa, &bv[2]);
            }
        }
    }

    float i0 = 1.0f / l0, i1 = 1.0f / l1;
    int row0 = b * SS + q0 + 16 * w + (lane >> 2);
    int cb = h * DHH + (lane & 3) * 2;
    #pragma unroll
    for (int nt = 0; nt < 8; nt++) {
        size_t o0 = (size_t)row0 * DD + cb + nt * 8;
        size_t o1 = (size_t)(row0 + 8) * DD + cb + nt * 8;
        float v0 = ao[nt][0] * i0, v1 = ao[nt][1] * i0;
        float v2 = ao[nt][2] * i1, v3 = ao[nt][3] * i1;
        *(uint32_t*)&ch[o0] = packsplit(v0, v1, 0);
        *(uint32_t*)&cl[o0] = packsplit(v0, v1, 1);
        *(uint32_t*)&ch[o1] = packsplit(v2, v3, 0);
        *(uint32_t*)&cl[o1] = packsplit(v2, v3, 1);
    }
}

// ---------------- launch ----------------
#define SYM(p, s) cudaGetSymbolAddress((void**)&p, s)

extern "C" void kernel_launch(void* const* d_in, const int* in_sizes, int n_in,
                              void* d_out, int out_size) {
    const float* x     = (const float*)d_in[0];
    const float* wq    = (const float*)d_in[1];
    const float* wk    = (const float*)d_in[2];
    const float* wv    = (const float*)d_in[3];
    const float* wo    = (const float*)d_in[4];
    const float* w1    = (const float*)d_in[5];
    const float* w2    = (const float*)d_in[6];
    const float* ln1_g = (const float*)d_in[7];
    const float* ln1_b = (const float*)d_in[8];
    const float* ln2_g = (const float*)d_in[9];
    const float* ln2_b = (const float*)d_in[10];
    const float* ln3_g = (const float*)d_in[11];
    const float* ln3_b = (const float*)d_in[12];
    float* out = (float*)d_out;

    float *p_attn, *p_ln2f, *p_res2;
    __nv_bfloat16 *p_ln1h, *p_ln1l, *p_ln2h, *p_ln2l, *p_ctxh, *p_ctxl, *p_f1h, *p_f1l;
    __nv_bfloat16 *p_qkvh, *p_qkvl;
    __nv_bfloat16 *p_wqh, *p_wql, *p_woh, *p_wol, *p_w1h, *p_w1l, *p_w2h, *p_w2l;
    SYM(p_attn, g_attn); SYM(p_ln2f, g_ln2f); SYM(p_res2, g_res2);
    SYM(p_ln1h, g_ln1h); SYM(p_ln1l, g_ln1l); SYM(p_ln2h, g_ln2h); SYM(p_ln2l, g_ln2l);
    SYM(p_ctxh, g_ctxh); SYM(p_ctxl, g_ctxl); SYM(p_f1h, g_f1h); SYM(p_f1l, g_f1l);
    SYM(p_qkvh, g_qkvh); SYM(p_qkvl, g_qkvl);
    SYM(p_wqh, g_wqh); SYM(p_wql, g_wql); SYM(p_woh, g_woh); SYM(p_wol, g_wol);
    SYM(p_w1h, g_w1h); SYM(p_w1l, g_w1l); SYM(p_w2h, g_w2h); SYM(p_w2l, g_w2l);

    cudaFuncSetAttribute(gemm_mma_kernel<0,0,1>, cudaFuncAttributeMaxDynamicSharedMemorySize, GSM);
    cudaFuncSetAttribute(gemm_mma_kernel<1,0,0>, cudaFuncAttributeMaxDynamicSharedMemorySize, GSM);
    cudaFuncSetAttribute(gemm_mma_kernel<0,1,1>, cudaFuncAttributeMaxDynamicSharedMemorySize, GSM);
    cudaFuncSetAttribute(flash_mma_kernel, cudaFuncAttributeMaxDynamicSharedMemorySize, F_SM);

    transpose_qkv_kernel<<<dim3(DD / 32, DHH / 32, 48), dim3(32, 8)>>>(wq, wk, wv, p_wqh, p_wql);
    transpose_sq_kernel<<<dim3(32, 32, 3), dim3(32, 8)>>>(wo, w1, w2,
        p_woh, p_wol, p_w1h, p_w1l, p_w2h, p_w2l);

    layernorm_kernel<<<MM, 256>>>(x, ln1_g, ln1_b, nullptr, p_ln1h, p_ln1l);
    gemm_mma_kernel<0,0,1><<<dim3(LD3 / 128, MM / 64), 128, GSM>>>(
        p_ln1h, p_ln1l, p_wqh, p_wql, nullptr, p_qkvh, p_qkvl, nullptr, LD3, DD);
    flash_mma_kernel<<<dim3(SS / 64, HH, BB), 128, F_SM>>>(p_qkvh, p_qkvl, p_ctxh, p_ctxl);
    gemm_mma_kernel<1,0,0><<<dim3(DD / 128, MM / 64), 128, GSM>>>(
        p_ctxh, p_ctxl, p_woh, p_wol, p_attn, nullptr, nullptr, x, DD, DD);
    layernorm_kernel<<<MM, 256>>>(p_attn, ln2_g, ln2_b, p_ln2f, p_ln2h, p_ln2l);
    gemm_mma_kernel<0,1,1><<<dim3(DD / 128, MM / 64), 128, GSM>>>(
        p_ln2h, p_ln2l, p_w1h, p_w1l, nullptr, p_f1h, p_f1l, nullptr, DD, DD);
    gemm_mma_kernel<1,0,0><<<dim3(DD / 128, MM / 64), 128, GSM>>>(
        p_f1h, p_f1l, p_w2h, p_w2l, p_res2, nullptr, nullptr, p_ln2f, DD, DD);
    layernorm_kernel<<<MM, 256>>>(p_res2, ln3_g, ln3_b, out, nullptr, nullptr);
}

// round 9
// speedup vs baseline: 5.2135x; 1.3897x over previous
#include <cuda_runtime.h>
#include <cuda_fp16.h>
#include <math.h>
#include <stdint.h>

#define BB 2
#define SS 2048
#define DD 1024
#define HH 16
#define DHH 64
#define MM (BB * SS)
#define LD3 (3 * DD)

// ---------------- scratch ----------------
__device__ float g_attn[MM * DD];
__device__ float g_ln2f[MM * DD];
__device__ float g_res2[MM * DD];

__device__ __half g_ln1h[MM * DD], g_ln1l[MM * DD];
__device__ __half g_ln2h[MM * DD], g_ln2l[MM * DD];
__device__ __half g_ctxh[MM * DD], g_ctxl[MM * DD];
__device__ __half g_f1h [MM * DD], g_f1l [MM * DD];
__device__ __half g_qkvh[MM * LD3], g_qkvl[MM * LD3];
__device__ __half g_wqh[LD3 * DD];   // weights single fp16
__device__ __half g_woh[DD * DD];
__device__ __half g_w1h[DD * DD];
__device__ __half g_w2h[DD * DD];

// ---------------- helpers ----------------
__device__ __forceinline__ uint32_t smem_u32(const void* p) {
    uint32_t a;
    asm("{ .reg .u64 t; cvta.to.shared.u64 t, %1; cvt.u32.u64 %0, t; }" : "=r"(a) : "l"(p));
    return a;
}
__device__ __forceinline__ void cpa16(uint32_t dst, const void* src) {
    asm volatile("cp.async.cg.shared.global [%0], [%1], 16;" :: "r"(dst), "l"(src) : "memory");
}
__device__ __forceinline__ void cpcommit() { asm volatile("cp.async.commit_group;" ::: "memory"); }
template <int N> __device__ __forceinline__ void cpwait() {
    asm volatile("cp.async.wait_group %0;" :: "n"(N) : "memory");
}
__device__ __forceinline__ void ldsm_x4(uint32_t* r, uint32_t a) {
    asm volatile("ldmatrix.sync.aligned.m8n8.x4.shared.b16 {%0,%1,%2,%3}, [%4];"
        : "=r"(r[0]), "=r"(r[1]), "=r"(r[2]), "=r"(r[3]) : "r"(a));
}
__device__ __forceinline__ void ldsm_x4t(uint32_t* r, uint32_t a) {
    asm volatile("ldmatrix.sync.aligned.m8n8.x4.trans.shared.b16 {%0,%1,%2,%3}, [%4];"
        : "=r"(r[0]), "=r"(r[1]), "=r"(r[2]), "=r"(r[3]) : "r"(a));
}
__device__ __forceinline__ void mma16816(float* d, const uint32_t* a, const uint32_t* b) {
    asm volatile("mma.sync.aligned.m16n8k16.row.col.f32.f16.f16.f32 "
        "{%0,%1,%2,%3},{%4,%5,%6,%7},{%8,%9},{%0,%1,%2,%3};"
        : "+f"(d[0]), "+f"(d[1]), "+f"(d[2]), "+f"(d[3])
        : "r"(a[0]), "r"(a[1]), "r"(a[2]), "r"(a[3]), "r"(b[0]), "r"(b[1]));
}
__device__ __forceinline__ void f16split(float v, __half& h, __half& l) {
    h = __float2half_rn(v);
    l = __float2half_rn(v - __half2float(h));
}
__device__ __forceinline__ uint32_t packh(float a, float b) {
    __half2 t = __floats2half2_rn(a, b);
    return *(uint32_t*)&t;
}
__device__ __forceinline__ uint32_t packsplit(float a, float b, int lo) {
    __half ha, la, hb, lb;
    f16split(a, ha, la); f16split(b, hb, lb);
    __half2 t;
    if (lo) { t.x = la; t.y = lb; } else { t.x = ha; t.y = hb; }
    return *(uint32_t*)&t;
}

// ---------------- layernorm ----------------
__device__ __forceinline__ float block_sum_256(float v, float* red) {
    #pragma unroll
    for (int o = 16; o; o >>= 1) v += __shfl_xor_sync(0xffffffffu, v, o);
    int w = threadIdx.x >> 5;
    if ((threadIdx.x & 31) == 0) red[w] = v;
    __syncthreads();
    if (threadIdx.x < 8) {
        v = red[threadIdx.x];
        #pragma unroll
        for (int o = 4; o; o >>= 1) v += __shfl_xor_sync(0xffu, v, o);
        if (threadIdx.x == 0) red[0] = v;
    }
    __syncthreads();
    float r = red[0];
    __syncthreads();
    return r;
}

__global__ void layernorm_kernel(const float* __restrict__ x,
                                 const float* __restrict__ g,
                                 const float* __restrict__ b,
                                 float* __restrict__ outf,
                                 __half* __restrict__ outh,
                                 __half* __restrict__ outl) {
    __shared__ float red[32];
    int row = blockIdx.x;
    const float* xr = x + (size_t)row * DD;
    float v[4], s = 0.f;
    #pragma unroll
    for (int i = 0; i < 4; i++) { v[i] = xr[threadIdx.x + i * 256]; s += v[i]; }
    float mean = block_sum_256(s, red) * (1.0f / DD);
    float sq = 0.f;
    #pragma unroll
    for (int i = 0; i < 4; i++) { float d = v[i] - mean; sq += d * d; }
    float inv = rsqrtf(block_sum_256(sq, red) * (1.0f / DD) + 1e-5f);
    #pragma unroll
    for (int i = 0; i < 4; i++) {
        int c = threadIdx.x + i * 256;
        float y = (v[i] - mean) * inv * g[c] + b[c];
        size_t o = (size_t)row * DD + c;
        if (outf) outf[o] = y;
        if (outh) { __half h, l; f16split(y, h, l); outh[o] = h; outl[o] = l; }
    }
}

// ---------------- weight transposes -> [N,K] single fp16 ----------------
__global__ void transpose_qkv_kernel(const float* __restrict__ wq, const float* __restrict__ wk,
                                     const float* __restrict__ wv,
                                     __half* __restrict__ th) {
    __shared__ float t[32][33];
    int sel = blockIdx.z >> 4, h = blockIdx.z & 15;
    const float* src = (sel == 0 ? wq : (sel == 1 ? wk : wv)) + (size_t)h * DD * DHH;
    int d0 = blockIdx.x * 32, dh0 = blockIdx.y * 32;
    int tx = threadIdx.x, ty = threadIdx.y;
    #pragma unroll
    for (int j = 0; j < 4; j++)
        t[ty + j * 8][tx] = src[(size_t)(d0 + ty + j * 8) * DHH + dh0 + tx];
    __syncthreads();
    int nb = sel * DD + h * DHH + dh0;
    #pragma unroll
    for (int j = 0; j < 4; j++) {
        size_t o = (size_t)(nb + ty + j * 8) * DD + d0 + tx;
        th[o] = __float2half_rn(t[tx][ty + j * 8]);
    }
}

__global__ void transpose_sq_kernel(const float* __restrict__ w0, const float* __restrict__ w1,
                                    const float* __restrict__ w2,
                                    __half* __restrict__ t0h, __half* __restrict__ t1h,
                                    __half* __restrict__ t2h) {
    __shared__ float t[32][33];
    int z = blockIdx.z;
    const float* src = z == 0 ? w0 : (z == 1 ? w1 : w2);
    __half* dh = z == 0 ? t0h : (z == 1 ? t1h : t2h);
    int r0 = blockIdx.x * 32, c0 = blockIdx.y * 32;
    int tx = threadIdx.x, ty = threadIdx.y;
    #pragma unroll
    for (int j = 0; j < 4; j++)
        t[ty + j * 8][tx] = src[(size_t)(r0 + ty + j * 8) * DD + c0 + tx];
    __syncthreads();
    #pragma unroll
    for (int j = 0; j < 4; j++) {
        size_t o = (size_t)(c0 + ty + j * 8) * DD + r0 + tx;
        dh[o] = __float2half_rn(t[tx][ty + j * 8]);
    }
}

// ---------------- fused mma.sync fp16 2-term GEMM ----------------
// C = (Ah+Al)[M,K] @ B[N,K]^T, A fp16 hi/lo, B single fp16.
// 128 threads, tile 64x128, BK=32, occ 4, term-major.
#define GLDA 40
#define ATILE (64 * GLDA * 2)    // 5120
#define BTILE (128 * GLDA * 2)   // 10240
#define GSTG  (2 * ATILE + BTILE)  // 20480
#define GSM   (2 * GSTG)           // 40960

__device__ __forceinline__ void g_load(uint32_t st,
    const __half* __restrict__ Ah, const __half* __restrict__ Al,
    const __half* __restrict__ B,
    int brow, int bcol, int k0, int K, int tid)
{
    #pragma unroll
    for (int it = 0; it < 2; it++) {
        int g = tid + it * 128;
        int r = g >> 2, gi = g & 3;
        uint32_t so = (uint32_t)(r * GLDA + gi * 8) * 2;
        size_t ao = (size_t)(brow + r) * K + k0 + gi * 8;
        cpa16(st + so,         Ah + ao);
        cpa16(st + ATILE + so, Al + ao);
    }
    #pragma unroll
    for (int it = 0; it < 4; it++) {
        int g = tid + it * 128;
        int r = g >> 2, gi = g & 3;
        uint32_t so = (uint32_t)(r * GLDA + gi * 8) * 2;
        cpa16(st + 2 * ATILE + so, B + (size_t)(bcol + r) * K + k0 + gi * 8);
    }
}

template <int ADD, int RELU, int SPLIT>
__global__ void __launch_bounds__(128, 4)
gemm_mma_kernel(const __half* __restrict__ Ah, const __half* __restrict__ Al,
                const __half* __restrict__ B,
                float* __restrict__ Cf, __half* __restrict__ Ch,
                __half* __restrict__ Cl, const float* __restrict__ R, int N, int K) {
    extern __shared__ char smg[];
    uint32_t sbase = smem_u32(smg);
    int tid = threadIdx.x, lane = tid & 31, wid = tid >> 5;
    int wn = wid * 32;
    int brow = blockIdx.y * 64, bcol = blockIdx.x * 128;
    int NC = K >> 5;

    float acc[4][4][4];
    #pragma unroll
    for (int i = 0; i < 4; i++)
        #pragma unroll
        for (int j = 0; j < 4; j++)
            #pragma unroll
            for (int e = 0; e < 4; e++) acc[i][j][e] = 0.f;

    g_load(sbase, Ah, Al, B, brow, bcol, 0, K, tid); cpcommit();

    int aRow = lane & 15, aCol8 = (lane >> 4) * 8;
    int bnRow = (lane & 7) + ((lane >> 4) & 1) * 8;
    int bkCol = ((lane >> 3) & 1) * 8;

    for (int c = 0; c < NC; c++) {
        cpwait<0>();
        __syncthreads();
        if (c + 1 < NC) {
            g_load(sbase + ((c + 1) & 1) * GSTG, Ah, Al, B,
                   brow, bcol, (c + 1) * 32, K, tid);
            cpcommit();
        }
        uint32_t sA = sbase + (c & 1) * GSTG;

        #pragma unroll
        for (int ks = 0; ks < 2; ks++) {
            uint32_t ah[4][4], al[4][4], bb[4][2];
            #pragma unroll
            for (int mt = 0; mt < 4; mt++) {
                uint32_t off = (uint32_t)((mt * 16 + aRow) * GLDA + ks * 16 + aCol8) * 2;
                ldsm_x4(ah[mt], sA + off);
                ldsm_x4(al[mt], sA + ATILE + off);
            }
            #pragma unroll
            for (int ntp = 0; ntp < 2; ntp++) {
                uint32_t off = (uint32_t)((wn + ntp * 16 + bnRow) * GLDA + ks * 16 + bkCol) * 2;
                ldsm_x4(&bb[ntp * 2][0], sA + 2 * ATILE + off);
            }
            #pragma unroll
            for (int mt = 0; mt < 4; mt++)
                #pragma unroll
                for (int nt = 0; nt < 4; nt++)
                    mma16816(acc[mt][nt], ah[mt], bb[nt]);
            #pragma unroll
            for (int mt = 0; mt < 4; mt++)
                #pragma unroll
                for (int nt = 0; nt < 4; nt++)
                    mma16816(acc[mt][nt], al[mt], bb[nt]);
        }
    }

    int r0 = brow + (lane >> 2);
    int c0 = bcol + wn + (lane & 3) * 2;
    #pragma unroll
    for (int mt = 0; mt < 4; mt++)
        #pragma unroll
        for (int half = 0; half < 2; half++) {
            int row = r0 + mt * 16 + half * 8;
            #pragma unroll
            for (int nt = 0; nt < 4; nt++) {
                float vx = acc[mt][nt][half * 2], vy = acc[mt][nt][half * 2 + 1];
                size_t o = (size_t)row * N + c0 + nt * 8;
                if (ADD) { vx += R[o]; vy += R[o + 1]; }
                if (RELU) { vx = fmaxf(vx, 0.f); vy = fmaxf(vy, 0.f); }
                if (SPLIT) {
                    *(uint32_t*)&Ch[o] = packsplit(vx, vy, 0);
                    *(uint32_t*)&Cl[o] = packsplit(vx, vy, 1);
                } else {
                    *(float2*)&Cf[o] = make_float2(vx, vy);
                }
            }
        }
}

// ---------------- flash attention (fp16, 2-term S) ----------------
// Q hi/lo fp16; K,V single fp16 (read from qkvh).
#define FST 72
#define F_QH 0
#define F_QL 9216
#define F_ST0 18432
#define F_STG 18432           // per stage: K (9216) + V (9216)
#define F_SM (F_ST0 + 2 * F_STG)   // 55296

__device__ __forceinline__ void f_load_tile(uint32_t st,
    const __half* __restrict__ qh, int b, int h, int krow, int tid)
{
    #pragma unroll
    for (int i = 0; i < 4; i++) {
        int g = tid + i * 128, r = g >> 3, gr = g & 7;
        size_t kro = (size_t)(b * SS + krow + r) * LD3 + DD + h * DHH + gr * 8;
        uint32_t dst = (uint32_t)(r * FST + gr * 8) * 2;
        cpa16(st + dst,        qh + kro);        // K
        cpa16(st + 9216 + dst, qh + kro + DD);   // V
    }
}

__global__ void __launch_bounds__(128, 3)
flash_mma_kernel(const __half* __restrict__ qh, const __half* __restrict__ ql,
                 __half* __restrict__ ch, __half* __restrict__ cl) {
    extern __shared__ char smf[];
    uint32_t sb = smem_u32(smf);
    int tid = threadIdx.x, lane = tid & 31, w = tid >> 5;
    int b = blockIdx.z, h = blockIdx.y, q0 = blockIdx.x * 64;

    #pragma unroll
    for (int i = 0; i < 4; i++) {
        int g = tid + i * 128, r = g >> 3, gr = g & 7;
        size_t src = (size_t)(b * SS + q0 + r) * LD3 + h * DHH + gr * 8;
        uint32_t dst = (uint32_t)(r * FST + gr * 8) * 2;
        cpa16(sb + F_QH + dst, qh + src);
        cpa16(sb + F_QL + dst, ql + src);
    }
    cpcommit();
    f_load_tile(sb + F_ST0, qh, b, h, 0, tid);
    cpcommit();

    cpwait<1>();
    __syncthreads();
    int lr = lane & 15, hc = (lane >> 4) * 8;
    uint32_t Qh[4][4], Ql[4][4];
    #pragma unroll
    for (int kk = 0; kk < 4; kk++) {
        uint32_t off = (uint32_t)((16 * w + lr) * FST + kk * 16 + hc) * 2;
        ldsm_x4(Qh[kk], sb + F_QH + off);
        ldsm_x4(Ql[kk], sb + F_QL + off);
    }

    int bnRow = (lane & 7) + ((lane >> 4) & 1) * 8;
    int bkCol = ((lane >> 3) & 1) * 8;
    int vRow = (lane & 7) + ((lane >> 3) & 1) * 8;
    int vCol = (lane >> 4) * 8;

    float m0 = -1e30f, m1 = -1e30f, l0 = 0.f, l1 = 0.f;
    float ao[8][4];
    #pragma unroll
    for (int n = 0; n < 8; n++)
        #pragma unroll
        for (int e = 0; e < 4; e++) ao[n][e] = 0.f;

    for (int kb = 0; kb < SS; kb += 64) {
        int t = kb >> 6;
        cpwait<0>();
        __syncthreads();
        if (kb + 64 < SS) {
            f_load_tile(sb + F_ST0 + ((t + 1) & 1) * F_STG, qh, b, h, kb + 64, tid);
            cpcommit();
        }
        uint32_t st = sb + F_ST0 + (t & 1) * F_STG;

        float s_[8][4];
        #pragma unroll
        for (int n = 0; n < 8; n++)
            #pragma unroll
            for (int e = 0; e < 4; e++) s_[n][e] = 0.f;
        #pragma unroll
        for (int kk = 0; kk < 4; kk++) {
            uint32_t bh[8][2];
            #pragma unroll
            for (int ntp = 0; ntp < 4; ntp++) {
                uint32_t off = (uint32_t)((ntp * 16 + bnRow) * FST + kk * 16 + bkCol) * 2;
                ldsm_x4(&bh[ntp * 2][0], st + off);
            }
            #pragma unroll
            for (int nt = 0; nt < 8; nt++) mma16816(s_[nt], Qh[kk], bh[nt]);
            #pragma unroll
            for (int nt = 0; nt < 8; nt++) mma16816(s_[nt], Ql[kk], bh[nt]);
        }

        float tm0 = -1e30f, tm1 = -1e30f;
        #pragma unroll
        for (int n = 0; n < 8; n++) {
            #pragma unroll
            for (int e = 0; e < 4; e++) s_[n][e] *= 0.125f;
            tm0 = fmaxf(tm0, fmaxf(s_[n][0], s_[n][1]));
            tm1 = fmaxf(tm1, fmaxf(s_[n][2], s_[n][3]));
        }
        tm0 = fmaxf(tm0, __shfl_xor_sync(0xffffffffu, tm0, 1));
        tm0 = fmaxf(tm0, __shfl_xor_sync(0xffffffffu, tm0, 2));
        tm1 = fmaxf(tm1, __shfl_xor_sync(0xffffffffu, tm1, 1));
        tm1 = fmaxf(tm1, __shfl_xor_sync(0xffffffffu, tm1, 2));
        float mn0 = fmaxf(m0, tm0), mn1 = fmaxf(m1, tm1);
        float sc0 = __expf(m0 - mn0), sc1 = __expf(m1 - mn1);
        m0 = mn0; m1 = mn1;
        float ls0 = 0.f, ls1 = 0.f;
        #pragma unroll
        for (int n = 0; n < 8; n++) {
            s_[n][0] = __expf(s_[n][0] - mn0);
            s_[n][1] = __expf(s_[n][1] - mn0);
            s_[n][2] = __expf(s_[n][2] - mn1);
            s_[n][3] = __expf(s_[n][3] - mn1);
            ls0 += s_[n][0] + s_[n][1];
            ls1 += s_[n][2] + s_[n][3];
        }
        ls0 += __shfl_xor_sync(0xffffffffu, ls0, 1);
        ls0 += __shfl_xor_sync(0xffffffffu, ls0, 2);
        ls1 += __shfl_xor_sync(0xffffffffu, ls1, 1);
        ls1 += __shfl_xor_sync(0xffffffffu, ls1, 2);
        l0 = l0 * sc0 + ls0;
        l1 = l1 * sc1 + ls1;
        #pragma unroll
        for (int n = 0; n < 8; n++) {
            ao[n][0] *= sc0; ao[n][1] *= sc0;
            ao[n][2] *= sc1; ao[n][3] *= sc1;
        }

        #pragma unroll
        for (int k2 = 0; k2 < 4; k2++) {
            uint32_t pa[4];
            pa[0] = packh(s_[2 * k2][0],     s_[2 * k2][1]);
            pa[1] = packh(s_[2 * k2][2],     s_[2 * k2][3]);
            pa[2] = packh(s_[2 * k2 + 1][0], s_[2 * k2 + 1][1]);
            pa[3] = packh(s_[2 * k2 + 1][2], s_[2 * k2 + 1][3]);
            #pragma unroll
            for (int ntp = 0; ntp < 4; ntp++) {
                uint32_t bv[4];
                ldsm_x4t(bv, st + 9216
                         + (uint32_t)((k2 * 16 + vRow) * FST + ntp * 16 + vCol) * 2);
                mma16816(ao[ntp * 2],     pa, &bv[0]);
                mma16816(ao[ntp * 2 + 1], pa, &bv[2]);
            }
        }
    }

    float i0 = 1.0f / l0, i1 = 1.0f / l1;
    int row0 = b * SS + q0 + 16 * w + (lane >> 2);
    int cb = h * DHH + (lane & 3) * 2;
    #pragma unroll
    for (int nt = 0; nt < 8; nt++) {
        size_t o0 = (size_t)row0 * DD + cb + nt * 8;
        size_t o1 = (size_t)(row0 + 8) * DD + cb + nt * 8;
        float v0 = ao[nt][0] * i0, v1 = ao[nt][1] * i0;
        float v2 = ao[nt][2] * i1, v3 = ao[nt][3] * i1;
        *(uint32_t*)&ch[o0] = packsplit(v0, v1, 0);
        *(uint32_t*)&cl[o0] = packsplit(v0, v1, 1);
        *(uint32_t*)&ch[o1] = packsplit(v2, v3, 0);
        *(uint32_t*)&cl[o1] = packsplit(v2, v3, 1);
    }
}

// ---------------- launch ----------------
#define SYM(p, s) cudaGetSymbolAddress((void**)&p, s)

extern "C" void kernel_launch(void* const* d_in, const int* in_sizes, int n_in,
                              void* d_out, int out_size) {
    const float* x     = (const float*)d_in[0];
    const float* wq    = (const float*)d_in[1];
    const float* wk    = (const float*)d_in[2];
    const float* wv    = (const float*)d_in[3];
    const float* wo    = (const float*)d_in[4];
    const float* w1    = (const float*)d_in[5];
    const float* w2    = (const float*)d_in[6];
    const float* ln1_g = (const float*)d_in[7];
    const float* ln1_b = (const float*)d_in[8];
    const float* ln2_g = (const float*)d_in[9];
    const float* ln2_b = (const float*)d_in[10];
    const float* ln3_g = (const float*)d_in[11];
    const float* ln3_b = (const float*)d_in[12];
    float* out = (float*)d_out;

    float *p_attn, *p_ln2f, *p_res2;
    __half *p_ln1h, *p_ln1l, *p_ln2h, *p_ln2l, *p_ctxh, *p_ctxl, *p_f1h, *p_f1l;
    __half *p_qkvh, *p_qkvl;
    __half *p_wqh, *p_woh, *p_w1h, *p_w2h;
    SYM(p_attn, g_attn); SYM(p_ln2f, g_ln2f); SYM(p_res2, g_res2);
    SYM(p_ln1h, g_ln1h); SYM(p_ln1l, g_ln1l); SYM(p_ln2h, g_ln2h); SYM(p_ln2l, g_ln2l);
    SYM(p_ctxh, g_ctxh); SYM(p_ctxl, g_ctxl); SYM(p_f1h, g_f1h); SYM(p_f1l, g_f1l);
    SYM(p_qkvh, g_qkvh); SYM(p_qkvl, g_qkvl);
    SYM(p_wqh, g_wqh); SYM(p_woh, g_woh); SYM(p_w1h, g_w1h); SYM(p_w2h, g_w2h);

    cudaFuncSetAttribute(gemm_mma_kernel<0,0,1>, cudaFuncAttributeMaxDynamicSharedMemorySize, GSM);
    cudaFuncSetAttribute(gemm_mma_kernel<1,0,0>, cudaFuncAttributeMaxDynamicSharedMemorySize, GSM);
    cudaFuncSetAttribute(gemm_mma_kernel<0,1,1>, cudaFuncAttributeMaxDynamicSharedMemorySize, GSM);
    cudaFuncSetAttribute(flash_mma_kernel, cudaFuncAttributeMaxDynamicSharedMemorySize, F_SM);

    transpose_qkv_kernel<<<dim3(DD / 32, DHH / 32, 48), dim3(32, 8)>>>(wq, wk, wv, p_wqh);
    transpose_sq_kernel<<<dim3(32, 32, 3), dim3(32, 8)>>>(wo, w1, w2, p_woh, p_w1h, p_w2h);

    layernorm_kernel<<<MM, 256>>>(x, ln1_g, ln1_b, nullptr, p_ln1h, p_ln1l);
    gemm_mma_kernel<0,0,1><<<dim3(LD3 / 128, MM / 64), 128, GSM>>>(
        p_ln1h, p_ln1l, p_wqh, nullptr, p_qkvh, p_qkvl, nullptr, LD3, DD);
    flash_mma_kernel<<<dim3(SS / 64, HH, BB), 128, F_SM>>>(p_qkvh, p_qkvl, p_ctxh, p_ctxl);
    gemm_mma_kernel<1,0,0><<<dim3(DD / 128, MM / 64), 128, GSM>>>(
        p_ctxh, p_ctxl, p_woh, p_attn, nullptr, nullptr, x, DD, DD);
    layernorm_kernel<<<MM, 256>>>(p_attn, ln2_g, ln2_b, p_ln2f, p_ln2h, p_ln2l);
    gemm_mma_kernel<0,1,1><<<dim3(DD / 128, MM / 64), 128, GSM>>>(
        p_ln2h, p_ln2l, p_w1h, nullptr, p_f1h, p_f1l, nullptr, DD, DD);
    gemm_mma_kernel<1,0,0><<<dim3(DD / 128, MM / 64), 128, GSM>>>(
        p_f1h, p_f1l, p_w2h, p_res2, nullptr, nullptr, p_ln2f, DD, DD);
    layernorm_kernel<<<MM, 256>>>(p_res2, ln3_g, ln3_b, out, nullptr, nullptr);
}

// round 10
// speedup vs baseline: 7.5426x; 1.4467x over previous
#include <cuda_runtime.h>
#include <cuda_fp16.h>
#include <math.h>
#include <stdint.h>

#define BB 2
#define SS 2048
#define DD 1024
#define HH 16
#define DHH 64
#define MM (BB * SS)
#define LD3 (3 * DD)

// ---------------- scratch ----------------
__device__ float g_attn[MM * DD];
__device__ float g_ln2f[MM * DD];
__device__ float g_res2[MM * DD];

__device__ __half g_ln1h[MM * DD];
__device__ __half g_ln2h[MM * DD];
__device__ __half g_ctxh[MM * DD];
__device__ __half g_f1h [MM * DD];
__device__ __half g_qkvh[MM * LD3];
__device__ __half g_wqh[LD3 * DD];
__device__ __half g_woh[DD * DD];
__device__ __half g_w1h[DD * DD];
__device__ __half g_w2h[DD * DD];

// ---------------- helpers ----------------
__device__ __forceinline__ uint32_t smem_u32(const void* p) {
    uint32_t a;
    asm("{ .reg .u64 t; cvta.to.shared.u64 t, %1; cvt.u32.u64 %0, t; }" : "=r"(a) : "l"(p));
    return a;
}
__device__ __forceinline__ void cpa16(uint32_t dst, const void* src) {
    asm volatile("cp.async.cg.shared.global [%0], [%1], 16;" :: "r"(dst), "l"(src) : "memory");
}
__device__ __forceinline__ void cpcommit() { asm volatile("cp.async.commit_group;" ::: "memory"); }
template <int N> __device__ __forceinline__ void cpwait() {
    asm volatile("cp.async.wait_group %0;" :: "n"(N) : "memory");
}
__device__ __forceinline__ void ldsm_x4(uint32_t* r, uint32_t a) {
    asm volatile("ldmatrix.sync.aligned.m8n8.x4.shared.b16 {%0,%1,%2,%3}, [%4];"
        : "=r"(r[0]), "=r"(r[1]), "=r"(r[2]), "=r"(r[3]) : "r"(a));
}
__device__ __forceinline__ void ldsm_x4t(uint32_t* r, uint32_t a) {
    asm volatile("ldmatrix.sync.aligned.m8n8.x4.trans.shared.b16 {%0,%1,%2,%3}, [%4];"
        : "=r"(r[0]), "=r"(r[1]), "=r"(r[2]), "=r"(r[3]) : "r"(a));
}
__device__ __forceinline__ void mma16816(float* d, const uint32_t* a, const uint32_t* b) {
    asm volatile("mma.sync.aligned.m16n8k16.row.col.f32.f16.f16.f32 "
        "{%0,%1,%2,%3},{%4,%5,%6,%7},{%8,%9},{%0,%1,%2,%3};"
        : "+f"(d[0]), "+f"(d[1]), "+f"(d[2]), "+f"(d[3])
        : "r"(a[0]), "r"(a[1]), "r"(a[2]), "r"(a[3]), "r"(b[0]), "r"(b[1]));
}
__device__ __forceinline__ uint32_t packh(float a, float b) {
    __half2 t = __floats2half2_rn(a, b);
    return *(uint32_t*)&t;
}

// ---------------- layernorm ----------------
__device__ __forceinline__ float block_sum_256(float v, float* red) {
    #pragma unroll
    for (int o = 16; o; o >>= 1) v += __shfl_xor_sync(0xffffffffu, v, o);
    int w = threadIdx.x >> 5;
    if ((threadIdx.x & 31) == 0) red[w] = v;
    __syncthreads();
    if (threadIdx.x < 8) {
        v = red[threadIdx.x];
        #pragma unroll
        for (int o = 4; o; o >>= 1) v += __shfl_xor_sync(0xffu, v, o);
        if (threadIdx.x == 0) red[0] = v;
    }
    __syncthreads();
    float r = red[0];
    __syncthreads();
    return r;
}

__global__ void layernorm_kernel(const float* __restrict__ x,
                                 const float* __restrict__ g,
                                 const float* __restrict__ b,
                                 float* __restrict__ outf,
                                 __half* __restrict__ outh) {
    __shared__ float red[32];
    int row = blockIdx.x;
    const float* xr = x + (size_t)row * DD;
    float v[4], s = 0.f;
    #pragma unroll
    for (int i = 0; i < 4; i++) { v[i] = xr[threadIdx.x + i * 256]; s += v[i]; }
    float mean = block_sum_256(s, red) * (1.0f / DD);
    float sq = 0.f;
    #pragma unroll
    for (int i = 0; i < 4; i++) { float d = v[i] - mean; sq += d * d; }
    float inv = rsqrtf(block_sum_256(sq, red) * (1.0f / DD) + 1e-5f);
    #pragma unroll
    for (int i = 0; i < 4; i++) {
        int c = threadIdx.x + i * 256;
        float y = (v[i] - mean) * inv * g[c] + b[c];
        size_t o = (size_t)row * DD + c;
        if (outf) outf[o] = y;
        if (outh) outh[o] = __float2half_rn(y);
    }
}

// ---------------- weight transposes -> [N,K] single fp16 ----------------
__global__ void transpose_qkv_kernel(const float* __restrict__ wq, const float* __restrict__ wk,
                                     const float* __restrict__ wv,
                                     __half* __restrict__ th) {
    __shared__ float t[32][33];
    int sel = blockIdx.z >> 4, h = blockIdx.z & 15;
    const float* src = (sel == 0 ? wq : (sel == 1 ? wk : wv)) + (size_t)h * DD * DHH;
    int d0 = blockIdx.x * 32, dh0 = blockIdx.y * 32;
    int tx = threadIdx.x, ty = threadIdx.y;
    #pragma unroll
    for (int j = 0; j < 4; j++)
        t[ty + j * 8][tx] = src[(size_t)(d0 + ty + j * 8) * DHH + dh0 + tx];
    __syncthreads();
    int nb = sel * DD + h * DHH + dh0;
    #pragma unroll
    for (int j = 0; j < 4; j++) {
        size_t o = (size_t)(nb + ty + j * 8) * DD + d0 + tx;
        th[o] = __float2half_rn(t[tx][ty + j * 8]);
    }
}

__global__ void transpose_sq_kernel(const float* __restrict__ w0, const float* __restrict__ w1,
                                    const float* __restrict__ w2,
                                    __half* __restrict__ t0h, __half* __restrict__ t1h,
                                    __half* __restrict__ t2h) {
    __shared__ float t[32][33];
    int z = blockIdx.z;
    const float* src = z == 0 ? w0 : (z == 1 ? w1 : w2);
    __half* dh = z == 0 ? t0h : (z == 1 ? t1h : t2h);
    int r0 = blockIdx.x * 32, c0 = blockIdx.y * 32;
    int tx = threadIdx.x, ty = threadIdx.y;
    #pragma unroll
    for (int j = 0; j < 4; j++)
        t[ty + j * 8][tx] = src[(size_t)(r0 + ty + j * 8) * DD + c0 + tx];
    __syncthreads();
    #pragma unroll
    for (int j = 0; j < 4; j++) {
        size_t o = (size_t)(c0 + ty + j * 8) * DD + r0 + tx;
        dh[o] = __float2half_rn(t[tx][ty + j * 8]);
    }
}

// ---------------- mma.sync fp16 single-term GEMM ----------------
// C = A[M,K] @ B[N,K]^T, both single fp16, fp32 accum.
// 128 threads, tile 64x128, BK=32, occ 4.
#define GLDA 40
#define ATILE (64 * GLDA * 2)    // 5120
#define BTILE (128 * GLDA * 2)   // 10240
#define GSTG  (ATILE + BTILE)    // 15360
#define GSM   (2 * GSTG)         // 30720

__device__ __forceinline__ void g_load(uint32_t st,
    const __half* __restrict__ A, const __half* __restrict__ B,
    int brow, int bcol, int k0, int K, int tid)
{
    #pragma unroll
    for (int it = 0; it < 2; it++) {
        int g = tid + it * 128;
        int r = g >> 2, gi = g & 3;
        uint32_t so = (uint32_t)(r * GLDA + gi * 8) * 2;
        cpa16(st + so, A + (size_t)(brow + r) * K + k0 + gi * 8);
    }
    #pragma unroll
    for (int it = 0; it < 4; it++) {
        int g = tid + it * 128;
        int r = g >> 2, gi = g & 3;
        uint32_t so = (uint32_t)(r * GLDA + gi * 8) * 2;
        cpa16(st + ATILE + so, B + (size_t)(bcol + r) * K + k0 + gi * 8);
    }
}

template <int ADD, int RELU, int HOUT>
__global__ void __launch_bounds__(128, 4)
gemm_mma_kernel(const __half* __restrict__ A, const __half* __restrict__ B,
                float* __restrict__ Cf, __half* __restrict__ Ch,
                const float* __restrict__ R, int N, int K) {
    extern __shared__ char smg[];
    uint32_t sbase = smem_u32(smg);
    int tid = threadIdx.x, lane = tid & 31, wid = tid >> 5;
    int wn = wid * 32;
    int brow = blockIdx.y * 64, bcol = blockIdx.x * 128;
    int NC = K >> 5;

    float acc[4][4][4];
    #pragma unroll
    for (int i = 0; i < 4; i++)
        #pragma unroll
        for (int j = 0; j < 4; j++)
            #pragma unroll
            for (int e = 0; e < 4; e++) acc[i][j][e] = 0.f;

    g_load(sbase, A, B, brow, bcol, 0, K, tid); cpcommit();

    int aRow = lane & 15, aCol8 = (lane >> 4) * 8;
    int bnRow = (lane & 7) + ((lane >> 4) & 1) * 8;
    int bkCol = ((lane >> 3) & 1) * 8;

    for (int c = 0; c < NC; c++) {
        cpwait<0>();
        __syncthreads();
        if (c + 1 < NC) {
            g_load(sbase + ((c + 1) & 1) * GSTG, A, B, brow, bcol, (c + 1) * 32, K, tid);
            cpcommit();
        }
        uint32_t sA = sbase + (c & 1) * GSTG;

        #pragma unroll
        for (int ks = 0; ks < 2; ks++) {
            uint32_t ah[4][4], bb[4][2];
            #pragma unroll
            for (int mt = 0; mt < 4; mt++) {
                uint32_t off = (uint32_t)((mt * 16 + aRow) * GLDA + ks * 16 + aCol8) * 2;
                ldsm_x4(ah[mt], sA + off);
            }
            #pragma unroll
            for (int ntp = 0; ntp < 2; ntp++) {
                uint32_t off = (uint32_t)((wn + ntp * 16 + bnRow) * GLDA + ks * 16 + bkCol) * 2;
                ldsm_x4(&bb[ntp * 2][0], sA + ATILE + off);
            }
            #pragma unroll
            for (int mt = 0; mt < 4; mt++)
                #pragma unroll
                for (int nt = 0; nt < 4; nt++)
                    mma16816(acc[mt][nt], ah[mt], bb[nt]);
        }
    }

    int r0 = brow + (lane >> 2);
    int c0 = bcol + wn + (lane & 3) * 2;
    #pragma unroll
    for (int mt = 0; mt < 4; mt++)
        #pragma unroll
        for (int half = 0; half < 2; half++) {
            int row = r0 + mt * 16 + half * 8;
            #pragma unroll
            for (int nt = 0; nt < 4; nt++) {
                float vx = acc[mt][nt][half * 2], vy = acc[mt][nt][half * 2 + 1];
                size_t o = (size_t)row * N + c0 + nt * 8;
                if (ADD) { vx += R[o]; vy += R[o + 1]; }
                if (RELU) { vx = fmaxf(vx, 0.f); vy = fmaxf(vy, 0.f); }
                if (HOUT) {
                    *(uint32_t*)&Ch[o] = packh(vx, vy);
                } else {
                    *(float2*)&Cf[o] = make_float2(vx, vy);
                }
            }
        }
}

// ---------------- flash attention (single fp16) ----------------
#define FST 72
#define F_Q 0
#define F_ST0 9216
#define F_STG 18432           // per stage: K (9216) + V (9216)
#define F_SM (F_ST0 + 2 * F_STG)   // 46080

__device__ __forceinline__ void f_load_tile(uint32_t st,
    const __half* __restrict__ qkv, int b, int h, int krow, int tid)
{
    #pragma unroll
    for (int i = 0; i < 4; i++) {
        int g = tid + i * 128, r = g >> 3, gr = g & 7;
        size_t kro = (size_t)(b * SS + krow + r) * LD3 + DD + h * DHH + gr * 8;
        uint32_t dst = (uint32_t)(r * FST + gr * 8) * 2;
        cpa16(st + dst,        qkv + kro);        // K
        cpa16(st + 9216 + dst, qkv + kro + DD);   // V
    }
}

__global__ void __launch_bounds__(128, 4)
flash_mma_kernel(const __half* __restrict__ qkv, __half* __restrict__ ch) {
    extern __shared__ char smf[];
    uint32_t sb = smem_u32(smf);
    int tid = threadIdx.x, lane = tid & 31, w = tid >> 5;
    int b = blockIdx.z, h = blockIdx.y, q0 = blockIdx.x * 64;

    #pragma unroll
    for (int i = 0; i < 4; i++) {
        int g = tid + i * 128, r = g >> 3, gr = g & 7;
        size_t src = (size_t)(b * SS + q0 + r) * LD3 + h * DHH + gr * 8;
        uint32_t dst = (uint32_t)(r * FST + gr * 8) * 2;
        cpa16(sb + F_Q + dst, qkv + src);
    }
    cpcommit();
    f_load_tile(sb + F_ST0, qkv, b, h, 0, tid);
    cpcommit();

    cpwait<1>();
    __syncthreads();
    int lr = lane & 15, hc = (lane >> 4) * 8;
    uint32_t Qf[4][4];
    #pragma unroll
    for (int kk = 0; kk < 4; kk++) {
        uint32_t off = (uint32_t)((16 * w + lr) * FST + kk * 16 + hc) * 2;
        ldsm_x4(Qf[kk], sb + F_Q + off);
    }

    int bnRow = (lane & 7) + ((lane >> 4) & 1) * 8;
    int bkCol = ((lane >> 3) & 1) * 8;
    int vRow = (lane & 7) + ((lane >> 3) & 1) * 8;
    int vCol = (lane >> 4) * 8;

    float m0 = -1e30f, m1 = -1e30f, l0 = 0.f, l1 = 0.f;
    float ao[8][4];
    #pragma unroll
    for (int n = 0; n < 8; n++)
        #pragma unroll
        for (int e = 0; e < 4; e++) ao[n][e] = 0.f;

    for (int kb = 0; kb < SS; kb += 64) {
        int t = kb >> 6;
        cpwait<0>();
        __syncthreads();
        if (kb + 64 < SS) {
            f_load_tile(sb + F_ST0 + ((t + 1) & 1) * F_STG, qkv, b, h, kb + 64, tid);
            cpcommit();
        }
        uint32_t st = sb + F_ST0 + (t & 1) * F_STG;

        float s_[8][4];
        #pragma unroll
        for (int n = 0; n < 8; n++)
            #pragma unroll
            for (int e = 0; e < 4; e++) s_[n][e] = 0.f;
        #pragma unroll
        for (int kk = 0; kk < 4; kk++) {
            uint32_t bh[8][2];
            #pragma unroll
            for (int ntp = 0; ntp < 4; ntp++) {
                uint32_t off = (uint32_t)((ntp * 16 + bnRow) * FST + kk * 16 + bkCol) * 2;
                ldsm_x4(&bh[ntp * 2][0], st + off);
            }
            #pragma unroll
            for (int nt = 0; nt < 8; nt++) mma16816(s_[nt], Qf[kk], bh[nt]);
        }

        float tm0 = -1e30f, tm1 = -1e30f;
        #pragma unroll
        for (int n = 0; n < 8; n++) {
            #pragma unroll
            for (int e = 0; e < 4; e++) s_[n][e] *= 0.125f;
            tm0 = fmaxf(tm0, fmaxf(s_[n][0], s_[n][1]));
            tm1 = fmaxf(tm1, fmaxf(s_[n][2], s_[n][3]));
        }
        tm0 = fmaxf(tm0, __shfl_xor_sync(0xffffffffu, tm0, 1));
        tm0 = fmaxf(tm0, __shfl_xor_sync(0xffffffffu, tm0, 2));
        tm1 = fmaxf(tm1, __shfl_xor_sync(0xffffffffu, tm1, 1));
        tm1 = fmaxf(tm1, __shfl_xor_sync(0xffffffffu, tm1, 2));
        float mn0 = fmaxf(m0, tm0), mn1 = fmaxf(m1, tm1);
        float sc0 = __expf(m0 - mn0), sc1 = __expf(m1 - mn1);
        m0 = mn0; m1 = mn1;
        float ls0 = 0.f, ls1 = 0.f;
        #pragma unroll
        for (int n = 0; n < 8; n++) {
            s_[n][0] = __expf(s_[n][0] - mn0);
            s_[n][1] = __expf(s_[n][1] - mn0);
            s_[n][2] = __expf(s_[n][2] - mn1);
            s_[n][3] = __expf(s_[n][3] - mn1);
            ls0 += s_[n][0] + s_[n][1];
            ls1 += s_[n][2] + s_[n][3];
        }
        ls0 += __shfl_xor_sync(0xffffffffu, ls0, 1);
        ls0 += __shfl_xor_sync(0xffffffffu, ls0, 2);
        ls1 += __shfl_xor_sync(0xffffffffu, ls1, 1);
        ls1 += __shfl_xor_sync(0xffffffffu, ls1, 2);
        l0 = l0 * sc0 + ls0;
        l1 = l1 * sc1 + ls1;
        #pragma unroll
        for (int n = 0; n < 8; n++) {
            ao[n][0] *= sc0; ao[n][1] *= sc0;
            ao[n][2] *= sc1; ao[n][3] *= sc1;
        }

        #pragma unroll
        for (int k2 = 0; k2 < 4; k2++) {
            uint32_t pa[4];
            pa[0] = packh(s_[2 * k2][0],     s_[2 * k2][1]);
            pa[1] = packh(s_[2 * k2][2],     s_[2 * k2][3]);
            pa[2] = packh(s_[2 * k2 + 1][0], s_[2 * k2 + 1][1]);
            pa[3] = packh(s_[2 * k2 + 1][2], s_[2 * k2 + 1][3]);
            #pragma unroll
            for (int ntp = 0; ntp < 4; ntp++) {
                uint32_t bv[4];
                ldsm_x4t(bv, st + 9216
                         + (uint32_t)((k2 * 16 + vRow) * FST + ntp * 16 + vCol) * 2);
                mma16816(ao[ntp * 2],     pa, &bv[0]);
                mma16816(ao[ntp * 2 + 1], pa, &bv[2]);
            }
        }
    }

    float i0 = 1.0f / l0, i1 = 1.0f / l1;
    int row0 = b * SS + q0 + 16 * w + (lane >> 2);
    int cb = h * DHH + (lane & 3) * 2;
    #pragma unroll
    for (int nt = 0; nt < 8; nt++) {
        size_t o0 = (size_t)row0 * DD + cb + nt * 8;
        size_t o1 = (size_t)(row0 + 8) * DD + cb + nt * 8;
        *(uint32_t*)&ch[o0] = packh(ao[nt][0] * i0, ao[nt][1] * i0);
        *(uint32_t*)&ch[o1] = packh(ao[nt][2] * i1, ao[nt][3] * i1);
    }
}

// ---------------- launch ----------------
#define SYM(p, s) cudaGetSymbolAddress((void**)&p, s)

extern "C" void kernel_launch(void* const* d_in, const int* in_sizes, int n_in,
                              void* d_out, int out_size) {
    const float* x     = (const float*)d_in[0];
    const float* wq    = (const float*)d_in[1];
    const float* wk    = (const float*)d_in[2];
    const float* wv    = (const float*)d_in[3];
    const float* wo    = (const float*)d_in[4];
    const float* w1    = (const float*)d_in[5];
    const float* w2    = (const float*)d_in[6];
    const float* ln1_g = (const float*)d_in[7];
    const float* ln1_b = (const float*)d_in[8];
    const float* ln2_g = (const float*)d_in[9];
    const float* ln2_b = (const float*)d_in[10];
    const float* ln3_g = (const float*)d_in[11];
    const float* ln3_b = (const float*)d_in[12];
    float* out = (float*)d_out;

    float *p_attn, *p_ln2f, *p_res2;
    __half *p_ln1h, *p_ln2h, *p_ctxh, *p_f1h, *p_qkvh;
    __half *p_wqh, *p_woh, *p_w1h, *p_w2h;
    SYM(p_attn, g_attn); SYM(p_ln2f, g_ln2f); SYM(p_res2, g_res2);
    SYM(p_ln1h, g_ln1h); SYM(p_ln2h, g_ln2h);
    SYM(p_ctxh, g_ctxh); SYM(p_f1h, g_f1h); SYM(p_qkvh, g_qkvh);
    SYM(p_wqh, g_wqh); SYM(p_woh, g_woh); SYM(p_w1h, g_w1h); SYM(p_w2h, g_w2h);

    cudaFuncSetAttribute(gemm_mma_kernel<0,0,1>, cudaFuncAttributeMaxDynamicSharedMemorySize, GSM);
    cudaFuncSetAttribute(gemm_mma_kernel<1,0,0>, cudaFuncAttributeMaxDynamicSharedMemorySize, GSM);
    cudaFuncSetAttribute(gemm_mma_kernel<0,1,1>, cudaFuncAttributeMaxDynamicSharedMemorySize, GSM);
    cudaFuncSetAttribute(flash_mma_kernel, cudaFuncAttributeMaxDynamicSharedMemorySize, F_SM);

    transpose_qkv_kernel<<<dim3(DD / 32, DHH / 32, 48), dim3(32, 8)>>>(wq, wk, wv, p_wqh);
    transpose_sq_kernel<<<dim3(32, 32, 3), dim3(32, 8)>>>(wo, w1, w2, p_woh, p_w1h, p_w2h);

    layernorm_kernel<<<MM, 256>>>(x, ln1_g, ln1_b, nullptr, p_ln1h);
    gemm_mma_kernel<0,0,1><<<dim3(LD3 / 128, MM / 64), 128, GSM>>>(
        p_ln1h, p_wqh, nullptr, p_qkvh, nullptr, LD3, DD);
    flash_mma_kernel<<<dim3(SS / 64, HH, BB), 128, F_SM>>>(p_qkvh, p_ctxh);
    gemm_mma_kernel<1,0,0><<<dim3(DD / 128, MM / 64), 128, GSM>>>(
        p_ctxh, p_woh, p_attn, nullptr, x, DD, DD);
    layernorm_kernel<<<MM, 256>>>(p_attn, ln2_g, ln2_b, p_ln2f, p_ln2h);
    gemm_mma_kernel<0,1,1><<<dim3(DD / 128, MM / 64), 128, GSM>>>(
        p_ln2h, p_w1h, nullptr, p_f1h, nullptr, DD, DD);
    gemm_mma_kernel<1,0,0><<<dim3(DD / 128, MM / 64), 128, GSM>>>(
        p_f1h, p_w2h, p_res2, nullptr, p_ln2f, DD, DD);
    layernorm_kernel<<<MM, 256>>>(p_res2, ln3_g, ln3_b, out, nullptr);
}

// round 11
// speedup vs baseline: 7.9349x; 1.0520x over previous
#include <cuda_runtime.h>
#include <cuda_fp16.h>
#include <math.h>
#include <stdint.h>

#define BB 2
#define SS 2048
#define DD 1024
#define HH 16
#define DHH 64
#define MM (BB * SS)
#define LD3 (3 * DD)

// ---------------- scratch ----------------
__device__ float g_attn[MM * DD];
__device__ float g_ln2f[MM * DD];
__device__ float g_res2[MM * DD];

__device__ __half g_ln1h[MM * DD];
__device__ __half g_ln2h[MM * DD];
__device__ __half g_ctxh[MM * DD];
__device__ __half g_f1h [MM * DD];
__device__ __half g_qkvh[MM * LD3];
__device__ __half g_wqh[LD3 * DD];
__device__ __half g_woh[DD * DD];
__device__ __half g_w1h[DD * DD];
__device__ __half g_w2h[DD * DD];

// ---------------- helpers ----------------
__device__ __forceinline__ uint32_t smem_u32(const void* p) {
    uint32_t a;
    asm("{ .reg .u64 t; cvta.to.shared.u64 t, %1; cvt.u32.u64 %0, t; }" : "=r"(a) : "l"(p));
    return a;
}
__device__ __forceinline__ void cpa16(uint32_t dst, const void* src) {
    asm volatile("cp.async.cg.shared.global [%0], [%1], 16;" :: "r"(dst), "l"(src) : "memory");
}
__device__ __forceinline__ void cpcommit() { asm volatile("cp.async.commit_group;" ::: "memory"); }
template <int N> __device__ __forceinline__ void cpwait() {
    asm volatile("cp.async.wait_group %0;" :: "n"(N) : "memory");
}
__device__ __forceinline__ void ldsm_x4(uint32_t* r, uint32_t a) {
    asm volatile("ldmatrix.sync.aligned.m8n8.x4.shared.b16 {%0,%1,%2,%3}, [%4];"
        : "=r"(r[0]), "=r"(r[1]), "=r"(r[2]), "=r"(r[3]) : "r"(a));
}
__device__ __forceinline__ void ldsm_x4t(uint32_t* r, uint32_t a) {
    asm volatile("ldmatrix.sync.aligned.m8n8.x4.trans.shared.b16 {%0,%1,%2,%3}, [%4];"
        : "=r"(r[0]), "=r"(r[1]), "=r"(r[2]), "=r"(r[3]) : "r"(a));
}
__device__ __forceinline__ void mma16816(float* d, const uint32_t* a, const uint32_t* b) {
    asm volatile("mma.sync.aligned.m16n8k16.row.col.f32.f16.f16.f32 "
        "{%0,%1,%2,%3},{%4,%5,%6,%7},{%8,%9},{%0,%1,%2,%3};"
        : "+f"(d[0]), "+f"(d[1]), "+f"(d[2]), "+f"(d[3])
        : "r"(a[0]), "r"(a[1]), "r"(a[2]), "r"(a[3]), "r"(b[0]), "r"(b[1]));
}
__device__ __forceinline__ uint32_t packh(float a, float b) {
    __half2 t = __floats2half2_rn(a, b);
    return *(uint32_t*)&t;
}

// ---------------- layernorm ----------------
__device__ __forceinline__ float block_sum_256(float v, float* red) {
    #pragma unroll
    for (int o = 16; o; o >>= 1) v += __shfl_xor_sync(0xffffffffu, v, o);
    int w = threadIdx.x >> 5;
    if ((threadIdx.x & 31) == 0) red[w] = v;
    __syncthreads();
    if (threadIdx.x < 8) {
        v = red[threadIdx.x];
        #pragma unroll
        for (int o = 4; o; o >>= 1) v += __shfl_xor_sync(0xffu, v, o);
        if (threadIdx.x == 0) red[0] = v;
    }
    __syncthreads();
    float r = red[0];
    __syncthreads();
    return r;
}

__global__ void layernorm_kernel(const float* __restrict__ x,
                                 const float* __restrict__ g,
                                 const float* __restrict__ b,
                                 float* __restrict__ outf,
                                 __half* __restrict__ outh) {
    __shared__ float red[32];
    int row = blockIdx.x;
    const float* xr = x + (size_t)row * DD;
    float v[4], s = 0.f;
    #pragma unroll
    for (int i = 0; i < 4; i++) { v[i] = xr[threadIdx.x + i * 256]; s += v[i]; }
    float mean = block_sum_256(s, red) * (1.0f / DD);
    float sq = 0.f;
    #pragma unroll
    for (int i = 0; i < 4; i++) { float d = v[i] - mean; sq += d * d; }
    float inv = rsqrtf(block_sum_256(sq, red) * (1.0f / DD) + 1e-5f);
    #pragma unroll
    for (int i = 0; i < 4; i++) {
        int c = threadIdx.x + i * 256;
        float y = (v[i] - mean) * inv * g[c] + b[c];
        size_t o = (size_t)row * DD + c;
        if (outf) outf[o] = y;
        if (outh) outh[o] = __float2half_rn(y);
    }
}

// ---------------- weight transposes -> [N,K] single fp16 ----------------
__global__ void transpose_qkv_kernel(const float* __restrict__ wq, const float* __restrict__ wk,
                                     const float* __restrict__ wv,
                                     __half* __restrict__ th) {
    __shared__ float t[32][33];
    int sel = blockIdx.z >> 4, h = blockIdx.z & 15;
    const float* src = (sel == 0 ? wq : (sel == 1 ? wk : wv)) + (size_t)h * DD * DHH;
    int d0 = blockIdx.x * 32, dh0 = blockIdx.y * 32;
    int tx = threadIdx.x, ty = threadIdx.y;
    #pragma unroll
    for (int j = 0; j < 4; j++)
        t[ty + j * 8][tx] = src[(size_t)(d0 + ty + j * 8) * DHH + dh0 + tx];
    __syncthreads();
    int nb = sel * DD + h * DHH + dh0;
    #pragma unroll
    for (int j = 0; j < 4; j++) {
        size_t o = (size_t)(nb + ty + j * 8) * DD + d0 + tx;
        th[o] = __float2half_rn(t[tx][ty + j * 8]);
    }
}

__global__ void transpose_sq_kernel(const float* __restrict__ w0, const float* __restrict__ w1,
                                    const float* __restrict__ w2,
                                    __half* __restrict__ t0h, __half* __restrict__ t1h,
                                    __half* __restrict__ t2h) {
    __shared__ float t[32][33];
    int z = blockIdx.z;
    const float* src = z == 0 ? w0 : (z == 1 ? w1 : w2);
    __half* dh = z == 0 ? t0h : (z == 1 ? t1h : t2h);
    int r0 = blockIdx.x * 32, c0 = blockIdx.y * 32;
    int tx = threadIdx.x, ty = threadIdx.y;
    #pragma unroll
    for (int j = 0; j < 4; j++)
        t[ty + j * 8][tx] = src[(size_t)(r0 + ty + j * 8) * DD + c0 + tx];
    __syncthreads();
    #pragma unroll
    for (int j = 0; j < 4; j++) {
        size_t o = (size_t)(c0 + ty + j * 8) * DD + r0 + tx;
        dh[o] = __float2half_rn(t[tx][ty + j * 8]);
    }
}

// ---------------- mma.sync fp16 GEMM, BK=64, fragment-pipelined ----------------
// C = A[M,K] @ B[N,K]^T. 128 threads, tile 64x128, occ 4.
#define GLDA 72                   // 64 k elems + 8 pad (144B rows, conflict-free)
#define ATILE (64 * GLDA * 2)     // 9216
#define BTILE (128 * GLDA * 2)    // 18432
#define GSTG  (ATILE + BTILE)     // 27648
#define GSM   (2 * GSTG)          // 55296

__device__ __forceinline__ void g_load(uint32_t st,
    const __half* __restrict__ A, const __half* __restrict__ B,
    int brow, int bcol, int k0, int K, int tid)
{
    #pragma unroll
    for (int it = 0; it < 4; it++) {           // A: 64 rows x 8 granules
        int g = tid + it * 128;
        int r = g >> 3, gi = g & 7;
        uint32_t so = (uint32_t)(r * GLDA + gi * 8) * 2;
        cpa16(st + so, A + (size_t)(brow + r) * K + k0 + gi * 8);
    }
    #pragma unroll
    for (int it = 0; it < 8; it++) {           // B: 128 rows x 8 granules
        int g = tid + it * 128;
        int r = g >> 3, gi = g & 7;
        uint32_t so = (uint32_t)(r * GLDA + gi * 8) * 2;
        cpa16(st + ATILE + so, B + (size_t)(bcol + r) * K + k0 + gi * 8);
    }
}

template <int ADD, int RELU, int HOUT>
__global__ void __launch_bounds__(128, 4)
gemm_mma_kernel(const __half* __restrict__ A, const __half* __restrict__ B,
                float* __restrict__ Cf, __half* __restrict__ Ch,
                const float* __restrict__ R, int N, int K) {
    extern __shared__ char smg[];
    uint32_t sbase = smem_u32(smg);
    int tid = threadIdx.x, lane = tid & 31, wid = tid >> 5;
    int wn = wid * 32;
    int brow = blockIdx.y * 64, bcol = blockIdx.x * 128;
    int NC = K >> 6;

    float acc[4][4][4];
    #pragma unroll
    for (int i = 0; i < 4; i++)
        #pragma unroll
        for (int j = 0; j < 4; j++)
            #pragma unroll
            for (int e = 0; e < 4; e++) acc[i][j][e] = 0.f;

    g_load(sbase, A, B, brow, bcol, 0, K, tid); cpcommit();

    int aRow = lane & 15, aCol8 = (lane >> 4) * 8;
    int bnRow = (lane & 7) + ((lane >> 4) & 1) * 8;
    int bkCol = ((lane >> 3) & 1) * 8;

    uint32_t af[2][4][4];   // A-fragment double buffer

    for (int c = 0; c < NC; c++) {
        cpwait<0>();
        __syncthreads();
        if (c + 1 < NC) {
            g_load(sbase + ((c + 1) & 1) * GSTG, A, B, brow, bcol, (c + 1) * 64, K, tid);
            cpcommit();
        }
        uint32_t sA = sbase + (c & 1) * GSTG;

        // preload A frags for ks=0
        #pragma unroll
        for (int mt = 0; mt < 4; mt++) {
            uint32_t off = (uint32_t)((mt * 16 + aRow) * GLDA + aCol8) * 2;
            ldsm_x4(af[0][mt], sA + off);
        }

        #pragma unroll
        for (int ks = 0; ks < 4; ks++) {
            uint32_t bb[4][2];
            #pragma unroll
            for (int ntp = 0; ntp < 2; ntp++) {
                uint32_t off = (uint32_t)((wn + ntp * 16 + bnRow) * GLDA + ks * 16 + bkCol) * 2;
                ldsm_x4(&bb[ntp * 2][0], sA + ATILE + off);
            }
            if (ks < 3) {       // prefetch next A frags (overlaps with MMAs below)
                #pragma unroll
                for (int mt = 0; mt < 4; mt++) {
                    uint32_t off = (uint32_t)((mt * 16 + aRow) * GLDA + (ks + 1) * 16 + aCol8) * 2;
                    ldsm_x4(af[(ks + 1) & 1][mt], sA + off);
                }
            }
            #pragma unroll
            for (int mt = 0; mt < 4; mt++)
                #pragma unroll
                for (int nt = 0; nt < 4; nt++)
                    mma16816(acc[mt][nt], af[ks & 1][mt], bb[nt]);
        }
    }

    int r0 = brow + (lane >> 2);
    int c0 = bcol + wn + (lane & 3) * 2;
    #pragma unroll
    for (int mt = 0; mt < 4; mt++)
        #pragma unroll
        for (int half = 0; half < 2; half++) {
            int row = r0 + mt * 16 + half * 8;
            #pragma unroll
            for (int nt = 0; nt < 4; nt++) {
                float vx = acc[mt][nt][half * 2], vy = acc[mt][nt][half * 2 + 1];
                size_t o = (size_t)row * N + c0 + nt * 8;
                if (ADD) { vx += R[o]; vy += R[o + 1]; }
                if (RELU) { vx = fmaxf(vx, 0.f); vy = fmaxf(vy, 0.f); }
                if (HOUT) {
                    *(uint32_t*)&Ch[o] = packh(vx, vy);
                } else {
                    *(float2*)&Cf[o] = make_float2(vx, vy);
                }
            }
        }
}

// ---------------- flash attention (single fp16) ----------------
#define FST 72
#define F_Q 0
#define F_ST0 9216
#define F_STG 18432           // per stage: K (9216) + V (9216)
#define F_SM (F_ST0 + 2 * F_STG)   // 46080

__device__ __forceinline__ void f_load_tile(uint32_t st,
    const __half* __restrict__ qkv, int b, int h, int krow, int tid)
{
    #pragma unroll
    for (int i = 0; i < 4; i++) {
        int g = tid + i * 128, r = g >> 3, gr = g & 7;
        size_t kro = (size_t)(b * SS + krow + r) * LD3 + DD + h * DHH + gr * 8;
        uint32_t dst = (uint32_t)(r * FST + gr * 8) * 2;
        cpa16(st + dst,        qkv + kro);        // K
        cpa16(st + 9216 + dst, qkv + kro + DD);   // V
    }
}

__global__ void __launch_bounds__(128, 4)
flash_mma_kernel(const __half* __restrict__ qkv, __half* __restrict__ ch) {
    extern __shared__ char smf[];
    uint32_t sb = smem_u32(smf);
    int tid = threadIdx.x, lane = tid & 31, w = tid >> 5;
    int b = blockIdx.z, h = blockIdx.y, q0 = blockIdx.x * 64;

    #pragma unroll
    for (int i = 0; i < 4; i++) {
        int g = tid + i * 128, r = g >> 3, gr = g & 7;
        size_t src = (size_t)(b * SS + q0 + r) * LD3 + h * DHH + gr * 8;
        uint32_t dst = (uint32_t)(r * FST + gr * 8) * 2;
        cpa16(sb + F_Q + dst, qkv + src);
    }
    cpcommit();
    f_load_tile(sb + F_ST0, qkv, b, h, 0, tid);
    cpcommit();

    cpwait<1>();
    __syncthreads();
    int lr = lane & 15, hc = (lane >> 4) * 8;
    uint32_t Qf[4][4];
    #pragma unroll
    for (int kk = 0; kk < 4; kk++) {
        uint32_t off = (uint32_t)((16 * w + lr) * FST + kk * 16 + hc) * 2;
        ldsm_x4(Qf[kk], sb + F_Q + off);
    }

    int bnRow = (lane & 7) + ((lane >> 4) & 1) * 8;
    int bkCol = ((lane >> 3) & 1) * 8;
    int vRow = (lane & 7) + ((lane >> 3) & 1) * 8;
    int vCol = (lane >> 4) * 8;

    float m0 = -1e30f, m1 = -1e30f, l0 = 0.f, l1 = 0.f;
    float ao[8][4];
    #pragma unroll
    for (int n = 0; n < 8; n++)
        #pragma unroll
        for (int e = 0; e < 4; e++) ao[n][e] = 0.f;

    for (int kb = 0; kb < SS; kb += 64) {
        int t = kb >> 6;
        cpwait<0>();
        __syncthreads();
        if (kb + 64 < SS) {
            f_load_tile(sb + F_ST0 + ((t + 1) & 1) * F_STG, qkv, b, h, kb + 64, tid);
            cpcommit();
        }
        uint32_t st = sb + F_ST0 + (t & 1) * F_STG;

        float s_[8][4];
        #pragma unroll
        for (int n = 0; n < 8; n++)
            #pragma unroll
            for (int e = 0; e < 4; e++) s_[n][e] = 0.f;
        #pragma unroll
        for (int kk = 0; kk < 4; kk++) {
            uint32_t bh[8][2];
            #pragma unroll
            for (int ntp = 0; ntp < 4; ntp++) {
                uint32_t off = (uint32_t)((ntp * 16 + bnRow) * FST + kk * 16 + bkCol) * 2;
                ldsm_x4(&bh[ntp * 2][0], st + off);
            }
            #pragma unroll
            for (int nt = 0; nt < 8; nt++) mma16816(s_[nt], Qf[kk], bh[nt]);
        }

        float tm0 = -1e30f, tm1 = -1e30f;
        #pragma unroll
        for (int n = 0; n < 8; n++) {
            #pragma unroll
            for (int e = 0; e < 4; e++) s_[n][e] *= 0.125f;
            tm0 = fmaxf(tm0, fmaxf(s_[n][0], s_[n][1]));
            tm1 = fmaxf(tm1, fmaxf(s_[n][2], s_[n][3]));
        }
        tm0 = fmaxf(tm0, __shfl_xor_sync(0xffffffffu, tm0, 1));
        tm0 = fmaxf(tm0, __shfl_xor_sync(0xffffffffu, tm0, 2));
        tm1 = fmaxf(tm1, __shfl_xor_sync(0xffffffffu, tm1, 1));
        tm1 = fmaxf(tm1, __shfl_xor_sync(0xffffffffu, tm1, 2));
        float mn0 = fmaxf(m0, tm0), mn1 = fmaxf(m1, tm1);
        float sc0 = __expf(m0 - mn0), sc1 = __expf(m1 - mn1);
        m0 = mn0; m1 = mn1;
        float ls0 = 0.f, ls1 = 0.f;
        #pragma unroll
        for (int n = 0; n < 8; n++) {
            s_[n][0] = __expf(s_[n][0] - mn0);
            s_[n][1] = __expf(s_[n][1] - mn0);
            s_[n][2] = __expf(s_[n][2] - mn1);
            s_[n][3] = __expf(s_[n][3] - mn1);
            ls0 += s_[n][0] + s_[n][1];
            ls1 += s_[n][2] + s_[n][3];
        }
        ls0 += __shfl_xor_sync(0xffffffffu, ls0, 1);
        ls0 += __shfl_xor_sync(0xffffffffu, ls0, 2);
        ls1 += __shfl_xor_sync(0xffffffffu, ls1, 1);
        ls1 += __shfl_xor_sync(0xffffffffu, ls1, 2);
        l0 = l0 * sc0 + ls0;
        l1 = l1 * sc1 + ls1;
        #pragma unroll
        for (int n = 0; n < 8; n++) {
            ao[n][0] *= sc0; ao[n][1] *= sc0;
            ao[n][2] *= sc1; ao[n][3] *= sc1;
        }

        #pragma unroll
        for (int k2 = 0; k2 < 4; k2++) {
            uint32_t pa[4];
            pa[0] = packh(s_[2 * k2][0],     s_[2 * k2][1]);
            pa[1] = packh(s_[2 * k2][2],     s_[2 * k2][3]);
            pa[2] = packh(s_[2 * k2 + 1][0], s_[2 * k2 + 1][1]);
            pa[3] = packh(s_[2 * k2 + 1][2], s_[2 * k2 + 1][3]);
            #pragma unroll
            for (int ntp = 0; ntp < 4; ntp++) {
                uint32_t bv[4];
                ldsm_x4t(bv, st + 9216
                         + (uint32_t)((k2 * 16 + vRow) * FST + ntp * 16 + vCol) * 2);
                mma16816(ao[ntp * 2],     pa, &bv[0]);
                mma16816(ao[ntp * 2 + 1], pa, &bv[2]);
            }
        }
    }

    float i0 = 1.0f / l0, i1 = 1.0f / l1;
    int row0 = b * SS + q0 + 16 * w + (lane >> 2);
    int cb = h * DHH + (lane & 3) * 2;
    #pragma unroll
    for (int nt = 0; nt < 8; nt++) {
        size_t o0 = (size_t)row0 * DD + cb + nt * 8;
        size_t o1 = (size_t)(row0 + 8) * DD + cb + nt * 8;
        *(uint32_t*)&ch[o0] = packh(ao[nt][0] * i0, ao[nt][1] * i0);
        *(uint32_t*)&ch[o1] = packh(ao[nt][2] * i1, ao[nt][3] * i1);
    }
}

// ---------------- launch ----------------
#define SYM(p, s) cudaGetSymbolAddress((void**)&p, s)

extern "C" void kernel_launch(void* const* d_in, const int* in_sizes, int n_in,
                              void* d_out, int out_size) {
    const float* x     = (const float*)d_in[0];
    const float* wq    = (const float*)d_in[1];
    const float* wk    = (const float*)d_in[2];
    const float* wv    = (const float*)d_in[3];
    const float* wo    = (const float*)d_in[4];
    const float* w1    = (const float*)d_in[5];
    const float* w2    = (const float*)d_in[6];
    const float* ln1_g = (const float*)d_in[7];
    const float* ln1_b = (const float*)d_in[8];
    const float* ln2_g = (const float*)d_in[9];
    const float* ln2_b = (const float*)d_in[10];
    const float* ln3_g = (const float*)d_in[11];
    const float* ln3_b = (const float*)d_in[12];
    float* out = (float*)d_out;

    float *p_attn, *p_ln2f, *p_res2;
    __half *p_ln1h, *p_ln2h, *p_ctxh, *p_f1h, *p_qkvh;
    __half *p_wqh, *p_woh, *p_w1h, *p_w2h;
    SYM(p_attn, g_attn); SYM(p_ln2f, g_ln2f); SYM(p_res2, g_res2);
    SYM(p_ln1h, g_ln1h); SYM(p_ln2h, g_ln2h);
    SYM(p_ctxh, g_ctxh); SYM(p_f1h, g_f1h); SYM(p_qkvh, g_qkvh);
    SYM(p_wqh, g_wqh); SYM(p_woh, g_woh); SYM(p_w1h, g_w1h); SYM(p_w2h, g_w2h);

    cudaFuncSetAttribute(gemm_mma_kernel<0,0,1>, cudaFuncAttributeMaxDynamicSharedMemorySize, GSM);
    cudaFuncSetAttribute(gemm_mma_kernel<1,0,0>, cudaFuncAttributeMaxDynamicSharedMemorySize, GSM);
    cudaFuncSetAttribute(gemm_mma_kernel<0,1,1>, cudaFuncAttributeMaxDynamicSharedMemorySize, GSM);
    cudaFuncSetAttribute(flash_mma_kernel, cudaFuncAttributeMaxDynamicSharedMemorySize, F_SM);

    transpose_qkv_kernel<<<dim3(DD / 32, DHH / 32, 48), dim3(32, 8)>>>(wq, wk, wv, p_wqh);
    transpose_sq_kernel<<<dim3(32, 32, 3), dim3(32, 8)>>>(wo, w1, w2, p_woh, p_w1h, p_w2h);

    layernorm_kernel<<<MM, 256>>>(x, ln1_g, ln1_b, nullptr, p_ln1h);
    gemm_mma_kernel<0,0,1><<<dim3(LD3 / 128, MM / 64), 128, GSM>>>(
        p_ln1h, p_wqh, nullptr, p_qkvh, nullptr, LD3, DD);
    flash_mma_kernel<<<dim3(SS / 64, HH, BB), 128, F_SM>>>(p_qkvh, p_ctxh);
    gemm_mma_kernel<1,0,0><<<dim3(DD / 128, MM / 64), 128, GSM>>>(
        p_ctxh, p_woh, p_attn, nullptr, x, DD, DD);
    layernorm_kernel<<<MM, 256>>>(p_attn, ln2_g, ln2_b, p_ln2f, p_ln2h);
    gemm_mma_kernel<0,1,1><<<dim3(DD / 128, MM / 64), 128, GSM>>>(
        p_ln2h, p_w1h, nullptr, p_f1h, nullptr, DD, DD);
    gemm_mma_kernel<1,0,0><<<dim3(DD / 128, MM / 64), 128, GSM>>>(
        p_f1h, p_w2h, p_res2, nullptr, p_ln2f, DD, DD);
    layernorm_kernel<<<MM, 256>>>(p_res2, ln3_g, ln3_b, out, nullptr);
}